// round 3
// baseline (speedup 1.0000x reference)
#include <cuda_runtime.h>
#include <cuda_bf16.h>
#include <cstdint>

// Problem constants
#define BB 256   // batch
#define MM 96    // memory slots
#define WW 128   // write tokens
#define DD 512   // embed dim

// ---------------- scratch (static device globals: allocation-free) ----------
__device__ __nv_bfloat16 g_wtok_bf[BB * WW * DD];
__device__ __nv_bfloat16 g_mem_bf[BB * MM * DD];
__device__ __nv_bfloat16 g_Wq_bf[DD * DD];
__device__ __nv_bfloat16 g_Wk_bf[DD * DD];
__device__ __nv_bfloat16 g_We_bf[DD * DD];
__device__ __nv_bfloat16 g_Wa_bf[DD * DD];

__device__ __nv_bfloat16 g_qb[BB * WW * DD];   // q in bf16 (scores input)
__device__ __nv_bfloat16 g_kb[BB * MM * DD];   // k in bf16 (scores input)
__device__ float g_e[BB * WW * DD];
__device__ float g_a[BB * WW * DD];
__device__ float g_s[BB * WW * MM];

static __device__ __forceinline__ uint32_t smem_u32(const void* p) {
    uint32_t a;
    asm("{ .reg .u64 t; cvta.to.shared.u64 t, %1; cvt.u32.u64 %0, t; }" : "=r"(a) : "l"(p));
    return a;
}

static __device__ __forceinline__ unsigned long long pk2(float x, float y) {
    unsigned long long r;
    asm("mov.b64 %0, {%1, %2};" : "=l"(r) : "f"(x), "f"(y));
    return r;
}
static __device__ __forceinline__ void upk2(float& x, float& y, unsigned long long r) {
    asm("mov.b64 {%0, %1}, %2;" : "=f"(x), "=f"(y) : "l"(r));
}
static __device__ __forceinline__ unsigned long long fma2(
    unsigned long long a, unsigned long long b, unsigned long long c) {
    unsigned long long d;
    asm("fma.rn.f32x2 %0, %1, %2, %3;" : "=l"(d) : "l"(a), "l"(b), "l"(c));
    return d;
}

// ---------------------------------------------------------------------------
// fp32 -> bf16 conversion (vectorized, grid-stride)
// ---------------------------------------------------------------------------
__global__ __launch_bounds__(256) void f2bf_kernel(
    const float4* __restrict__ src, uint2* __restrict__ dst, int n4)
{
    int i = blockIdx.x * 256 + threadIdx.x;
    int stride = gridDim.x * 256;
    for (; i < n4; i += stride) {
        float4 v = src[i];
        __nv_bfloat162 lo = __floats2bfloat162_rn(v.x, v.y);
        __nv_bfloat162 hi = __floats2bfloat162_rn(v.z, v.w);
        uint2 o;
        o.x = *(uint32_t*)&lo;
        o.y = *(uint32_t*)&hi;
        dst[i] = o;
    }
}

// 4 weight matrices (each DD*DD) in one launch
__global__ __launch_bounds__(256) void f2bf4_kernel(
    const float4* __restrict__ s0, const float4* __restrict__ s1,
    const float4* __restrict__ s2, const float4* __restrict__ s3,
    uint2* __restrict__ d0, uint2* __restrict__ d1,
    uint2* __restrict__ d2, uint2* __restrict__ d3)
{
    const int n4 = DD * DD / 4;  // 65536
    int i = blockIdx.x * 256 + threadIdx.x;    // 0 .. 4*n4
    int mat = i >> 16;
    int off = i & (n4 - 1);
    const float4* src = (mat == 0) ? s0 : (mat == 1) ? s1 : (mat == 2) ? s2 : s3;
    uint2* dst = (mat == 0) ? d0 : (mat == 1) ? d1 : (mat == 2) ? d2 : d3;
    float4 v = src[off];
    __nv_bfloat162 lo = __floats2bfloat162_rn(v.x, v.y);
    __nv_bfloat162 hi = __floats2bfloat162_rn(v.z, v.w);
    uint2 o;
    o.x = *(uint32_t*)&lo;
    o.y = *(uint32_t*)&hi;
    dst[off] = o;
}

// ---------------------------------------------------------------------------
// Tensor-core GEMM: C[r, n] = act( sum_k A[r,k] * Bw[n,k] + bias[n] )
// act: 0=none fp32 out, 1=sigmoid fp32, 2=tanh fp32, 3=none bf16 out
// ---------------------------------------------------------------------------
#define GBM 128
#define GBN 128
#define GBK 32
#define LDSK 40
#define NKT (DD / GBK)   // 16

__global__ __launch_bounds__(256) void mma_gemm_kernel(
    const __nv_bfloat16* __restrict__ A,
    const __nv_bfloat16* __restrict__ Bw,
    const float* __restrict__ bias,
    void* __restrict__ Cv, int act)
{
    __shared__ __nv_bfloat16 sA[2][GBM * LDSK];
    __shared__ __nv_bfloat16 sB[2][GBN * LDSK];

    const int tid = threadIdx.x;
    const int wid = tid >> 5;
    const int lane = tid & 31;
    const int wm = wid & 1;       // 2 warps along m
    const int wn = wid >> 1;      // 4 warps along n
    const long rowbase = (long)blockIdx.x * GBM;
    const int colbase = blockIdx.y * GBN;

    float acc[4][4][4];
#pragma unroll
    for (int mi = 0; mi < 4; mi++)
#pragma unroll
        for (int ni = 0; ni < 4; ni++)
#pragma unroll
            for (int v = 0; v < 4; v++) acc[mi][ni][v] = 0.f;

    const uint32_t sA_base = smem_u32(&sA[0][0]);
    const uint32_t sB_base = smem_u32(&sB[0][0]);

    const int ar0 = tid >> 2, ac0 = (tid & 3) * 8;
    const int c1 = tid + 256;
    const int ar1 = c1 >> 2, ac1 = (c1 & 3) * 8;

#define STAGE(buf, kt) do {                                                        \
    const int kk_ = (kt) * GBK;                                                    \
    const __nv_bfloat16* ga0 = A  + (rowbase + ar0) * DD + kk_ + ac0;              \
    const __nv_bfloat16* ga1 = A  + (rowbase + ar1) * DD + kk_ + ac1;              \
    const __nv_bfloat16* gb0 = Bw + (long)(colbase + ar0) * DD + kk_ + ac0;        \
    const __nv_bfloat16* gb1 = Bw + (long)(colbase + ar1) * DD + kk_ + ac1;        \
    uint32_t s_;                                                                   \
    s_ = sA_base + (uint32_t)(((buf) * GBM * LDSK + ar0 * LDSK + ac0) * 2);        \
    asm volatile("cp.async.cg.shared.global [%0], [%1], 16;\n" :: "r"(s_), "l"(ga0)); \
    s_ = sA_base + (uint32_t)(((buf) * GBM * LDSK + ar1 * LDSK + ac1) * 2);        \
    asm volatile("cp.async.cg.shared.global [%0], [%1], 16;\n" :: "r"(s_), "l"(ga1)); \
    s_ = sB_base + (uint32_t)(((buf) * GBN * LDSK + ar0 * LDSK + ac0) * 2);        \
    asm volatile("cp.async.cg.shared.global [%0], [%1], 16;\n" :: "r"(s_), "l"(gb0)); \
    s_ = sB_base + (uint32_t)(((buf) * GBN * LDSK + ar1 * LDSK + ac1) * 2);        \
    asm volatile("cp.async.cg.shared.global [%0], [%1], 16;\n" :: "r"(s_), "l"(gb1)); \
    asm volatile("cp.async.commit_group;\n");                                      \
} while (0)

    STAGE(0, 0);

    for (int kt = 0; kt < NKT; kt++) {
        if (kt + 1 < NKT) {
            STAGE((kt + 1) & 1, kt + 1);
            asm volatile("cp.async.wait_group 1;\n");
        } else {
            asm volatile("cp.async.wait_group 0;\n");
        }
        __syncthreads();

        const int buf = kt & 1;
#pragma unroll
        for (int ks = 0; ks < 2; ks++) {
            const int k0 = ks * 16;

            uint32_t af[4][4];
#pragma unroll
            for (int mi = 0; mi < 4; mi++) {
                const int m0 = wm * 64 + mi * 16;
                uint32_t addr = sA_base + (uint32_t)((buf * GBM * LDSK +
                    (m0 + (lane & 15)) * LDSK + k0 + ((lane >> 4) * 8)) * 2);
                asm volatile(
                    "ldmatrix.sync.aligned.m8n8.x4.shared.b16 {%0,%1,%2,%3}, [%4];\n"
                    : "=r"(af[mi][0]), "=r"(af[mi][1]), "=r"(af[mi][2]), "=r"(af[mi][3])
                    : "r"(addr));
            }

            uint32_t bf[4][2];
#pragma unroll
            for (int nj = 0; nj < 2; nj++) {
                const int n0 = wn * 32 + nj * 16;
                uint32_t addr = sB_base + (uint32_t)((buf * GBN * LDSK +
                    (n0 + (lane & 7) + ((lane >> 4) << 3)) * LDSK +
                    k0 + (((lane >> 3) & 1) * 8)) * 2);
                uint32_t r0, r1, r2, r3;
                asm volatile(
                    "ldmatrix.sync.aligned.m8n8.x4.shared.b16 {%0,%1,%2,%3}, [%4];\n"
                    : "=r"(r0), "=r"(r1), "=r"(r2), "=r"(r3) : "r"(addr));
                bf[nj * 2][0] = r0;     bf[nj * 2][1] = r1;
                bf[nj * 2 + 1][0] = r2; bf[nj * 2 + 1][1] = r3;
            }

#pragma unroll
            for (int mi = 0; mi < 4; mi++)
#pragma unroll
                for (int ni = 0; ni < 4; ni++)
                    asm volatile(
                        "mma.sync.aligned.m16n8k16.row.col.f32.bf16.bf16.f32 "
                        "{%0,%1,%2,%3}, {%4,%5,%6,%7}, {%8,%9}, {%0,%1,%2,%3};\n"
                        : "+f"(acc[mi][ni][0]), "+f"(acc[mi][ni][1]),
                          "+f"(acc[mi][ni][2]), "+f"(acc[mi][ni][3])
                        : "r"(af[mi][0]), "r"(af[mi][1]), "r"(af[mi][2]), "r"(af[mi][3]),
                          "r"(bf[ni][0]), "r"(bf[ni][1]));
        }
        __syncthreads();
    }

    // epilogue: bias + activation
#pragma unroll
    for (int mi = 0; mi < 4; mi++) {
        const long r0 = rowbase + wm * 64 + mi * 16 + (lane >> 2);
#pragma unroll
        for (int ni = 0; ni < 4; ni++) {
            const int col = colbase + wn * 32 + ni * 8 + (lane & 3) * 2;
            const float b0 = bias[col], b1 = bias[col + 1];
            float v0 = acc[mi][ni][0] + b0;
            float v1 = acc[mi][ni][1] + b1;
            float v2 = acc[mi][ni][2] + b0;
            float v3 = acc[mi][ni][3] + b1;
            if (act == 1) {
                v0 = 1.f / (1.f + __expf(-v0)); v1 = 1.f / (1.f + __expf(-v1));
                v2 = 1.f / (1.f + __expf(-v2)); v3 = 1.f / (1.f + __expf(-v3));
            } else if (act == 2) {
                v0 = tanhf(v0); v1 = tanhf(v1);
                v2 = tanhf(v2); v3 = tanhf(v3);
            }
            if (act == 3) {
                __nv_bfloat16* Cb = (__nv_bfloat16*)Cv;
                *(__nv_bfloat162*)&Cb[r0 * DD + col] = __floats2bfloat162_rn(v0, v1);
                *(__nv_bfloat162*)&Cb[(r0 + 8) * DD + col] = __floats2bfloat162_rn(v2, v3);
            } else {
                float* C = (float*)Cv;
                *(float2*)&C[r0 * DD + col] = make_float2(v0, v1);
                *(float2*)&C[(r0 + 8) * DD + col] = make_float2(v2, v3);
            }
        }
    }
#undef STAGE
}

// ---------------------------------------------------------------------------
// Fused scores + softmax on tensor cores.
// One block per batch b: tile W=128 rows x M=96 cols, K loop over D=512.
// 8 warps as 4(m-rows) x 2(n-cols); warp tile 32x48 -> 2x6 m16n8k16 mma.
// attn (fp32) written to S.
// ---------------------------------------------------------------------------
__global__ __launch_bounds__(256) void scores_softmax_kernel(
    const __nv_bfloat16* __restrict__ Q, const __nv_bfloat16* __restrict__ K,
    float* __restrict__ S)
{
    __shared__ __nv_bfloat16 sQ[2][WW * LDSK];
    __shared__ __nv_bfloat16 sK[2][MM * LDSK];
    __shared__ float pmax[2][WW];
    __shared__ float psum[2][WW];

    const int b = blockIdx.x;
    const int tid = threadIdx.x;
    const int wid = tid >> 5;
    const int lane = tid & 31;
    const int wm = wid & 3;    // 4 groups of 32 rows
    const int wn = wid >> 2;   // 2 groups of 48 cols

    const __nv_bfloat16* Qb = Q + (size_t)b * WW * DD;
    const __nv_bfloat16* Kb = K + (size_t)b * MM * DD;

    float acc[2][6][4];
#pragma unroll
    for (int mi = 0; mi < 2; mi++)
#pragma unroll
        for (int ni = 0; ni < 6; ni++)
#pragma unroll
            for (int v = 0; v < 4; v++) acc[mi][ni][v] = 0.f;

    const uint32_t sQ_base = smem_u32(&sQ[0][0]);
    const uint32_t sK_base = smem_u32(&sK[0][0]);

    const int qr0 = tid >> 2, qc0 = (tid & 3) * 8;
    const int qc1i = tid + 256;
    const int qr1 = qc1i >> 2, qc1 = (qc1i & 3) * 8;
    const int kr0 = tid >> 2, kc0 = (tid & 3) * 8;           // chunks 0..255
    const int kr1 = 64 + (tid >> 2), kc1 = (tid & 3) * 8;    // chunks 256..383 (tid<128)

#define SSTAGE(buf, kt) do {                                                       \
    const int kk_ = (kt) * GBK;                                                    \
    uint32_t s_;                                                                   \
    s_ = sQ_base + (uint32_t)(((buf) * WW * LDSK + qr0 * LDSK + qc0) * 2);         \
    asm volatile("cp.async.cg.shared.global [%0], [%1], 16;\n"                     \
                 :: "r"(s_), "l"(Qb + (size_t)qr0 * DD + kk_ + qc0));              \
    s_ = sQ_base + (uint32_t)(((buf) * WW * LDSK + qr1 * LDSK + qc1) * 2);         \
    asm volatile("cp.async.cg.shared.global [%0], [%1], 16;\n"                     \
                 :: "r"(s_), "l"(Qb + (size_t)qr1 * DD + kk_ + qc1));              \
    s_ = sK_base + (uint32_t)(((buf) * MM * LDSK + kr0 * LDSK + kc0) * 2);         \
    asm volatile("cp.async.cg.shared.global [%0], [%1], 16;\n"                     \
                 :: "r"(s_), "l"(Kb + (size_t)kr0 * DD + kk_ + kc0));              \
    if (tid < 128) {                                                               \
        s_ = sK_base + (uint32_t)(((buf) * MM * LDSK + kr1 * LDSK + kc1) * 2);     \
        asm volatile("cp.async.cg.shared.global [%0], [%1], 16;\n"                 \
                     :: "r"(s_), "l"(Kb + (size_t)kr1 * DD + kk_ + kc1));          \
    }                                                                              \
    asm volatile("cp.async.commit_group;\n");                                      \
} while (0)

    SSTAGE(0, 0);

    for (int kt = 0; kt < NKT; kt++) {
        if (kt + 1 < NKT) {
            SSTAGE((kt + 1) & 1, kt + 1);
            asm volatile("cp.async.wait_group 1;\n");
        } else {
            asm volatile("cp.async.wait_group 0;\n");
        }
        __syncthreads();

        const int buf = kt & 1;
#pragma unroll
        for (int ks = 0; ks < 2; ks++) {
            const int k0 = ks * 16;

            uint32_t af[2][4];
#pragma unroll
            for (int mi = 0; mi < 2; mi++) {
                const int m0 = wm * 32 + mi * 16;
                uint32_t addr = sQ_base + (uint32_t)((buf * WW * LDSK +
                    (m0 + (lane & 15)) * LDSK + k0 + ((lane >> 4) * 8)) * 2);
                asm volatile(
                    "ldmatrix.sync.aligned.m8n8.x4.shared.b16 {%0,%1,%2,%3}, [%4];\n"
                    : "=r"(af[mi][0]), "=r"(af[mi][1]), "=r"(af[mi][2]), "=r"(af[mi][3])
                    : "r"(addr));
            }

            uint32_t bf[6][2];
#pragma unroll
            for (int nj = 0; nj < 3; nj++) {
                const int n0 = wn * 48 + nj * 16;
                uint32_t addr = sK_base + (uint32_t)((buf * MM * LDSK +
                    (n0 + (lane & 7) + ((lane >> 4) << 3)) * LDSK +
                    k0 + (((lane >> 3) & 1) * 8)) * 2);
                uint32_t r0, r1, r2, r3;
                asm volatile(
                    "ldmatrix.sync.aligned.m8n8.x4.shared.b16 {%0,%1,%2,%3}, [%4];\n"
                    : "=r"(r0), "=r"(r1), "=r"(r2), "=r"(r3) : "r"(addr));
                bf[nj * 2][0] = r0;     bf[nj * 2][1] = r1;
                bf[nj * 2 + 1][0] = r2; bf[nj * 2 + 1][1] = r3;
            }

#pragma unroll
            for (int mi = 0; mi < 2; mi++)
#pragma unroll
                for (int ni = 0; ni < 6; ni++)
                    asm volatile(
                        "mma.sync.aligned.m16n8k16.row.col.f32.bf16.bf16.f32 "
                        "{%0,%1,%2,%3}, {%4,%5,%6,%7}, {%8,%9}, {%0,%1,%2,%3};\n"
                        : "+f"(acc[mi][ni][0]), "+f"(acc[mi][ni][1]),
                          "+f"(acc[mi][ni][2]), "+f"(acc[mi][ni][3])
                        : "r"(af[mi][0]), "r"(af[mi][1]), "r"(af[mi][2]), "r"(af[mi][3]),
                          "r"(bf[ni][0]), "r"(bf[ni][1]));
        }
        __syncthreads();
    }
#undef SSTAGE

    // scale
    const float scale = 0.04419417382415922f;  // 1/sqrt(512)
#pragma unroll
    for (int mi = 0; mi < 2; mi++)
#pragma unroll
        for (int ni = 0; ni < 6; ni++)
#pragma unroll
            for (int v = 0; v < 4; v++) acc[mi][ni][v] *= scale;

    // rows owned by this thread: mi in {0,1}, half h in {0,1}
    int rows[2][2];
#pragma unroll
    for (int mi = 0; mi < 2; mi++) {
        rows[mi][0] = wm * 32 + mi * 16 + (lane >> 2);
        rows[mi][1] = rows[mi][0] + 8;
    }

    // per-row max over this warp's 48 cols
#pragma unroll
    for (int mi = 0; mi < 2; mi++) {
#pragma unroll
        for (int h = 0; h < 2; h++) {
            float mx = -1e30f;
#pragma unroll
            for (int ni = 0; ni < 6; ni++) {
                mx = fmaxf(mx, acc[mi][ni][h * 2 + 0]);
                mx = fmaxf(mx, acc[mi][ni][h * 2 + 1]);
            }
            mx = fmaxf(mx, __shfl_xor_sync(0xffffffffu, mx, 1));
            mx = fmaxf(mx, __shfl_xor_sync(0xffffffffu, mx, 2));
            pmax[wn][rows[mi][h]] = mx;
        }
    }
    __syncthreads();

    float inv[2][2];
#pragma unroll
    for (int mi = 0; mi < 2; mi++) {
#pragma unroll
        for (int h = 0; h < 2; h++) {
            const float gmax = fmaxf(pmax[0][rows[mi][h]], pmax[1][rows[mi][h]]);
            float sm = 0.f;
#pragma unroll
            for (int ni = 0; ni < 6; ni++) {
                float e0 = __expf(acc[mi][ni][h * 2 + 0] - gmax);
                float e1 = __expf(acc[mi][ni][h * 2 + 1] - gmax);
                acc[mi][ni][h * 2 + 0] = e0;
                acc[mi][ni][h * 2 + 1] = e1;
                sm += e0 + e1;
            }
            sm += __shfl_xor_sync(0xffffffffu, sm, 1);
            sm += __shfl_xor_sync(0xffffffffu, sm, 2);
            psum[wn][rows[mi][h]] = sm;
        }
    }
    __syncthreads();

#pragma unroll
    for (int mi = 0; mi < 2; mi++)
#pragma unroll
        for (int h = 0; h < 2; h++)
            inv[mi][h] = 1.f / (psum[0][rows[mi][h]] + psum[1][rows[mi][h]]);

    // write attn
#pragma unroll
    for (int mi = 0; mi < 2; mi++) {
#pragma unroll
        for (int h = 0; h < 2; h++) {
            float* rowp = S + ((size_t)(b * WW + rows[mi][h])) * MM;
#pragma unroll
            for (int ni = 0; ni < 6; ni++) {
                const int col = wn * 48 + ni * 8 + (lane & 3) * 2;
                *(float2*)(rowp + col) = make_float2(
                    acc[mi][ni][h * 2 + 0] * inv[mi][h],
                    acc[mi][ni][h * 2 + 1] * inv[mi][h]);
            }
        }
    }
}

// ---------------------------------------------------------------------------
// Sequential erase/add scan over W + fused LayerNorm, packed f32x2 FMA.
// Block = (b, m-chunk of 48). 256 threads: 128 d-threads (4 floats each)
// x 2 m-groups (24 m rows each).
// ---------------------------------------------------------------------------
__global__ __launch_bounds__(256) void update_ln_kernel(
    const float* __restrict__ mem, const float* __restrict__ attn,
    const float* __restrict__ E, const float* __restrict__ Aadd,
    const float* __restrict__ gamma, const float* __restrict__ beta,
    float* __restrict__ out)
{
    const int b = blockIdx.y;
    const int m0 = blockIdx.x * 48;
    const int tid = threadIdx.x;
    const int dg = tid & 127;    // d-group lane: owns floats dg*4 .. dg*4+3
    const int mg = tid >> 7;     // m-group: rows m0 + mg*24 .. +23

    __shared__ float a_s[WW * 48];
    __shared__ float red[2][4][24][2];   // [mg][warp-in-group][j][sum,sumsq]

    unsigned long long s[24][2];
    const float4* memp = (const float4*)mem + ((size_t)(b * MM + m0 + mg * 24)) * 128 + dg;
#pragma unroll
    for (int j = 0; j < 24; j++) {
        float4 v = memp[j * 128];
        s[j][0] = pk2(v.x, v.y);
        s[j][1] = pk2(v.z, v.w);
    }
    for (int idx = tid; idx < WW * 48; idx += 256) {
        int w = idx / 48, mm = idx % 48;
        a_s[idx] = attn[((size_t)(b * WW + w)) * MM + m0 + mm];
    }
    __syncthreads();

    const float4* Ep = (const float4*)E    + (size_t)b * WW * 128 + dg;
    const float4* Ap = (const float4*)Aadd + (size_t)b * WW * 128 + dg;

    for (int w = 0; w < WW; w++) {
        float4 e4 = Ep[w * 128];
        float4 d4 = Ap[w * 128];
        unsigned long long ne01 = pk2(-e4.x, -e4.y);
        unsigned long long ne23 = pk2(-e4.z, -e4.w);
        unsigned long long dd01 = pk2(d4.x, d4.y);
        unsigned long long dd23 = pk2(d4.z, d4.w);
        const float* arow = &a_s[w * 48 + mg * 24];
#pragma unroll
        for (int j = 0; j < 24; j++) {
            float c = arow[j];
            unsigned long long c2 = pk2(c, c);
            s[j][0] = fma2(c2, fma2(ne01, s[j][0], dd01), s[j][0]);
            s[j][1] = fma2(c2, fma2(ne23, s[j][1], dd23), s[j][1]);
        }
    }

    // per-row LayerNorm: reduce over 128 d-threads (4 warps per m-group)
    const int wg = (tid >> 5) & 3;
    const int lane = tid & 31;
#pragma unroll
    for (int j = 0; j < 24; j++) {
        float x0, x1, x2, x3;
        upk2(x0, x1, s[j][0]);
        upk2(x2, x3, s[j][1]);
        float sm = x0 + x1 + x2 + x3;
        float sq = fmaf(x0, x0, fmaf(x1, x1, fmaf(x2, x2, x3 * x3)));
#pragma unroll
        for (int o = 16; o > 0; o >>= 1) {
            sm += __shfl_xor_sync(0xffffffffu, sm, o);
            sq += __shfl_xor_sync(0xffffffffu, sq, o);
        }
        if (lane == 0) { red[mg][wg][j][0] = sm; red[mg][wg][j][1] = sq; }
    }
    __syncthreads();

    const float4 g4 = ((const float4*)gamma)[dg];
    const float4 bt4 = ((const float4*)beta)[dg];
    float4* outp = (float4*)out + ((size_t)(b * MM + m0 + mg * 24)) * 128 + dg;

#pragma unroll
    for (int j = 0; j < 24; j++) {
        float Ssum = red[mg][0][j][0] + red[mg][1][j][0] + red[mg][2][j][0] + red[mg][3][j][0];
        float Qsum = red[mg][0][j][1] + red[mg][1][j][1] + red[mg][2][j][1] + red[mg][3][j][1];
        float mu = Ssum * (1.f / 512.f);
        float var = Qsum * (1.f / 512.f) - mu * mu;
        float rs = rsqrtf(var + 1e-5f);
        float x0, x1, x2, x3;
        upk2(x0, x1, s[j][0]);
        upk2(x2, x3, s[j][1]);
        float4 o;
        o.x = fmaf((x0 - mu) * rs, g4.x, bt4.x);
        o.y = fmaf((x1 - mu) * rs, g4.y, bt4.y);
        o.z = fmaf((x2 - mu) * rs, g4.z, bt4.z);
        o.w = fmaf((x3 - mu) * rs, g4.w, bt4.w);
        outp[j * 128] = o;
    }
}

// ---------------------------------------------------------------------------
extern "C" void kernel_launch(void* const* d_in, const int* in_sizes, int n_in,
                              void* d_out, int out_size)
{
    const float* memory = (const float*)d_in[0];
    const float* wtok   = (const float*)d_in[1];
    const float* Wq = (const float*)d_in[2];  const float* bq = (const float*)d_in[3];
    const float* Wk = (const float*)d_in[4];  const float* bk = (const float*)d_in[5];
    const float* We = (const float*)d_in[6];  const float* be = (const float*)d_in[7];
    const float* Wa = (const float*)d_in[8];  const float* ba = (const float*)d_in[9];
    const float* gamma = (const float*)d_in[10];
    const float* beta  = (const float*)d_in[11];
    float* out = (float*)d_out;

    float *e, *a, *s;
    __nv_bfloat16 *qb, *kb, *wt_bf, *m_bf, *wq_bf, *wk_bf, *we_bf, *wa_bf;
    cudaGetSymbolAddress((void**)&e, g_e);
    cudaGetSymbolAddress((void**)&a, g_a);
    cudaGetSymbolAddress((void**)&s, g_s);
    cudaGetSymbolAddress((void**)&qb, g_qb);
    cudaGetSymbolAddress((void**)&kb, g_kb);
    cudaGetSymbolAddress((void**)&wt_bf, g_wtok_bf);
    cudaGetSymbolAddress((void**)&m_bf, g_mem_bf);
    cudaGetSymbolAddress((void**)&wq_bf, g_Wq_bf);
    cudaGetSymbolAddress((void**)&wk_bf, g_Wk_bf);
    cudaGetSymbolAddress((void**)&we_bf, g_We_bf);
    cudaGetSymbolAddress((void**)&wa_bf, g_Wa_bf);

    // launches 0-2: conversions
    {
        int n4 = BB * WW * DD / 4;
        f2bf_kernel<<<(n4 + 255) / 256, 256>>>((const float4*)wtok, (uint2*)wt_bf, n4);
        n4 = BB * MM * DD / 4;
        f2bf_kernel<<<(n4 + 255) / 256, 256>>>((const float4*)memory, (uint2*)m_bf, n4);
        f2bf4_kernel<<<4 * (DD * DD / 4) / 256, 256>>>(
            (const float4*)Wq, (const float4*)Wk, (const float4*)We, (const float4*)Wa,
            (uint2*)wq_bf, (uint2*)wk_bf, (uint2*)we_bf, (uint2*)wa_bf);
    }

    // launches 3-6: tensor-core GEMMs (launch 5 = 'a' GEMM gets profiled by ncu -s 5)
    mma_gemm_kernel<<<dim3(BB * WW / GBM, DD / GBN), 256>>>(wt_bf, wq_bf, bq, qb, 3);
    mma_gemm_kernel<<<dim3(BB * WW / GBM, DD / GBN), 256>>>(wt_bf, we_bf, be, e, 1);
    mma_gemm_kernel<<<dim3(BB * WW / GBM, DD / GBN), 256>>>(wt_bf, wa_bf, ba, a, 2);
    mma_gemm_kernel<<<dim3(BB * MM / GBM, DD / GBN), 256>>>(m_bf, wk_bf, bk, kb, 3);

    // launch 7: fused scores + softmax (tensor cores)
    scores_softmax_kernel<<<BB, 256>>>(qb, kb, s);

    // launch 8: sequential write scan + fused layernorm (f32x2 packed FMA)
    update_ln_kernel<<<dim3(2, BB), 256>>>(memory, s, e, a, gamma, beta, out);
}

// round 4
// speedup vs baseline: 1.0862x; 1.0862x over previous
#include <cuda_runtime.h>
#include <cuda_bf16.h>
#include <cstdint>

// Problem constants
#define BB 256   // batch
#define MM 96    // memory slots
#define WW 128   // write tokens
#define DD 512   // embed dim

// ---------------- scratch (static device globals: allocation-free) ----------
__device__ __nv_bfloat16 g_wtok_bf[BB * WW * DD];
__device__ __nv_bfloat16 g_mem_bf[BB * MM * DD];
__device__ __nv_bfloat16 g_Wq_bf[DD * DD];
__device__ __nv_bfloat16 g_Wk_bf[DD * DD];
__device__ __nv_bfloat16 g_We_bf[DD * DD];
__device__ __nv_bfloat16 g_Wa_bf[DD * DD];

__device__ __nv_bfloat16 g_qb[BB * WW * DD];   // q in bf16 (scores input)
__device__ __nv_bfloat16 g_kb[BB * MM * DD];   // k in bf16 (scores input)
__device__ float g_e[BB * WW * DD];
__device__ float g_a[BB * WW * DD];
__device__ float g_s[BB * WW * MM];

static __device__ __forceinline__ uint32_t smem_u32(const void* p) {
    uint32_t a;
    asm("{ .reg .u64 t; cvta.to.shared.u64 t, %1; cvt.u32.u64 %0, t; }" : "=r"(a) : "l"(p));
    return a;
}

// ---------------------------------------------------------------------------
// fp32 -> bf16: wtok + memory in one launch
// ---------------------------------------------------------------------------
__global__ __launch_bounds__(256) void f2bf_inputs_kernel(
    const float4* __restrict__ s0, uint2* __restrict__ d0, int n0,   // wtok
    const float4* __restrict__ s1, uint2* __restrict__ d1, int n1)   // memory
{
    int i = blockIdx.x * 256 + threadIdx.x;
    int stride = gridDim.x * 256;
    int ntot = n0 + n1;
    for (; i < ntot; i += stride) {
        const float4* src = (i < n0) ? s0 : s1;
        uint2* dst = (i < n0) ? d0 : d1;
        int off = (i < n0) ? i : i - n0;
        float4 v = src[off];
        __nv_bfloat162 lo = __floats2bfloat162_rn(v.x, v.y);
        __nv_bfloat162 hi = __floats2bfloat162_rn(v.z, v.w);
        uint2 o;
        o.x = *(uint32_t*)&lo;
        o.y = *(uint32_t*)&hi;
        dst[off] = o;
    }
}

// 4 weight matrices (each DD*DD) in one launch
__global__ __launch_bounds__(256) void f2bf4_kernel(
    const float4* __restrict__ s0, const float4* __restrict__ s1,
    const float4* __restrict__ s2, const float4* __restrict__ s3,
    uint2* __restrict__ d0, uint2* __restrict__ d1,
    uint2* __restrict__ d2, uint2* __restrict__ d3)
{
    const int n4 = DD * DD / 4;  // 65536
    int i = blockIdx.x * 256 + threadIdx.x;
    int mat = i >> 16;
    int off = i & (n4 - 1);
    const float4* src = (mat == 0) ? s0 : (mat == 1) ? s1 : (mat == 2) ? s2 : s3;
    uint2* dst = (mat == 0) ? d0 : (mat == 1) ? d1 : (mat == 2) ? d2 : d3;
    float4 v = src[off];
    __nv_bfloat162 lo = __floats2bfloat162_rn(v.x, v.y);
    __nv_bfloat162 hi = __floats2bfloat162_rn(v.z, v.w);
    uint2 o;
    o.x = *(uint32_t*)&lo;
    o.y = *(uint32_t*)&hi;
    dst[off] = o;
}

// ---------------------------------------------------------------------------
// Tensor-core GEMM core (device inline): C = act(A @ Bw^T + bias)
// Tile 128x128x32, 256 threads, warp tile 64x32, mma m16n8k16 bf16.
// ---------------------------------------------------------------------------
#define GBM 128
#define GBN 128
#define GBK 32
#define LDSK 40
#define NKT (DD / GBK)   // 16

struct GemmSmem {
    __nv_bfloat16 sA[2][GBM * LDSK];
    __nv_bfloat16 sB[2][GBN * LDSK];
};

static __device__ __forceinline__ void gemm_tile(
    GemmSmem* sm,
    const __nv_bfloat16* __restrict__ A,   // [*, DD], rowbase applied by caller
    const __nv_bfloat16* __restrict__ Bw,  // [DD, DD]
    const float* __restrict__ bias,
    void* __restrict__ Cv,                 // base of output matrix
    long rowbase, int colbase, int act)
{
    const int tid = threadIdx.x;
    const int wid = tid >> 5;
    const int lane = tid & 31;
    const int wm = wid & 1;
    const int wn = wid >> 1;

    float acc[4][4][4];
#pragma unroll
    for (int mi = 0; mi < 4; mi++)
#pragma unroll
        for (int ni = 0; ni < 4; ni++)
#pragma unroll
            for (int v = 0; v < 4; v++) acc[mi][ni][v] = 0.f;

    const uint32_t sA_base = smem_u32(&sm->sA[0][0]);
    const uint32_t sB_base = smem_u32(&sm->sB[0][0]);

    const int ar0 = tid >> 2, ac0 = (tid & 3) * 8;
    const int c1 = tid + 256;
    const int ar1 = c1 >> 2, ac1 = (c1 & 3) * 8;

#define STAGE(buf, kt) do {                                                        \
    const int kk_ = (kt) * GBK;                                                    \
    const __nv_bfloat16* ga0 = A  + (rowbase + ar0) * DD + kk_ + ac0;              \
    const __nv_bfloat16* ga1 = A  + (rowbase + ar1) * DD + kk_ + ac1;              \
    const __nv_bfloat16* gb0 = Bw + (long)(colbase + ar0) * DD + kk_ + ac0;        \
    const __nv_bfloat16* gb1 = Bw + (long)(colbase + ar1) * DD + kk_ + ac1;        \
    uint32_t s_;                                                                   \
    s_ = sA_base + (uint32_t)(((buf) * GBM * LDSK + ar0 * LDSK + ac0) * 2);        \
    asm volatile("cp.async.cg.shared.global [%0], [%1], 16;\n" :: "r"(s_), "l"(ga0)); \
    s_ = sA_base + (uint32_t)(((buf) * GBM * LDSK + ar1 * LDSK + ac1) * 2);        \
    asm volatile("cp.async.cg.shared.global [%0], [%1], 16;\n" :: "r"(s_), "l"(ga1)); \
    s_ = sB_base + (uint32_t)(((buf) * GBN * LDSK + ar0 * LDSK + ac0) * 2);        \
    asm volatile("cp.async.cg.shared.global [%0], [%1], 16;\n" :: "r"(s_), "l"(gb0)); \
    s_ = sB_base + (uint32_t)(((buf) * GBN * LDSK + ar1 * LDSK + ac1) * 2);        \
    asm volatile("cp.async.cg.shared.global [%0], [%1], 16;\n" :: "r"(s_), "l"(gb1)); \
    asm volatile("cp.async.commit_group;\n");                                      \
} while (0)

    STAGE(0, 0);

    for (int kt = 0; kt < NKT; kt++) {
        if (kt + 1 < NKT) {
            STAGE((kt + 1) & 1, kt + 1);
            asm volatile("cp.async.wait_group 1;\n");
        } else {
            asm volatile("cp.async.wait_group 0;\n");
        }
        __syncthreads();

        const int buf = kt & 1;
#pragma unroll
        for (int ks = 0; ks < 2; ks++) {
            const int k0 = ks * 16;

            uint32_t af[4][4];
#pragma unroll
            for (int mi = 0; mi < 4; mi++) {
                const int m0 = wm * 64 + mi * 16;
                uint32_t addr = sA_base + (uint32_t)((buf * GBM * LDSK +
                    (m0 + (lane & 15)) * LDSK + k0 + ((lane >> 4) * 8)) * 2);
                asm volatile(
                    "ldmatrix.sync.aligned.m8n8.x4.shared.b16 {%0,%1,%2,%3}, [%4];\n"
                    : "=r"(af[mi][0]), "=r"(af[mi][1]), "=r"(af[mi][2]), "=r"(af[mi][3])
                    : "r"(addr));
            }

            uint32_t bfr[4][2];
#pragma unroll
            for (int nj = 0; nj < 2; nj++) {
                const int n0 = wn * 32 + nj * 16;
                uint32_t addr = sB_base + (uint32_t)((buf * GBN * LDSK +
                    (n0 + (lane & 7) + ((lane >> 4) << 3)) * LDSK +
                    k0 + (((lane >> 3) & 1) * 8)) * 2);
                uint32_t r0, r1, r2, r3;
                asm volatile(
                    "ldmatrix.sync.aligned.m8n8.x4.shared.b16 {%0,%1,%2,%3}, [%4];\n"
                    : "=r"(r0), "=r"(r1), "=r"(r2), "=r"(r3) : "r"(addr));
                bfr[nj * 2][0] = r0;     bfr[nj * 2][1] = r1;
                bfr[nj * 2 + 1][0] = r2; bfr[nj * 2 + 1][1] = r3;
            }

#pragma unroll
            for (int mi = 0; mi < 4; mi++)
#pragma unroll
                for (int ni = 0; ni < 4; ni++)
                    asm volatile(
                        "mma.sync.aligned.m16n8k16.row.col.f32.bf16.bf16.f32 "
                        "{%0,%1,%2,%3}, {%4,%5,%6,%7}, {%8,%9}, {%0,%1,%2,%3};\n"
                        : "+f"(acc[mi][ni][0]), "+f"(acc[mi][ni][1]),
                          "+f"(acc[mi][ni][2]), "+f"(acc[mi][ni][3])
                        : "r"(af[mi][0]), "r"(af[mi][1]), "r"(af[mi][2]), "r"(af[mi][3]),
                          "r"(bfr[ni][0]), "r"(bfr[ni][1]));
        }
        __syncthreads();
    }
#undef STAGE

    // epilogue: bias + activation
#pragma unroll
    for (int mi = 0; mi < 4; mi++) {
        const long r0 = rowbase + wm * 64 + mi * 16 + (lane >> 2);
#pragma unroll
        for (int ni = 0; ni < 4; ni++) {
            const int col = colbase + wn * 32 + ni * 8 + (lane & 3) * 2;
            const float b0 = bias[col], b1 = bias[col + 1];
            float v0 = acc[mi][ni][0] + b0;
            float v1 = acc[mi][ni][1] + b1;
            float v2 = acc[mi][ni][2] + b0;
            float v3 = acc[mi][ni][3] + b1;
            if (act == 1) {
                v0 = 1.f / (1.f + __expf(-v0)); v1 = 1.f / (1.f + __expf(-v1));
                v2 = 1.f / (1.f + __expf(-v2)); v3 = 1.f / (1.f + __expf(-v3));
            } else if (act == 2) {
                v0 = tanhf(v0); v1 = tanhf(v1);
                v2 = tanhf(v2); v3 = tanhf(v3);
            }
            if (act == 3) {
                __nv_bfloat16* Cb = (__nv_bfloat16*)Cv;
                *(__nv_bfloat162*)&Cb[r0 * DD + col] = __floats2bfloat162_rn(v0, v1);
                *(__nv_bfloat162*)&Cb[(r0 + 8) * DD + col] = __floats2bfloat162_rn(v2, v3);
            } else {
                float* C = (float*)Cv;
                *(float2*)&C[r0 * DD + col] = make_float2(v0, v1);
                *(float2*)&C[(r0 + 8) * DD + col] = make_float2(v2, v3);
            }
        }
    }
}

// Fused q/e/a projections: blockIdx.y in 0..11; [0,4) Wq->bf16, [4,8) We->sig,
// [8,12) Wa->tanh.
__global__ __launch_bounds__(256) void fused_wtok_gemm_kernel(
    const __nv_bfloat16* __restrict__ A,
    const __nv_bfloat16* __restrict__ Wq, const __nv_bfloat16* __restrict__ We,
    const __nv_bfloat16* __restrict__ Wa,
    const float* __restrict__ bq, const float* __restrict__ be,
    const float* __restrict__ ba,
    __nv_bfloat16* __restrict__ q_out, float* __restrict__ e_out,
    float* __restrict__ a_out)
{
    __shared__ GemmSmem sm;
    const int bn = blockIdx.y;
    const int mat = bn >> 2;
    const int colbase = (bn & 3) * GBN;
    const long rowbase = (long)blockIdx.x * GBM;
    if (mat == 0)
        gemm_tile(&sm, A, Wq, bq, q_out, rowbase, colbase, 3);
    else if (mat == 1)
        gemm_tile(&sm, A, We, be, e_out, rowbase, colbase, 1);
    else
        gemm_tile(&sm, A, Wa, ba, a_out, rowbase, colbase, 2);
}

__global__ __launch_bounds__(256) void k_gemm_kernel(
    const __nv_bfloat16* __restrict__ A, const __nv_bfloat16* __restrict__ Wk,
    const float* __restrict__ bk, __nv_bfloat16* __restrict__ k_out)
{
    __shared__ GemmSmem sm;
    gemm_tile(&sm, A, Wk, bk, k_out, (long)blockIdx.x * GBM, blockIdx.y * GBN, 3);
}

// ---------------------------------------------------------------------------
// Fused scores + softmax on tensor cores. One block per batch b.
// ---------------------------------------------------------------------------
__global__ __launch_bounds__(256) void scores_softmax_kernel(
    const __nv_bfloat16* __restrict__ Q, const __nv_bfloat16* __restrict__ K,
    float* __restrict__ S)
{
    __shared__ __nv_bfloat16 sQ[2][WW * LDSK];
    __shared__ __nv_bfloat16 sK[2][MM * LDSK];
    __shared__ float pmax[2][WW];
    __shared__ float psum[2][WW];

    const int b = blockIdx.x;
    const int tid = threadIdx.x;
    const int wid = tid >> 5;
    const int lane = tid & 31;
    const int wm = wid & 3;
    const int wn = wid >> 2;

    const __nv_bfloat16* Qb = Q + (size_t)b * WW * DD;
    const __nv_bfloat16* Kb = K + (size_t)b * MM * DD;

    float acc[2][6][4];
#pragma unroll
    for (int mi = 0; mi < 2; mi++)
#pragma unroll
        for (int ni = 0; ni < 6; ni++)
#pragma unroll
            for (int v = 0; v < 4; v++) acc[mi][ni][v] = 0.f;

    const uint32_t sQ_base = smem_u32(&sQ[0][0]);
    const uint32_t sK_base = smem_u32(&sK[0][0]);

    const int qr0 = tid >> 2, qc0 = (tid & 3) * 8;
    const int qc1i = tid + 256;
    const int qr1 = qc1i >> 2, qc1 = (qc1i & 3) * 8;
    const int kr0 = tid >> 2, kc0 = (tid & 3) * 8;
    const int kr1 = 64 + (tid >> 2), kc1 = (tid & 3) * 8;

#define SSTAGE(buf, kt) do {                                                       \
    const int kk_ = (kt) * GBK;                                                    \
    uint32_t s_;                                                                   \
    s_ = sQ_base + (uint32_t)(((buf) * WW * LDSK + qr0 * LDSK + qc0) * 2);         \
    asm volatile("cp.async.cg.shared.global [%0], [%1], 16;\n"                     \
                 :: "r"(s_), "l"(Qb + (size_t)qr0 * DD + kk_ + qc0));              \
    s_ = sQ_base + (uint32_t)(((buf) * WW * LDSK + qr1 * LDSK + qc1) * 2);         \
    asm volatile("cp.async.cg.shared.global [%0], [%1], 16;\n"                     \
                 :: "r"(s_), "l"(Qb + (size_t)qr1 * DD + kk_ + qc1));              \
    s_ = sK_base + (uint32_t)(((buf) * MM * LDSK + kr0 * LDSK + kc0) * 2);         \
    asm volatile("cp.async.cg.shared.global [%0], [%1], 16;\n"                     \
                 :: "r"(s_), "l"(Kb + (size_t)kr0 * DD + kk_ + kc0));              \
    if (tid < 128) {                                                               \
        s_ = sK_base + (uint32_t)(((buf) * MM * LDSK + kr1 * LDSK + kc1) * 2);     \
        asm volatile("cp.async.cg.shared.global [%0], [%1], 16;\n"                 \
                     :: "r"(s_), "l"(Kb + (size_t)kr1 * DD + kk_ + kc1));          \
    }                                                                              \
    asm volatile("cp.async.commit_group;\n");                                      \
} while (0)

    SSTAGE(0, 0);

    for (int kt = 0; kt < NKT; kt++) {
        if (kt + 1 < NKT) {
            SSTAGE((kt + 1) & 1, kt + 1);
            asm volatile("cp.async.wait_group 1;\n");
        } else {
            asm volatile("cp.async.wait_group 0;\n");
        }
        __syncthreads();

        const int buf = kt & 1;
#pragma unroll
        for (int ks = 0; ks < 2; ks++) {
            const int k0 = ks * 16;

            uint32_t af[2][4];
#pragma unroll
            for (int mi = 0; mi < 2; mi++) {
                const int m0 = wm * 32 + mi * 16;
                uint32_t addr = sQ_base + (uint32_t)((buf * WW * LDSK +
                    (m0 + (lane & 15)) * LDSK + k0 + ((lane >> 4) * 8)) * 2);
                asm volatile(
                    "ldmatrix.sync.aligned.m8n8.x4.shared.b16 {%0,%1,%2,%3}, [%4];\n"
                    : "=r"(af[mi][0]), "=r"(af[mi][1]), "=r"(af[mi][2]), "=r"(af[mi][3])
                    : "r"(addr));
            }

            uint32_t bfr[6][2];
#pragma unroll
            for (int nj = 0; nj < 3; nj++) {
                const int n0 = wn * 48 + nj * 16;
                uint32_t addr = sK_base + (uint32_t)((buf * MM * LDSK +
                    (n0 + (lane & 7) + ((lane >> 4) << 3)) * LDSK +
                    k0 + (((lane >> 3) & 1) * 8)) * 2);
                uint32_t r0, r1, r2, r3;
                asm volatile(
                    "ldmatrix.sync.aligned.m8n8.x4.shared.b16 {%0,%1,%2,%3}, [%4];\n"
                    : "=r"(r0), "=r"(r1), "=r"(r2), "=r"(r3) : "r"(addr));
                bfr[nj * 2][0] = r0;     bfr[nj * 2][1] = r1;
                bfr[nj * 2 + 1][0] = r2; bfr[nj * 2 + 1][1] = r3;
            }

#pragma unroll
            for (int mi = 0; mi < 2; mi++)
#pragma unroll
                for (int ni = 0; ni < 6; ni++)
                    asm volatile(
                        "mma.sync.aligned.m16n8k16.row.col.f32.bf16.bf16.f32 "
                        "{%0,%1,%2,%3}, {%4,%5,%6,%7}, {%8,%9}, {%0,%1,%2,%3};\n"
                        : "+f"(acc[mi][ni][0]), "+f"(acc[mi][ni][1]),
                          "+f"(acc[mi][ni][2]), "+f"(acc[mi][ni][3])
                        : "r"(af[mi][0]), "r"(af[mi][1]), "r"(af[mi][2]), "r"(af[mi][3]),
                          "r"(bfr[ni][0]), "r"(bfr[ni][1]));
        }
        __syncthreads();
    }
#undef SSTAGE

    const float scale = 0.04419417382415922f;  // 1/sqrt(512)
#pragma unroll
    for (int mi = 0; mi < 2; mi++)
#pragma unroll
        for (int ni = 0; ni < 6; ni++)
#pragma unroll
            for (int v = 0; v < 4; v++) acc[mi][ni][v] *= scale;

    int rows[2][2];
#pragma unroll
    for (int mi = 0; mi < 2; mi++) {
        rows[mi][0] = wm * 32 + mi * 16 + (lane >> 2);
        rows[mi][1] = rows[mi][0] + 8;
    }

#pragma unroll
    for (int mi = 0; mi < 2; mi++) {
#pragma unroll
        for (int h = 0; h < 2; h++) {
            float mx = -1e30f;
#pragma unroll
            for (int ni = 0; ni < 6; ni++) {
                mx = fmaxf(mx, acc[mi][ni][h * 2 + 0]);
                mx = fmaxf(mx, acc[mi][ni][h * 2 + 1]);
            }
            mx = fmaxf(mx, __shfl_xor_sync(0xffffffffu, mx, 1));
            mx = fmaxf(mx, __shfl_xor_sync(0xffffffffu, mx, 2));
            pmax[wn][rows[mi][h]] = mx;
        }
    }
    __syncthreads();

    float inv[2][2];
#pragma unroll
    for (int mi = 0; mi < 2; mi++) {
#pragma unroll
        for (int h = 0; h < 2; h++) {
            const float gmax = fmaxf(pmax[0][rows[mi][h]], pmax[1][rows[mi][h]]);
            float sm = 0.f;
#pragma unroll
            for (int ni = 0; ni < 6; ni++) {
                float e0 = __expf(acc[mi][ni][h * 2 + 0] - gmax);
                float e1 = __expf(acc[mi][ni][h * 2 + 1] - gmax);
                acc[mi][ni][h * 2 + 0] = e0;
                acc[mi][ni][h * 2 + 1] = e1;
                sm += e0 + e1;
            }
            sm += __shfl_xor_sync(0xffffffffu, sm, 1);
            sm += __shfl_xor_sync(0xffffffffu, sm, 2);
            psum[wn][rows[mi][h]] = sm;
        }
    }
    __syncthreads();

#pragma unroll
    for (int mi = 0; mi < 2; mi++)
#pragma unroll
        for (int h = 0; h < 2; h++)
            inv[mi][h] = 1.f / (psum[0][rows[mi][h]] + psum[1][rows[mi][h]]);

#pragma unroll
    for (int mi = 0; mi < 2; mi++) {
#pragma unroll
        for (int h = 0; h < 2; h++) {
            float* rowp = S + ((size_t)(b * WW + rows[mi][h])) * MM;
#pragma unroll
            for (int ni = 0; ni < 6; ni++) {
                const int col = wn * 48 + ni * 8 + (lane & 3) * 2;
                *(float2*)(rowp + col) = make_float2(
                    acc[mi][ni][h * 2 + 0] * inv[mi][h],
                    acc[mi][ni][h * 2 + 1] * inv[mi][h]);
            }
        }
    }
}

// ---------------------------------------------------------------------------
// Sequential erase/add scan over W + fused LayerNorm (scalar fmaf).
// Block = (b, m-chunk of 48). 256 threads: 128 d-threads (4 floats each)
// x 2 m-groups (24 m rows each). No per-m barriers in the scan.
// ---------------------------------------------------------------------------
__global__ __launch_bounds__(256) void update_ln_kernel(
    const float* __restrict__ mem, const float* __restrict__ attn,
    const float* __restrict__ E, const float* __restrict__ Aadd,
    const float* __restrict__ gamma, const float* __restrict__ beta,
    float* __restrict__ out)
{
    const int b = blockIdx.y;
    const int m0 = blockIdx.x * 48;
    const int tid = threadIdx.x;
    const int dg = tid & 127;    // d-group lane: owns floats dg*4 .. dg*4+3
    const int mg = tid >> 7;     // m-group: rows m0 + mg*24 .. +23

    __shared__ float a_s[WW * 48];
    __shared__ float red[2][4][24][2];

    float s0[24], s1[24], s2[24], s3[24];
    const float4* memp = (const float4*)mem + ((size_t)(b * MM + m0 + mg * 24)) * 128 + dg;
#pragma unroll
    for (int j = 0; j < 24; j++) {
        float4 v = memp[j * 128];
        s0[j] = v.x; s1[j] = v.y; s2[j] = v.z; s3[j] = v.w;
    }
    for (int idx = tid; idx < WW * 48; idx += 256) {
        int w = idx / 48, mm = idx % 48;
        a_s[idx] = attn[((size_t)(b * WW + w)) * MM + m0 + mm];
    }
    __syncthreads();

    const float4* Ep = (const float4*)E    + (size_t)b * WW * 128 + dg;
    const float4* Ap = (const float4*)Aadd + (size_t)b * WW * 128 + dg;

    for (int w = 0; w < WW; w++) {
        float4 e4 = Ep[w * 128];
        float4 d4 = Ap[w * 128];
        const float ne0 = -e4.x, ne1 = -e4.y, ne2 = -e4.z, ne3 = -e4.w;
        const float* arow = &a_s[w * 48 + mg * 24];
#pragma unroll
        for (int j = 0; j < 24; j++) {
            float c = arow[j];
            s0[j] = fmaf(c, fmaf(ne0, s0[j], d4.x), s0[j]);
            s1[j] = fmaf(c, fmaf(ne1, s1[j], d4.y), s1[j]);
            s2[j] = fmaf(c, fmaf(ne2, s2[j], d4.z), s2[j]);
            s3[j] = fmaf(c, fmaf(ne3, s3[j], d4.w), s3[j]);
        }
    }

    // per-row LayerNorm: reduce over 128 d-threads (4 warps per m-group)
    const int wg = (tid >> 5) & 3;
    const int lane = tid & 31;
#pragma unroll
    for (int j = 0; j < 24; j++) {
        float sm = s0[j] + s1[j] + s2[j] + s3[j];
        float sq = fmaf(s0[j], s0[j], fmaf(s1[j], s1[j],
                   fmaf(s2[j], s2[j], s3[j] * s3[j])));
#pragma unroll
        for (int o = 16; o > 0; o >>= 1) {
            sm += __shfl_xor_sync(0xffffffffu, sm, o);
            sq += __shfl_xor_sync(0xffffffffu, sq, o);
        }
        if (lane == 0) { red[mg][wg][j][0] = sm; red[mg][wg][j][1] = sq; }
    }
    __syncthreads();

    const float4 g4 = ((const float4*)gamma)[dg];
    const float4 bt4 = ((const float4*)beta)[dg];
    float4* outp = (float4*)out + ((size_t)(b * MM + m0 + mg * 24)) * 128 + dg;

#pragma unroll
    for (int j = 0; j < 24; j++) {
        float Ssum = red[mg][0][j][0] + red[mg][1][j][0] + red[mg][2][j][0] + red[mg][3][j][0];
        float Qsum = red[mg][0][j][1] + red[mg][1][j][1] + red[mg][2][j][1] + red[mg][3][j][1];
        float mu = Ssum * (1.f / 512.f);
        float var = Qsum * (1.f / 512.f) - mu * mu;
        float rs = rsqrtf(var + 1e-5f);
        float4 o;
        o.x = fmaf((s0[j] - mu) * rs, g4.x, bt4.x);
        o.y = fmaf((s1[j] - mu) * rs, g4.y, bt4.y);
        o.z = fmaf((s2[j] - mu) * rs, g4.z, bt4.z);
        o.w = fmaf((s3[j] - mu) * rs, g4.w, bt4.w);
        outp[j * 128] = o;
    }
}

// ---------------------------------------------------------------------------
extern "C" void kernel_launch(void* const* d_in, const int* in_sizes, int n_in,
                              void* d_out, int out_size)
{
    const float* memory = (const float*)d_in[0];
    const float* wtok   = (const float*)d_in[1];
    const float* Wq = (const float*)d_in[2];  const float* bq = (const float*)d_in[3];
    const float* Wk = (const float*)d_in[4];  const float* bk = (const float*)d_in[5];
    const float* We = (const float*)d_in[6];  const float* be = (const float*)d_in[7];
    const float* Wa = (const float*)d_in[8];  const float* ba = (const float*)d_in[9];
    const float* gamma = (const float*)d_in[10];
    const float* beta  = (const float*)d_in[11];
    float* out = (float*)d_out;

    float *e, *a, *s;
    __nv_bfloat16 *qb, *kb, *wt_bf, *m_bf, *wq_bf, *wk_bf, *we_bf, *wa_bf;
    cudaGetSymbolAddress((void**)&e, g_e);
    cudaGetSymbolAddress((void**)&a, g_a);
    cudaGetSymbolAddress((void**)&s, g_s);
    cudaGetSymbolAddress((void**)&qb, g_qb);
    cudaGetSymbolAddress((void**)&kb, g_kb);
    cudaGetSymbolAddress((void**)&wt_bf, g_wtok_bf);
    cudaGetSymbolAddress((void**)&m_bf, g_mem_bf);
    cudaGetSymbolAddress((void**)&wq_bf, g_Wq_bf);
    cudaGetSymbolAddress((void**)&wk_bf, g_Wk_bf);
    cudaGetSymbolAddress((void**)&we_bf, g_We_bf);
    cudaGetSymbolAddress((void**)&wa_bf, g_Wa_bf);

    // launch 0: input conversions (wtok + memory)
    {
        int n0 = BB * WW * DD / 4;
        int n1 = BB * MM * DD / 4;
        f2bf_inputs_kernel<<<2048, 256>>>(
            (const float4*)wtok, (uint2*)wt_bf, n0,
            (const float4*)memory, (uint2*)m_bf, n1);
    }
    // launch 1: weight conversions
    f2bf4_kernel<<<4 * (DD * DD / 4) / 256, 256>>>(
        (const float4*)Wq, (const float4*)Wk, (const float4*)We, (const float4*)Wa,
        (uint2*)wq_bf, (uint2*)wk_bf, (uint2*)we_bf, (uint2*)wa_bf);

    // launch 2: fused q/e/a projections (one launch, 3072 CTAs)
    fused_wtok_gemm_kernel<<<dim3(BB * WW / GBM, 12), 256>>>(
        wt_bf, wq_bf, we_bf, wa_bf, bq, be, ba, qb, e, a);

    // launch 3: k projection
    k_gemm_kernel<<<dim3(BB * MM / GBM, DD / GBN), 256>>>(m_bf, wk_bf, bk, kb);

    // launch 4: fused scores + softmax (tensor cores)
    scores_softmax_kernel<<<BB, 256>>>(qb, kb, s);

    // launch 5: sequential write scan + fused layernorm  (<- ncu -s 5 target)
    update_ln_kernel<<<dim3(2, BB), 256>>>(memory, s, e, a, gamma, beta, out);
}

// round 5
// speedup vs baseline: 1.1935x; 1.0988x over previous
#include <cuda_runtime.h>
#include <cuda_bf16.h>
#include <cstdint>

// Problem constants
#define BB 256   // batch
#define MM 96    // memory slots
#define WW 128   // write tokens
#define DD 512   // embed dim

// ---------------- scratch (static device globals: allocation-free) ----------
__device__ __nv_bfloat16 g_wtok_bf[BB * WW * DD];
__device__ __nv_bfloat16 g_mem_bf[BB * MM * DD];
__device__ __nv_bfloat16 g_Wq_bf[DD * DD];
__device__ __nv_bfloat16 g_Wk_bf[DD * DD];
__device__ __nv_bfloat16 g_We_bf[DD * DD];
__device__ __nv_bfloat16 g_Wa_bf[DD * DD];

__device__ __nv_bfloat16 g_qb[BB * WW * DD];   // q in bf16 (scores input)
__device__ __nv_bfloat16 g_kb[BB * MM * DD];   // k in bf16 (scores input)
__device__ float g_e[BB * WW * DD];
__device__ float g_a[BB * WW * DD];            // NEGATED tanh (scan convention)
__device__ float g_s[BB * WW * MM];

static __device__ __forceinline__ uint32_t smem_u32(const void* p) {
    uint32_t a;
    asm("{ .reg .u64 t; cvta.to.shared.u64 t, %1; cvt.u32.u64 %0, t; }" : "=r"(a) : "l"(p));
    return a;
}

static __device__ __forceinline__ unsigned long long pk2(float x, float y) {
    unsigned long long r;
    asm("mov.b64 %0, {%1, %2};" : "=l"(r) : "f"(x), "f"(y));
    return r;
}
static __device__ __forceinline__ void upk2(float& x, float& y, unsigned long long r) {
    asm("mov.b64 {%0, %1}, %2;" : "=f"(x), "=f"(y) : "l"(r));
}
static __device__ __forceinline__ unsigned long long fma2(
    unsigned long long a, unsigned long long b, unsigned long long c) {
    unsigned long long d;
    asm("fma.rn.f32x2 %0, %1, %2, %3;" : "=l"(d) : "l"(a), "l"(b), "l"(c));
    return d;
}

// ---------------------------------------------------------------------------
// fp32 -> bf16: wtok + memory in one launch
// ---------------------------------------------------------------------------
__global__ __launch_bounds__(256) void f2bf_inputs_kernel(
    const float4* __restrict__ s0, uint2* __restrict__ d0, int n0,
    const float4* __restrict__ s1, uint2* __restrict__ d1, int n1)
{
    int i = blockIdx.x * 256 + threadIdx.x;
    int stride = gridDim.x * 256;
    int ntot = n0 + n1;
    for (; i < ntot; i += stride) {
        const float4* src = (i < n0) ? s0 : s1;
        uint2* dst = (i < n0) ? d0 : d1;
        int off = (i < n0) ? i : i - n0;
        float4 v = src[off];
        __nv_bfloat162 lo = __floats2bfloat162_rn(v.x, v.y);
        __nv_bfloat162 hi = __floats2bfloat162_rn(v.z, v.w);
        uint2 o;
        o.x = *(uint32_t*)&lo;
        o.y = *(uint32_t*)&hi;
        dst[off] = o;
    }
}

// 4 weight matrices (each DD*DD) in one launch
__global__ __launch_bounds__(256) void f2bf4_kernel(
    const float4* __restrict__ s0, const float4* __restrict__ s1,
    const float4* __restrict__ s2, const float4* __restrict__ s3,
    uint2* __restrict__ d0, uint2* __restrict__ d1,
    uint2* __restrict__ d2, uint2* __restrict__ d3)
{
    const int n4 = DD * DD / 4;  // 65536
    int i = blockIdx.x * 256 + threadIdx.x;
    int mat = i >> 16;
    int off = i & (n4 - 1);
    const float4* src = (mat == 0) ? s0 : (mat == 1) ? s1 : (mat == 2) ? s2 : s3;
    uint2* dst = (mat == 0) ? d0 : (mat == 1) ? d1 : (mat == 2) ? d2 : d3;
    float4 v = src[off];
    __nv_bfloat162 lo = __floats2bfloat162_rn(v.x, v.y);
    __nv_bfloat162 hi = __floats2bfloat162_rn(v.z, v.w);
    uint2 o;
    o.x = *(uint32_t*)&lo;
    o.y = *(uint32_t*)&hi;
    dst[off] = o;
}

// ---------------------------------------------------------------------------
// Tensor-core GEMM core: C = act(A @ Bw^T + bias)
// act: 1=sigmoid fp32, 2=NEGATED tanh fp32, 3=none bf16 out
// ---------------------------------------------------------------------------
#define GBM 128
#define GBN 128
#define GBK 32
#define LDSK 40
#define NKT (DD / GBK)   // 16

struct GemmSmem {
    __nv_bfloat16 sA[2][GBM * LDSK];
    __nv_bfloat16 sB[2][GBN * LDSK];
};

static __device__ __forceinline__ void gemm_tile(
    GemmSmem* sm,
    const __nv_bfloat16* __restrict__ A,
    const __nv_bfloat16* __restrict__ Bw,
    const float* __restrict__ bias,
    void* __restrict__ Cv,
    long rowbase, int colbase, int act)
{
    const int tid = threadIdx.x;
    const int wid = tid >> 5;
    const int lane = tid & 31;
    const int wm = wid & 1;
    const int wn = wid >> 1;

    float acc[4][4][4];
#pragma unroll
    for (int mi = 0; mi < 4; mi++)
#pragma unroll
        for (int ni = 0; ni < 4; ni++)
#pragma unroll
            for (int v = 0; v < 4; v++) acc[mi][ni][v] = 0.f;

    const uint32_t sA_base = smem_u32(&sm->sA[0][0]);
    const uint32_t sB_base = smem_u32(&sm->sB[0][0]);

    const int ar0 = tid >> 2, ac0 = (tid & 3) * 8;
    const int c1 = tid + 256;
    const int ar1 = c1 >> 2, ac1 = (c1 & 3) * 8;

#define STAGE(buf, kt) do {                                                        \
    const int kk_ = (kt) * GBK;                                                    \
    const __nv_bfloat16* ga0 = A  + (rowbase + ar0) * DD + kk_ + ac0;              \
    const __nv_bfloat16* ga1 = A  + (rowbase + ar1) * DD + kk_ + ac1;              \
    const __nv_bfloat16* gb0 = Bw + (long)(colbase + ar0) * DD + kk_ + ac0;        \
    const __nv_bfloat16* gb1 = Bw + (long)(colbase + ar1) * DD + kk_ + ac1;        \
    uint32_t s_;                                                                   \
    s_ = sA_base + (uint32_t)(((buf) * GBM * LDSK + ar0 * LDSK + ac0) * 2);        \
    asm volatile("cp.async.cg.shared.global [%0], [%1], 16;\n" :: "r"(s_), "l"(ga0)); \
    s_ = sA_base + (uint32_t)(((buf) * GBM * LDSK + ar1 * LDSK + ac1) * 2);        \
    asm volatile("cp.async.cg.shared.global [%0], [%1], 16;\n" :: "r"(s_), "l"(ga1)); \
    s_ = sB_base + (uint32_t)(((buf) * GBN * LDSK + ar0 * LDSK + ac0) * 2);        \
    asm volatile("cp.async.cg.shared.global [%0], [%1], 16;\n" :: "r"(s_), "l"(gb0)); \
    s_ = sB_base + (uint32_t)(((buf) * GBN * LDSK + ar1 * LDSK + ac1) * 2);        \
    asm volatile("cp.async.cg.shared.global [%0], [%1], 16;\n" :: "r"(s_), "l"(gb1)); \
    asm volatile("cp.async.commit_group;\n");                                      \
} while (0)

    STAGE(0, 0);

    for (int kt = 0; kt < NKT; kt++) {
        if (kt + 1 < NKT) {
            STAGE((kt + 1) & 1, kt + 1);
            asm volatile("cp.async.wait_group 1;\n");
        } else {
            asm volatile("cp.async.wait_group 0;\n");
        }
        __syncthreads();

        const int buf = kt & 1;
#pragma unroll
        for (int ks = 0; ks < 2; ks++) {
            const int k0 = ks * 16;

            uint32_t af[4][4];
#pragma unroll
            for (int mi = 0; mi < 4; mi++) {
                const int m0 = wm * 64 + mi * 16;
                uint32_t addr = sA_base + (uint32_t)((buf * GBM * LDSK +
                    (m0 + (lane & 15)) * LDSK + k0 + ((lane >> 4) * 8)) * 2);
                asm volatile(
                    "ldmatrix.sync.aligned.m8n8.x4.shared.b16 {%0,%1,%2,%3}, [%4];\n"
                    : "=r"(af[mi][0]), "=r"(af[mi][1]), "=r"(af[mi][2]), "=r"(af[mi][3])
                    : "r"(addr));
            }

            uint32_t bfr[4][2];
#pragma unroll
            for (int nj = 0; nj < 2; nj++) {
                const int n0 = wn * 32 + nj * 16;
                uint32_t addr = sB_base + (uint32_t)((buf * GBN * LDSK +
                    (n0 + (lane & 7) + ((lane >> 4) << 3)) * LDSK +
                    k0 + (((lane >> 3) & 1) * 8)) * 2);
                uint32_t r0, r1, r2, r3;
                asm volatile(
                    "ldmatrix.sync.aligned.m8n8.x4.shared.b16 {%0,%1,%2,%3}, [%4];\n"
                    : "=r"(r0), "=r"(r1), "=r"(r2), "=r"(r3) : "r"(addr));
                bfr[nj * 2][0] = r0;     bfr[nj * 2][1] = r1;
                bfr[nj * 2 + 1][0] = r2; bfr[nj * 2 + 1][1] = r3;
            }

#pragma unroll
            for (int mi = 0; mi < 4; mi++)
#pragma unroll
                for (int ni = 0; ni < 4; ni++)
                    asm volatile(
                        "mma.sync.aligned.m16n8k16.row.col.f32.bf16.bf16.f32 "
                        "{%0,%1,%2,%3}, {%4,%5,%6,%7}, {%8,%9}, {%0,%1,%2,%3};\n"
                        : "+f"(acc[mi][ni][0]), "+f"(acc[mi][ni][1]),
                          "+f"(acc[mi][ni][2]), "+f"(acc[mi][ni][3])
                        : "r"(af[mi][0]), "r"(af[mi][1]), "r"(af[mi][2]), "r"(af[mi][3]),
                          "r"(bfr[ni][0]), "r"(bfr[ni][1]));
        }
        __syncthreads();
    }
#undef STAGE

#pragma unroll
    for (int mi = 0; mi < 4; mi++) {
        const long r0 = rowbase + wm * 64 + mi * 16 + (lane >> 2);
#pragma unroll
        for (int ni = 0; ni < 4; ni++) {
            const int col = colbase + wn * 32 + ni * 8 + (lane & 3) * 2;
            const float b0 = bias[col], b1 = bias[col + 1];
            float v0 = acc[mi][ni][0] + b0;
            float v1 = acc[mi][ni][1] + b1;
            float v2 = acc[mi][ni][2] + b0;
            float v3 = acc[mi][ni][3] + b1;
            if (act == 1) {
                v0 = 1.f / (1.f + __expf(-v0)); v1 = 1.f / (1.f + __expf(-v1));
                v2 = 1.f / (1.f + __expf(-v2)); v3 = 1.f / (1.f + __expf(-v3));
            } else if (act == 2) {
                v0 = -tanhf(v0); v1 = -tanhf(v1);   // negated for scan FFMA2 form
                v2 = -tanhf(v2); v3 = -tanhf(v3);
            }
            if (act == 3) {
                __nv_bfloat16* Cb = (__nv_bfloat16*)Cv;
                *(__nv_bfloat162*)&Cb[r0 * DD + col] = __floats2bfloat162_rn(v0, v1);
                *(__nv_bfloat162*)&Cb[(r0 + 8) * DD + col] = __floats2bfloat162_rn(v2, v3);
            } else {
                float* C = (float*)Cv;
                *(float2*)&C[r0 * DD + col] = make_float2(v0, v1);
                *(float2*)&C[(r0 + 8) * DD + col] = make_float2(v2, v3);
            }
        }
    }
}

// Fused q/e/a projections: blockIdx.y 0..11
__global__ __launch_bounds__(256) void fused_wtok_gemm_kernel(
    const __nv_bfloat16* __restrict__ A,
    const __nv_bfloat16* __restrict__ Wq, const __nv_bfloat16* __restrict__ We,
    const __nv_bfloat16* __restrict__ Wa,
    const float* __restrict__ bq, const float* __restrict__ be,
    const float* __restrict__ ba,
    __nv_bfloat16* __restrict__ q_out, float* __restrict__ e_out,
    float* __restrict__ a_out)
{
    __shared__ GemmSmem sm;
    const int bn = blockIdx.y;
    const int mat = bn >> 2;
    const int colbase = (bn & 3) * GBN;
    const long rowbase = (long)blockIdx.x * GBM;
    if (mat == 0)
        gemm_tile(&sm, A, Wq, bq, q_out, rowbase, colbase, 3);
    else if (mat == 1)
        gemm_tile(&sm, A, We, be, e_out, rowbase, colbase, 1);
    else
        gemm_tile(&sm, A, Wa, ba, a_out, rowbase, colbase, 2);
}

__global__ __launch_bounds__(256) void k_gemm_kernel(
    const __nv_bfloat16* __restrict__ A, const __nv_bfloat16* __restrict__ Wk,
    const float* __restrict__ bk, __nv_bfloat16* __restrict__ k_out)
{
    __shared__ GemmSmem sm;
    gemm_tile(&sm, A, Wk, bk, k_out, (long)blockIdx.x * GBM, blockIdx.y * GBN, 3);
}

// ---------------------------------------------------------------------------
// Fused scores + softmax on tensor cores. One block per batch b.
// ---------------------------------------------------------------------------
__global__ __launch_bounds__(256) void scores_softmax_kernel(
    const __nv_bfloat16* __restrict__ Q, const __nv_bfloat16* __restrict__ K,
    float* __restrict__ S)
{
    __shared__ __nv_bfloat16 sQ[2][WW * LDSK];
    __shared__ __nv_bfloat16 sK[2][MM * LDSK];
    __shared__ float pmax[2][WW];
    __shared__ float psum[2][WW];

    const int b = blockIdx.x;
    const int tid = threadIdx.x;
    const int wid = tid >> 5;
    const int lane = tid & 31;
    const int wm = wid & 3;
    const int wn = wid >> 2;

    const __nv_bfloat16* Qb = Q + (size_t)b * WW * DD;
    const __nv_bfloat16* Kb = K + (size_t)b * MM * DD;

    float acc[2][6][4];
#pragma unroll
    for (int mi = 0; mi < 2; mi++)
#pragma unroll
        for (int ni = 0; ni < 6; ni++)
#pragma unroll
            for (int v = 0; v < 4; v++) acc[mi][ni][v] = 0.f;

    const uint32_t sQ_base = smem_u32(&sQ[0][0]);
    const uint32_t sK_base = smem_u32(&sK[0][0]);

    const int qr0 = tid >> 2, qc0 = (tid & 3) * 8;
    const int qc1i = tid + 256;
    const int qr1 = qc1i >> 2, qc1 = (qc1i & 3) * 8;
    const int kr0 = tid >> 2, kc0 = (tid & 3) * 8;
    const int kr1 = 64 + (tid >> 2), kc1 = (tid & 3) * 8;

#define SSTAGE(buf, kt) do {                                                       \
    const int kk_ = (kt) * GBK;                                                    \
    uint32_t s_;                                                                   \
    s_ = sQ_base + (uint32_t)(((buf) * WW * LDSK + qr0 * LDSK + qc0) * 2);         \
    asm volatile("cp.async.cg.shared.global [%0], [%1], 16;\n"                     \
                 :: "r"(s_), "l"(Qb + (size_t)qr0 * DD + kk_ + qc0));              \
    s_ = sQ_base + (uint32_t)(((buf) * WW * LDSK + qr1 * LDSK + qc1) * 2);         \
    asm volatile("cp.async.cg.shared.global [%0], [%1], 16;\n"                     \
                 :: "r"(s_), "l"(Qb + (size_t)qr1 * DD + kk_ + qc1));              \
    s_ = sK_base + (uint32_t)(((buf) * MM * LDSK + kr0 * LDSK + kc0) * 2);         \
    asm volatile("cp.async.cg.shared.global [%0], [%1], 16;\n"                     \
                 :: "r"(s_), "l"(Kb + (size_t)kr0 * DD + kk_ + kc0));              \
    if (tid < 128) {                                                               \
        s_ = sK_base + (uint32_t)(((buf) * MM * LDSK + kr1 * LDSK + kc1) * 2);     \
        asm volatile("cp.async.cg.shared.global [%0], [%1], 16;\n"                 \
                     :: "r"(s_), "l"(Kb + (size_t)kr1 * DD + kk_ + kc1));          \
    }                                                                              \
    asm volatile("cp.async.commit_group;\n");                                      \
} while (0)

    SSTAGE(0, 0);

    for (int kt = 0; kt < NKT; kt++) {
        if (kt + 1 < NKT) {
            SSTAGE((kt + 1) & 1, kt + 1);
            asm volatile("cp.async.wait_group 1;\n");
        } else {
            asm volatile("cp.async.wait_group 0;\n");
        }
        __syncthreads();

        const int buf = kt & 1;
#pragma unroll
        for (int ks = 0; ks < 2; ks++) {
            const int k0 = ks * 16;

            uint32_t af[2][4];
#pragma unroll
            for (int mi = 0; mi < 2; mi++) {
                const int m0 = wm * 32 + mi * 16;
                uint32_t addr = sQ_base + (uint32_t)((buf * WW * LDSK +
                    (m0 + (lane & 15)) * LDSK + k0 + ((lane >> 4) * 8)) * 2);
                asm volatile(
                    "ldmatrix.sync.aligned.m8n8.x4.shared.b16 {%0,%1,%2,%3}, [%4];\n"
                    : "=r"(af[mi][0]), "=r"(af[mi][1]), "=r"(af[mi][2]), "=r"(af[mi][3])
                    : "r"(addr));
            }

            uint32_t bfr[6][2];
#pragma unroll
            for (int nj = 0; nj < 3; nj++) {
                const int n0 = wn * 48 + nj * 16;
                uint32_t addr = sK_base + (uint32_t)((buf * MM * LDSK +
                    (n0 + (lane & 7) + ((lane >> 4) << 3)) * LDSK +
                    k0 + (((lane >> 3) & 1) * 8)) * 2);
                uint32_t r0, r1, r2, r3;
                asm volatile(
                    "ldmatrix.sync.aligned.m8n8.x4.shared.b16 {%0,%1,%2,%3}, [%4];\n"
                    : "=r"(r0), "=r"(r1), "=r"(r2), "=r"(r3) : "r"(addr));
                bfr[nj * 2][0] = r0;     bfr[nj * 2][1] = r1;
                bfr[nj * 2 + 1][0] = r2; bfr[nj * 2 + 1][1] = r3;
            }

#pragma unroll
            for (int mi = 0; mi < 2; mi++)
#pragma unroll
                for (int ni = 0; ni < 6; ni++)
                    asm volatile(
                        "mma.sync.aligned.m16n8k16.row.col.f32.bf16.bf16.f32 "
                        "{%0,%1,%2,%3}, {%4,%5,%6,%7}, {%8,%9}, {%0,%1,%2,%3};\n"
                        : "+f"(acc[mi][ni][0]), "+f"(acc[mi][ni][1]),
                          "+f"(acc[mi][ni][2]), "+f"(acc[mi][ni][3])
                        : "r"(af[mi][0]), "r"(af[mi][1]), "r"(af[mi][2]), "r"(af[mi][3]),
                          "r"(bfr[ni][0]), "r"(bfr[ni][1]));
        }
        __syncthreads();
    }
#undef SSTAGE

    const float scale = 0.04419417382415922f;  // 1/sqrt(512)
#pragma unroll
    for (int mi = 0; mi < 2; mi++)
#pragma unroll
        for (int ni = 0; ni < 6; ni++)
#pragma unroll
            for (int v = 0; v < 4; v++) acc[mi][ni][v] *= scale;

    int rows[2][2];
#pragma unroll
    for (int mi = 0; mi < 2; mi++) {
        rows[mi][0] = wm * 32 + mi * 16 + (lane >> 2);
        rows[mi][1] = rows[mi][0] + 8;
    }

#pragma unroll
    for (int mi = 0; mi < 2; mi++) {
#pragma unroll
        for (int h = 0; h < 2; h++) {
            float mx = -1e30f;
#pragma unroll
            for (int ni = 0; ni < 6; ni++) {
                mx = fmaxf(mx, acc[mi][ni][h * 2 + 0]);
                mx = fmaxf(mx, acc[mi][ni][h * 2 + 1]);
            }
            mx = fmaxf(mx, __shfl_xor_sync(0xffffffffu, mx, 1));
            mx = fmaxf(mx, __shfl_xor_sync(0xffffffffu, mx, 2));
            pmax[wn][rows[mi][h]] = mx;
        }
    }
    __syncthreads();

    float inv[2][2];
#pragma unroll
    for (int mi = 0; mi < 2; mi++) {
#pragma unroll
        for (int h = 0; h < 2; h++) {
            const float gmax = fmaxf(pmax[0][rows[mi][h]], pmax[1][rows[mi][h]]);
            float sm = 0.f;
#pragma unroll
            for (int ni = 0; ni < 6; ni++) {
                float e0 = __expf(acc[mi][ni][h * 2 + 0] - gmax);
                float e1 = __expf(acc[mi][ni][h * 2 + 1] - gmax);
                acc[mi][ni][h * 2 + 0] = e0;
                acc[mi][ni][h * 2 + 1] = e1;
                sm += e0 + e1;
            }
            sm += __shfl_xor_sync(0xffffffffu, sm, 1);
            sm += __shfl_xor_sync(0xffffffffu, sm, 2);
            psum[wn][rows[mi][h]] = sm;
        }
    }
    __syncthreads();

#pragma unroll
    for (int mi = 0; mi < 2; mi++)
#pragma unroll
        for (int h = 0; h < 2; h++)
            inv[mi][h] = 1.f / (psum[0][rows[mi][h]] + psum[1][rows[mi][h]]);

#pragma unroll
    for (int mi = 0; mi < 2; mi++) {
#pragma unroll
        for (int h = 0; h < 2; h++) {
            float* rowp = S + ((size_t)(b * WW + rows[mi][h])) * MM;
#pragma unroll
            for (int ni = 0; ni < 6; ni++) {
                const int col = wn * 48 + ni * 8 + (lane & 3) * 2;
                *(float2*)(rowp + col) = make_float2(
                    acc[mi][ni][h * 2 + 0] * inv[mi][h],
                    acc[mi][ni][h * 2 + 1] * inv[mi][h]);
            }
        }
    }
}

// ---------------------------------------------------------------------------
// Sequential erase/add scan over W + fused LayerNorm, f32x2 done right.
// Block = (b, m-chunk of 24). 256 threads: 128 d-lanes (4 floats = 2 pairs)
// x 2 m-groups (12 rows each). State: 24 ULL pairs/thread.
// Inner step: x = fma2(-c, fma2(e, x, -ad), x) = x*(1-c*e) + c*ad.
//   (-c,-c) pre-duplicated in smem; -ad comes from negated tanh GEMM output;
//   e/-ad loaded as ulonglong2 (reg pairs direct from LDG.128).
// ---------------------------------------------------------------------------
__global__ __launch_bounds__(256) void update_ln_kernel(
    const float* __restrict__ mem, const float* __restrict__ attn,
    const float* __restrict__ E, const float* __restrict__ Aneg,
    const float* __restrict__ gamma, const float* __restrict__ beta,
    float* __restrict__ out)
{
    const int b = blockIdx.y;
    const int m0 = blockIdx.x * 24;
    const int tid = threadIdx.x;
    const int dg = tid & 127;    // owns floats dg*4 .. dg*4+3
    const int mg = tid >> 7;     // rows m0 + mg*12 + j

    __shared__ unsigned long long a_s2[2][WW][12];   // (-c,-c) per (mg,w,j): 24KB
    __shared__ float red[2][4][12][2];

    unsigned long long s[12][2];
    const float4* memp = (const float4*)mem + ((size_t)(b * MM + m0 + mg * 12)) * 128 + dg;
#pragma unroll
    for (int j = 0; j < 12; j++) {
        float4 v = memp[j * 128];
        s[j][0] = pk2(v.x, v.y);
        s[j][1] = pk2(v.z, v.w);
    }
    for (int idx = tid; idx < WW * 24; idx += 256) {
        int w = idx / 24, mm = idx % 24;
        float c = attn[((size_t)(b * WW + w)) * MM + m0 + mm];
        a_s2[mm / 12][w][mm % 12] = pk2(-c, -c);
    }
    __syncthreads();

    const ulonglong2* Ep = (const ulonglong2*)E    + (size_t)b * WW * 128 + dg;
    const ulonglong2* Ap = (const ulonglong2*)Aneg + (size_t)b * WW * 128 + dg;

    for (int w = 0; w < WW; w++) {
        ulonglong2 eu = Ep[w * 128];
        ulonglong2 au = Ap[w * 128];   // already negated add-vector
        const unsigned long long* crow = &a_s2[mg][w][0];
#pragma unroll
        for (int j = 0; j < 12; j++) {
            unsigned long long nc = crow[j];
            s[j][0] = fma2(nc, fma2(eu.x, s[j][0], au.x), s[j][0]);
            s[j][1] = fma2(nc, fma2(eu.y, s[j][1], au.y), s[j][1]);
        }
    }

    // per-row LayerNorm: reduce over 128 d-lanes (4 warps per m-group)
    const int wg = (tid >> 5) & 3;
    const int lane = tid & 31;
#pragma unroll
    for (int j = 0; j < 12; j++) {
        float x0, x1, x2, x3;
        upk2(x0, x1, s[j][0]);
        upk2(x2, x3, s[j][1]);
        float sm = x0 + x1 + x2 + x3;
        float sq = fmaf(x0, x0, fmaf(x1, x1, fmaf(x2, x2, x3 * x3)));
#pragma unroll
        for (int o = 16; o > 0; o >>= 1) {
            sm += __shfl_xor_sync(0xffffffffu, sm, o);
            sq += __shfl_xor_sync(0xffffffffu, sq, o);
        }
        if (lane == 0) { red[mg][wg][j][0] = sm; red[mg][wg][j][1] = sq; }
    }
    __syncthreads();

    const float4 g4 = ((const float4*)gamma)[dg];
    const float4 bt4 = ((const float4*)beta)[dg];
    float4* outp = (float4*)out + ((size_t)(b * MM + m0 + mg * 12)) * 128 + dg;

#pragma unroll
    for (int j = 0; j < 12; j++) {
        float Ssum = red[mg][0][j][0] + red[mg][1][j][0] + red[mg][2][j][0] + red[mg][3][j][0];
        float Qsum = red[mg][0][j][1] + red[mg][1][j][1] + red[mg][2][j][1] + red[mg][3][j][1];
        float mu = Ssum * (1.f / 512.f);
        float var = Qsum * (1.f / 512.f) - mu * mu;
        float rs = rsqrtf(var + 1e-5f);
        float x0, x1, x2, x3;
        upk2(x0, x1, s[j][0]);
        upk2(x2, x3, s[j][1]);
        float4 o;
        o.x = fmaf((x0 - mu) * rs, g4.x, bt4.x);
        o.y = fmaf((x1 - mu) * rs, g4.y, bt4.y);
        o.z = fmaf((x2 - mu) * rs, g4.z, bt4.z);
        o.w = fmaf((x3 - mu) * rs, g4.w, bt4.w);
        outp[j * 128] = o;
    }
}

// ---------------------------------------------------------------------------
extern "C" void kernel_launch(void* const* d_in, const int* in_sizes, int n_in,
                              void* d_out, int out_size)
{
    const float* memory = (const float*)d_in[0];
    const float* wtok   = (const float*)d_in[1];
    const float* Wq = (const float*)d_in[2];  const float* bq = (const float*)d_in[3];
    const float* Wk = (const float*)d_in[4];  const float* bk = (const float*)d_in[5];
    const float* We = (const float*)d_in[6];  const float* be = (const float*)d_in[7];
    const float* Wa = (const float*)d_in[8];  const float* ba = (const float*)d_in[9];
    const float* gamma = (const float*)d_in[10];
    const float* beta  = (const float*)d_in[11];
    float* out = (float*)d_out;

    float *e, *a, *s;
    __nv_bfloat16 *qb, *kb, *wt_bf, *m_bf, *wq_bf, *wk_bf, *we_bf, *wa_bf;
    cudaGetSymbolAddress((void**)&e, g_e);
    cudaGetSymbolAddress((void**)&a, g_a);
    cudaGetSymbolAddress((void**)&s, g_s);
    cudaGetSymbolAddress((void**)&qb, g_qb);
    cudaGetSymbolAddress((void**)&kb, g_kb);
    cudaGetSymbolAddress((void**)&wt_bf, g_wtok_bf);
    cudaGetSymbolAddress((void**)&m_bf, g_mem_bf);
    cudaGetSymbolAddress((void**)&wq_bf, g_Wq_bf);
    cudaGetSymbolAddress((void**)&wk_bf, g_Wk_bf);
    cudaGetSymbolAddress((void**)&we_bf, g_We_bf);
    cudaGetSymbolAddress((void**)&wa_bf, g_Wa_bf);

    // launch 0: input conversions (wtok + memory)
    {
        int n0 = BB * WW * DD / 4;
        int n1 = BB * MM * DD / 4;
        f2bf_inputs_kernel<<<2048, 256>>>(
            (const float4*)wtok, (uint2*)wt_bf, n0,
            (const float4*)memory, (uint2*)m_bf, n1);
    }
    // launch 1: weight conversions
    f2bf4_kernel<<<4 * (DD * DD / 4) / 256, 256>>>(
        (const float4*)Wq, (const float4*)Wk, (const float4*)We, (const float4*)Wa,
        (uint2*)wq_bf, (uint2*)wk_bf, (uint2*)we_bf, (uint2*)wa_bf);

    // launch 2: fused q/e/a projections (a written NEGATED)
    fused_wtok_gemm_kernel<<<dim3(BB * WW / GBM, 12), 256>>>(
        wt_bf, wq_bf, we_bf, wa_bf, bq, be, ba, qb, e, a);

    // launch 3: k projection
    k_gemm_kernel<<<dim3(BB * MM / GBM, DD / GBN), 256>>>(m_bf, wk_bf, bk, kb);

    // launch 4: fused scores + softmax (tensor cores)
    scores_softmax_kernel<<<BB, 256>>>(qb, kb, s);

    // launch 5: scan + layernorm, f32x2 (24 live pairs, zero pack overhead)
    update_ln_kernel<<<dim3(4, BB), 256>>>(memory, s, e, a, gamma, beta, out);
}

// round 7
// speedup vs baseline: 1.2138x; 1.0170x over previous
#include <cuda_runtime.h>
#include <cuda_bf16.h>
#include <cstdint>

// Problem constants
#define BB 256   // batch
#define MM 96    // memory slots
#define WW 128   // write tokens
#define DD 512   // embed dim

// ---------------- scratch (static device globals: allocation-free) ----------
__device__ __nv_bfloat16 g_wtok_bf[BB * WW * DD];
__device__ __nv_bfloat16 g_mem_bf[BB * MM * DD];
__device__ __nv_bfloat16 g_Wq_bf[DD * DD];
__device__ __nv_bfloat16 g_Wk_bf[DD * DD];
__device__ __nv_bfloat16 g_We_bf[DD * DD];
__device__ __nv_bfloat16 g_Wa_bf[DD * DD];

__device__ __nv_bfloat16 g_qb[BB * WW * DD];   // q bf16 (scores input)
__device__ __nv_bfloat16 g_kb[BB * MM * DD];   // k bf16 (scores input)
__device__ float g_e[BB * WW * DD];
__device__ float g_a[BB * WW * DD];            // NEGATED tanh (scan convention)
__device__ float g_s[BB * WW * MM];

static __device__ __forceinline__ uint32_t smem_u32(const void* p) {
    uint32_t a;
    asm("{ .reg .u64 t; cvta.to.shared.u64 t, %1; cvt.u32.u64 %0, t; }" : "=r"(a) : "l"(p));
    return a;
}

static __device__ __forceinline__ unsigned long long pk2(float x, float y) {
    unsigned long long r;
    asm("mov.b64 %0, {%1, %2};" : "=l"(r) : "f"(x), "f"(y));
    return r;
}
static __device__ __forceinline__ void upk2(float& x, float& y, unsigned long long r) {
    asm("mov.b64 {%0, %1}, %2;" : "=f"(x), "=f"(y) : "l"(r));
}
static __device__ __forceinline__ unsigned long long fma2(
    unsigned long long a, unsigned long long b, unsigned long long c) {
    unsigned long long d;
    asm("fma.rn.f32x2 %0, %1, %2, %3;" : "=l"(d) : "l"(a), "l"(b), "l"(c));
    return d;
}

// ---------------------------------------------------------------------------
// fp32 -> bf16 conversions
// ---------------------------------------------------------------------------
__global__ __launch_bounds__(256) void f2bf_inputs_kernel(
    const float4* __restrict__ s0, uint2* __restrict__ d0, int n0,
    const float4* __restrict__ s1, uint2* __restrict__ d1, int n1)
{
    int i = blockIdx.x * 256 + threadIdx.x;
    int stride = gridDim.x * 256;
    int ntot = n0 + n1;
    for (; i < ntot; i += stride) {
        const float4* src = (i < n0) ? s0 : s1;
        uint2* dst = (i < n0) ? d0 : d1;
        int off = (i < n0) ? i : i - n0;
        float4 v = src[off];
        __nv_bfloat162 lo = __floats2bfloat162_rn(v.x, v.y);
        __nv_bfloat162 hi = __floats2bfloat162_rn(v.z, v.w);
        uint2 o;
        o.x = *(uint32_t*)&lo;
        o.y = *(uint32_t*)&hi;
        dst[off] = o;
    }
}

__global__ __launch_bounds__(256) void f2bf4_kernel(
    const float4* __restrict__ s0, const float4* __restrict__ s1,
    const float4* __restrict__ s2, const float4* __restrict__ s3,
    uint2* __restrict__ d0, uint2* __restrict__ d1,
    uint2* __restrict__ d2, uint2* __restrict__ d3)
{
    const int n4 = DD * DD / 4;  // 65536
    int i = blockIdx.x * 256 + threadIdx.x;
    int mat = i >> 16;
    int off = i & (n4 - 1);
    const float4* src = (mat == 0) ? s0 : (mat == 1) ? s1 : (mat == 2) ? s2 : s3;
    uint2* dst = (mat == 0) ? d0 : (mat == 1) ? d1 : (mat == 2) ? d2 : d3;
    float4 v = src[off];
    __nv_bfloat162 lo = __floats2bfloat162_rn(v.x, v.y);
    __nv_bfloat162 hi = __floats2bfloat162_rn(v.z, v.w);
    uint2 o;
    o.x = *(uint32_t*)&lo;
    o.y = *(uint32_t*)&hi;
    dst[off] = o;
}

// ---------------------------------------------------------------------------
// mma.sync GEMM core: C = act(A @ Bw^T + bias)
// Tile 128x128x32, 256 threads, warp tile 64x32, m16n8k16 bf16.
// 3-stage cp.async pipeline, ONE __syncthreads per K-step.
// act: 1=sigmoid fp32, 2=NEGATED tanh fp32, 3=none bf16 out
// ---------------------------------------------------------------------------
#define GBM 128
#define GBN 128
#define GBK 32
#define LDSK 40
#define NKT (DD / GBK)            // 16
#define GEMM_ASTG (GBM * LDSK)    // bf16 elems per A stage (5120)
#define GEMM_BSTG (GBN * LDSK)
#define GEMM_SMEM ((3 * GEMM_ASTG + 3 * GEMM_BSTG) * 2)   // 61440 B

static __device__ __forceinline__ void gemm_tile(
    const __nv_bfloat16* __restrict__ A,
    const __nv_bfloat16* __restrict__ Bw,
    const float* __restrict__ bias,
    void* __restrict__ Cv,
    long rowbase, int colbase, int act)
{
    extern __shared__ __align__(128) char dsm[];
    const uint32_t sA_base = smem_u32(dsm);
    const uint32_t sB_base = sA_base + 3 * GEMM_ASTG * 2;

    const int tid = threadIdx.x;
    const int wid = tid >> 5;
    const int lane = tid & 31;
    const int wm = wid & 1;
    const int wn = wid >> 1;

    float acc[4][4][4];
#pragma unroll
    for (int mi = 0; mi < 4; mi++)
#pragma unroll
        for (int ni = 0; ni < 4; ni++)
#pragma unroll
            for (int v = 0; v < 4; v++) acc[mi][ni][v] = 0.f;

    const int ar0 = tid >> 2, ac0 = (tid & 3) * 8;
    const int c1 = tid + 256;
    const int ar1 = c1 >> 2, ac1 = (c1 & 3) * 8;

#define STAGE(buf, kt) do {                                                        \
    const int kk_ = (kt) * GBK;                                                    \
    const __nv_bfloat16* ga0 = A  + (rowbase + ar0) * DD + kk_ + ac0;              \
    const __nv_bfloat16* ga1 = A  + (rowbase + ar1) * DD + kk_ + ac1;              \
    const __nv_bfloat16* gb0 = Bw + (long)(colbase + ar0) * DD + kk_ + ac0;        \
    const __nv_bfloat16* gb1 = Bw + (long)(colbase + ar1) * DD + kk_ + ac1;        \
    uint32_t s_;                                                                   \
    s_ = sA_base + (uint32_t)((((buf) * GEMM_ASTG) + ar0 * LDSK + ac0) * 2);       \
    asm volatile("cp.async.cg.shared.global [%0], [%1], 16;\n" :: "r"(s_), "l"(ga0)); \
    s_ = sA_base + (uint32_t)((((buf) * GEMM_ASTG) + ar1 * LDSK + ac1) * 2);       \
    asm volatile("cp.async.cg.shared.global [%0], [%1], 16;\n" :: "r"(s_), "l"(ga1)); \
    s_ = sB_base + (uint32_t)((((buf) * GEMM_BSTG) + ar0 * LDSK + ac0) * 2);       \
    asm volatile("cp.async.cg.shared.global [%0], [%1], 16;\n" :: "r"(s_), "l"(gb0)); \
    s_ = sB_base + (uint32_t)((((buf) * GEMM_BSTG) + ar1 * LDSK + ac1) * 2);       \
    asm volatile("cp.async.cg.shared.global [%0], [%1], 16;\n" :: "r"(s_), "l"(gb1)); \
    asm volatile("cp.async.commit_group;\n");                                      \
} while (0)

    STAGE(0, 0);
    STAGE(1, 1);

    for (int kt = 0; kt < NKT; kt++) {
        if (kt == NKT - 1) asm volatile("cp.async.wait_group 0;\n");
        else               asm volatile("cp.async.wait_group 1;\n");
        __syncthreads();
        if (kt + 2 < NKT) {
            const int nb = (kt + 2) % 3;
            STAGE(nb, kt + 2);
        }

        const int buf = kt % 3;
#pragma unroll
        for (int ks = 0; ks < 2; ks++) {
            const int k0 = ks * 16;

            uint32_t af[4][4];
#pragma unroll
            for (int mi = 0; mi < 4; mi++) {
                const int m0 = wm * 64 + mi * 16;
                uint32_t addr = sA_base + (uint32_t)((buf * GEMM_ASTG +
                    (m0 + (lane & 15)) * LDSK + k0 + ((lane >> 4) * 8)) * 2);
                asm volatile(
                    "ldmatrix.sync.aligned.m8n8.x4.shared.b16 {%0,%1,%2,%3}, [%4];\n"
                    : "=r"(af[mi][0]), "=r"(af[mi][1]), "=r"(af[mi][2]), "=r"(af[mi][3])
                    : "r"(addr));
            }

            uint32_t bfr[4][2];
#pragma unroll
            for (int nj = 0; nj < 2; nj++) {
                const int n0 = wn * 32 + nj * 16;
                uint32_t addr = sB_base + (uint32_t)((buf * GEMM_BSTG +
                    (n0 + (lane & 7) + ((lane >> 4) << 3)) * LDSK +
                    k0 + (((lane >> 3) & 1) * 8)) * 2);
                uint32_t r0, r1, r2, r3;
                asm volatile(
                    "ldmatrix.sync.aligned.m8n8.x4.shared.b16 {%0,%1,%2,%3}, [%4];\n"
                    : "=r"(r0), "=r"(r1), "=r"(r2), "=r"(r3) : "r"(addr));
                bfr[nj * 2][0] = r0;     bfr[nj * 2][1] = r1;
                bfr[nj * 2 + 1][0] = r2; bfr[nj * 2 + 1][1] = r3;
            }

#pragma unroll
            for (int mi = 0; mi < 4; mi++)
#pragma unroll
                for (int ni = 0; ni < 4; ni++)
                    asm volatile(
                        "mma.sync.aligned.m16n8k16.row.col.f32.bf16.bf16.f32 "
                        "{%0,%1,%2,%3}, {%4,%5,%6,%7}, {%8,%9}, {%0,%1,%2,%3};\n"
                        : "+f"(acc[mi][ni][0]), "+f"(acc[mi][ni][1]),
                          "+f"(acc[mi][ni][2]), "+f"(acc[mi][ni][3])
                        : "r"(af[mi][0]), "r"(af[mi][1]), "r"(af[mi][2]), "r"(af[mi][3]),
                          "r"(bfr[ni][0]), "r"(bfr[ni][1]));
        }
    }
#undef STAGE

    // epilogue: bias + activation
#pragma unroll
    for (int mi = 0; mi < 4; mi++) {
        const long r0 = rowbase + wm * 64 + mi * 16 + (lane >> 2);
#pragma unroll
        for (int ni = 0; ni < 4; ni++) {
            const int col = colbase + wn * 32 + ni * 8 + (lane & 3) * 2;
            const float b0 = bias[col], b1 = bias[col + 1];
            float v0 = acc[mi][ni][0] + b0;
            float v1 = acc[mi][ni][1] + b1;
            float v2 = acc[mi][ni][2] + b0;
            float v3 = acc[mi][ni][3] + b1;
            if (act == 1) {
                v0 = 1.f / (1.f + __expf(-v0)); v1 = 1.f / (1.f + __expf(-v1));
                v2 = 1.f / (1.f + __expf(-v2)); v3 = 1.f / (1.f + __expf(-v3));
            } else if (act == 2) {
                v0 = -tanhf(v0); v1 = -tanhf(v1);   // negated for scan FFMA2 form
                v2 = -tanhf(v2); v3 = -tanhf(v3);
            }
            if (act == 3) {
                __nv_bfloat16* Cb = (__nv_bfloat16*)Cv;
                *(__nv_bfloat162*)&Cb[r0 * DD + col] = __floats2bfloat162_rn(v0, v1);
                *(__nv_bfloat162*)&Cb[(r0 + 8) * DD + col] = __floats2bfloat162_rn(v2, v3);
            } else {
                float* C = (float*)Cv;
                *(float2*)&C[r0 * DD + col] = make_float2(v0, v1);
                *(float2*)&C[(r0 + 8) * DD + col] = make_float2(v2, v3);
            }
        }
    }
}

// All 4 projections in one launch. blockIdx.y 0..15:
// [0,4)=Wq->bf16 q; [4,8)=We->sigmoid e; [8,12)=Wa->-tanh a; [12,16)=Wk->bf16 k.
__global__ __launch_bounds__(256) void all_gemm_kernel(
    const __nv_bfloat16* __restrict__ Awt, const __nv_bfloat16* __restrict__ Am,
    const __nv_bfloat16* __restrict__ Wq, const __nv_bfloat16* __restrict__ We,
    const __nv_bfloat16* __restrict__ Wa, const __nv_bfloat16* __restrict__ Wk,
    const float* __restrict__ bq, const float* __restrict__ be,
    const float* __restrict__ ba, const float* __restrict__ bk,
    __nv_bfloat16* __restrict__ q_out, float* __restrict__ e_out,
    float* __restrict__ a_out, __nv_bfloat16* __restrict__ k_out)
{
    const int bn = blockIdx.y;
    const int mat = bn >> 2;
    const int colbase = (bn & 3) * GBN;
    const long rowbase = (long)blockIdx.x * GBM;
    if (mat == 3) {
        if (blockIdx.x >= BB * MM / GBM) return;   // k has 192 row tiles
        gemm_tile(Am, Wk, bk, k_out, rowbase, colbase, 3);
    } else if (mat == 0) {
        gemm_tile(Awt, Wq, bq, q_out, rowbase, colbase, 3);
    } else if (mat == 1) {
        gemm_tile(Awt, We, be, e_out, rowbase, colbase, 1);
    } else {
        gemm_tile(Awt, Wa, ba, a_out, rowbase, colbase, 2);
    }
}

// ---------------------------------------------------------------------------
// Fused scores + softmax (mma.sync), 3-stage pipeline, one barrier per K-step.
// One block per batch b. Dynamic smem layout:
//   sQ: 3 * WW*LDSK bf16 (30720B) | sK: 3 * MM*LDSK bf16 (23040B)
//   pmax: 2*WW f32 (1024B) | psum: 2*WW f32 (1024B)   total 55808B
// ---------------------------------------------------------------------------
#define SC_QSTG (WW * LDSK)
#define SC_KSTG (MM * LDSK)
#define SC_SMEM ((3 * SC_QSTG + 3 * SC_KSTG) * 2 + 2048)

__global__ __launch_bounds__(256) void scores_softmax_kernel(
    const __nv_bfloat16* __restrict__ Q, const __nv_bfloat16* __restrict__ K,
    float* __restrict__ S)
{
    extern __shared__ __align__(128) char dsm[];
    const uint32_t sQ_base = smem_u32(dsm);
    const uint32_t sK_base = sQ_base + 3 * SC_QSTG * 2;
    float* pmax = (float*)(dsm + (3 * SC_QSTG + 3 * SC_KSTG) * 2);
    float* psum = pmax + 2 * WW;

    const int b = blockIdx.x;
    const int tid = threadIdx.x;
    const int wid = tid >> 5;
    const int lane = tid & 31;
    const int wm = wid & 3;
    const int wn = wid >> 2;

    const __nv_bfloat16* Qb = Q + (size_t)b * WW * DD;
    const __nv_bfloat16* Kb = K + (size_t)b * MM * DD;

    float acc[2][6][4];
#pragma unroll
    for (int mi = 0; mi < 2; mi++)
#pragma unroll
        for (int ni = 0; ni < 6; ni++)
#pragma unroll
            for (int v = 0; v < 4; v++) acc[mi][ni][v] = 0.f;

    const int qr0 = tid >> 2, qc0 = (tid & 3) * 8;
    const int qc1i = tid + 256;
    const int qr1 = qc1i >> 2, qc1 = (qc1i & 3) * 8;
    const int kr0 = tid >> 2, kc0 = (tid & 3) * 8;
    const int kr1 = 64 + (tid >> 2), kc1 = (tid & 3) * 8;

#define SSTAGE(buf, kt) do {                                                       \
    const int kk_ = (kt) * GBK;                                                    \
    uint32_t s_;                                                                   \
    s_ = sQ_base + (uint32_t)((((buf) * SC_QSTG) + qr0 * LDSK + qc0) * 2);         \
    asm volatile("cp.async.cg.shared.global [%0], [%1], 16;\n"                     \
                 :: "r"(s_), "l"(Qb + (size_t)qr0 * DD + kk_ + qc0));              \
    s_ = sQ_base + (uint32_t)((((buf) * SC_QSTG) + qr1 * LDSK + qc1) * 2);         \
    asm volatile("cp.async.cg.shared.global [%0], [%1], 16;\n"                     \
                 :: "r"(s_), "l"(Qb + (size_t)qr1 * DD + kk_ + qc1));              \
    s_ = sK_base + (uint32_t)((((buf) * SC_KSTG) + kr0 * LDSK + kc0) * 2);         \
    asm volatile("cp.async.cg.shared.global [%0], [%1], 16;\n"                     \
                 :: "r"(s_), "l"(Kb + (size_t)kr0 * DD + kk_ + kc0));              \
    if (tid < 128) {                                                               \
        s_ = sK_base + (uint32_t)((((buf) * SC_KSTG) + kr1 * LDSK + kc1) * 2);     \
        asm volatile("cp.async.cg.shared.global [%0], [%1], 16;\n"                 \
                     :: "r"(s_), "l"(Kb + (size_t)kr1 * DD + kk_ + kc1));          \
    }                                                                              \
    asm volatile("cp.async.commit_group;\n");                                     \
} while (0)

    SSTAGE(0, 0);
    SSTAGE(1, 1);

    for (int kt = 0; kt < NKT; kt++) {
        if (kt == NKT - 1) asm volatile("cp.async.wait_group 0;\n");
        else               asm volatile("cp.async.wait_group 1;\n");
        __syncthreads();
        if (kt + 2 < NKT) {
            const int nb = (kt + 2) % 3;
            SSTAGE(nb, kt + 2);
        }

        const int buf = kt % 3;
#pragma unroll
        for (int ks = 0; ks < 2; ks++) {
            const int k0 = ks * 16;

            uint32_t af[2][4];
#pragma unroll
            for (int mi = 0; mi < 2; mi++) {
                const int m0 = wm * 32 + mi * 16;
                uint32_t addr = sQ_base + (uint32_t)((buf * SC_QSTG +
                    (m0 + (lane & 15)) * LDSK + k0 + ((lane >> 4) * 8)) * 2);
                asm volatile(
                    "ldmatrix.sync.aligned.m8n8.x4.shared.b16 {%0,%1,%2,%3}, [%4];\n"
                    : "=r"(af[mi][0]), "=r"(af[mi][1]), "=r"(af[mi][2]), "=r"(af[mi][3])
                    : "r"(addr));
            }

            uint32_t bfr[6][2];
#pragma unroll
            for (int nj = 0; nj < 3; nj++) {
                const int n0 = wn * 48 + nj * 16;
                uint32_t addr = sK_base + (uint32_t)((buf * SC_KSTG +
                    (n0 + (lane & 7) + ((lane >> 4) << 3)) * LDSK +
                    k0 + (((lane >> 3) & 1) * 8)) * 2);
                uint32_t r0, r1, r2, r3;
                asm volatile(
                    "ldmatrix.sync.aligned.m8n8.x4.shared.b16 {%0,%1,%2,%3}, [%4];\n"
                    : "=r"(r0), "=r"(r1), "=r"(r2), "=r"(r3) : "r"(addr));
                bfr[nj * 2][0] = r0;     bfr[nj * 2][1] = r1;
                bfr[nj * 2 + 1][0] = r2; bfr[nj * 2 + 1][1] = r3;
            }

#pragma unroll
            for (int mi = 0; mi < 2; mi++)
#pragma unroll
                for (int ni = 0; ni < 6; ni++)
                    asm volatile(
                        "mma.sync.aligned.m16n8k16.row.col.f32.bf16.bf16.f32 "
                        "{%0,%1,%2,%3}, {%4,%5,%6,%7}, {%8,%9}, {%0,%1,%2,%3};\n"
                        : "+f"(acc[mi][ni][0]), "+f"(acc[mi][ni][1]),
                          "+f"(acc[mi][ni][2]), "+f"(acc[mi][ni][3])
                        : "r"(af[mi][0]), "r"(af[mi][1]), "r"(af[mi][2]), "r"(af[mi][3]),
                          "r"(bfr[ni][0]), "r"(bfr[ni][1]));
        }
    }
#undef SSTAGE

    const float scale = 0.04419417382415922f;  // 1/sqrt(512)
#pragma unroll
    for (int mi = 0; mi < 2; mi++)
#pragma unroll
        for (int ni = 0; ni < 6; ni++)
#pragma unroll
            for (int v = 0; v < 4; v++) acc[mi][ni][v] *= scale;

    int rows[2][2];
#pragma unroll
    for (int mi = 0; mi < 2; mi++) {
        rows[mi][0] = wm * 32 + mi * 16 + (lane >> 2);
        rows[mi][1] = rows[mi][0] + 8;
    }

    __syncthreads();   // smem reuse: stages dead, pmax/psum region live

#pragma unroll
    for (int mi = 0; mi < 2; mi++) {
#pragma unroll
        for (int h = 0; h < 2; h++) {
            float mx = -1e30f;
#pragma unroll
            for (int ni = 0; ni < 6; ni++) {
                mx = fmaxf(mx, acc[mi][ni][h * 2 + 0]);
                mx = fmaxf(mx, acc[mi][ni][h * 2 + 1]);
            }
            mx = fmaxf(mx, __shfl_xor_sync(0xffffffffu, mx, 1));
            mx = fmaxf(mx, __shfl_xor_sync(0xffffffffu, mx, 2));
            pmax[wn * WW + rows[mi][h]] = mx;
        }
    }
    __syncthreads();

    float inv[2][2];
#pragma unroll
    for (int mi = 0; mi < 2; mi++) {
#pragma unroll
        for (int h = 0; h < 2; h++) {
            const float gmax = fmaxf(pmax[rows[mi][h]], pmax[WW + rows[mi][h]]);
            float sm = 0.f;
#pragma unroll
            for (int ni = 0; ni < 6; ni++) {
                float e0 = __expf(acc[mi][ni][h * 2 + 0] - gmax);
                float e1 = __expf(acc[mi][ni][h * 2 + 1] - gmax);
                acc[mi][ni][h * 2 + 0] = e0;
                acc[mi][ni][h * 2 + 1] = e1;
                sm += e0 + e1;
            }
            sm += __shfl_xor_sync(0xffffffffu, sm, 1);
            sm += __shfl_xor_sync(0xffffffffu, sm, 2);
            psum[wn * WW + rows[mi][h]] = sm;
        }
    }
    __syncthreads();

#pragma unroll
    for (int mi = 0; mi < 2; mi++)
#pragma unroll
        for (int h = 0; h < 2; h++)
            inv[mi][h] = 1.f / (psum[rows[mi][h]] + psum[WW + rows[mi][h]]);

#pragma unroll
    for (int mi = 0; mi < 2; mi++) {
#pragma unroll
        for (int h = 0; h < 2; h++) {
            float* rowp = S + ((size_t)(b * WW + rows[mi][h])) * MM;
#pragma unroll
            for (int ni = 0; ni < 6; ni++) {
                const int col = wn * 48 + ni * 8 + (lane & 3) * 2;
                *(float2*)(rowp + col) = make_float2(
                    acc[mi][ni][h * 2 + 0] * inv[mi][h],
                    acc[mi][ni][h * 2 + 1] * inv[mi][h]);
            }
        }
    }
}

// ---------------------------------------------------------------------------
// Sequential erase/add scan over W + fused LayerNorm (f32x2, 24 live pairs).
// ---------------------------------------------------------------------------
__global__ __launch_bounds__(256) void update_ln_kernel(
    const float* __restrict__ mem, const float* __restrict__ attn,
    const float* __restrict__ E, const float* __restrict__ Aneg,
    const float* __restrict__ gamma, const float* __restrict__ beta,
    float* __restrict__ out)
{
    const int b = blockIdx.y;
    const int m0 = blockIdx.x * 24;
    const int tid = threadIdx.x;
    const int dg = tid & 127;
    const int mg = tid >> 7;

    __shared__ unsigned long long a_s2[2][WW][12];
    __shared__ float red[2][4][12][2];

    unsigned long long s[12][2];
    const float4* memp = (const float4*)mem + ((size_t)(b * MM + m0 + mg * 12)) * 128 + dg;
#pragma unroll
    for (int j = 0; j < 12; j++) {
        float4 v = memp[j * 128];
        s[j][0] = pk2(v.x, v.y);
        s[j][1] = pk2(v.z, v.w);
    }
    for (int idx = tid; idx < WW * 24; idx += 256) {
        int w = idx / 24, mm = idx % 24;
        float c = attn[((size_t)(b * WW + w)) * MM + m0 + mm];
        a_s2[mm / 12][w][mm % 12] = pk2(-c, -c);
    }
    __syncthreads();

    const ulonglong2* Ep = (const ulonglong2*)E    + (size_t)b * WW * 128 + dg;
    const ulonglong2* Ap = (const ulonglong2*)Aneg + (size_t)b * WW * 128 + dg;

    for (int w = 0; w < WW; w++) {
        ulonglong2 eu = Ep[w * 128];
        ulonglong2 au = Ap[w * 128];
        const unsigned long long* crow = &a_s2[mg][w][0];
#pragma unroll
        for (int j = 0; j < 12; j++) {
            unsigned long long nc = crow[j];
            s[j][0] = fma2(nc, fma2(eu.x, s[j][0], au.x), s[j][0]);
            s[j][1] = fma2(nc, fma2(eu.y, s[j][1], au.y), s[j][1]);
        }
    }

    const int wg = (tid >> 5) & 3;
    const int lane = tid & 31;
#pragma unroll
    for (int j = 0; j < 12; j++) {
        float x0, x1, x2, x3;
        upk2(x0, x1, s[j][0]);
        upk2(x2, x3, s[j][1]);
        float sm = x0 + x1 + x2 + x3;
        float sq = fmaf(x0, x0, fmaf(x1, x1, fmaf(x2, x2, x3 * x3)));
#pragma unroll
        for (int o = 16; o > 0; o >>= 1) {
            sm += __shfl_xor_sync(0xffffffffu, sm, o);
            sq += __shfl_xor_sync(0xffffffffu, sq, o);
        }
        if (lane == 0) { red[mg][wg][j][0] = sm; red[mg][wg][j][1] = sq; }
    }
    __syncthreads();

    const float4 g4 = ((const float4*)gamma)[dg];
    const float4 bt4 = ((const float4*)beta)[dg];
    float4* outp = (float4*)out + ((size_t)(b * MM + m0 + mg * 12)) * 128 + dg;

#pragma unroll
    for (int j = 0; j < 12; j++) {
        float Ssum = red[mg][0][j][0] + red[mg][1][j][0] + red[mg][2][j][0] + red[mg][3][j][0];
        float Qsum = red[mg][0][j][1] + red[mg][1][j][1] + red[mg][2][j][1] + red[mg][3][j][1];
        float mu = Ssum * (1.f / 512.f);
        float var = Qsum * (1.f / 512.f) - mu * mu;
        float rs = rsqrtf(var + 1e-5f);
        float x0, x1, x2, x3;
        upk2(x0, x1, s[j][0]);
        upk2(x2, x3, s[j][1]);
        float4 o;
        o.x = fmaf((x0 - mu) * rs, g4.x, bt4.x);
        o.y = fmaf((x1 - mu) * rs, g4.y, bt4.y);
        o.z = fmaf((x2 - mu) * rs, g4.z, bt4.z);
        o.w = fmaf((x3 - mu) * rs, g4.w, bt4.w);
        outp[j * 128] = o;
    }
}

// ---------------------------------------------------------------------------
extern "C" void kernel_launch(void* const* d_in, const int* in_sizes, int n_in,
                              void* d_out, int out_size)
{
    const float* memory = (const float*)d_in[0];
    const float* wtok   = (const float*)d_in[1];
    const float* Wq = (const float*)d_in[2];  const float* bq = (const float*)d_in[3];
    const float* Wk = (const float*)d_in[4];  const float* bk = (const float*)d_in[5];
    const float* We = (const float*)d_in[6];  const float* be = (const float*)d_in[7];
    const float* Wa = (const float*)d_in[8];  const float* ba = (const float*)d_in[9];
    const float* gamma = (const float*)d_in[10];
    const float* beta  = (const float*)d_in[11];
    float* out = (float*)d_out;

    float *e, *a, *s;
    __nv_bfloat16 *qb, *kb, *wt_bf, *m_bf, *wq_bf, *wk_bf, *we_bf, *wa_bf;
    cudaGetSymbolAddress((void**)&e, g_e);
    cudaGetSymbolAddress((void**)&a, g_a);
    cudaGetSymbolAddress((void**)&s, g_s);
    cudaGetSymbolAddress((void**)&qb, g_qb);
    cudaGetSymbolAddress((void**)&kb, g_kb);
    cudaGetSymbolAddress((void**)&wt_bf, g_wtok_bf);
    cudaGetSymbolAddress((void**)&m_bf, g_mem_bf);
    cudaGetSymbolAddress((void**)&wq_bf, g_Wq_bf);
    cudaGetSymbolAddress((void**)&wk_bf, g_Wk_bf);
    cudaGetSymbolAddress((void**)&we_bf, g_We_bf);
    cudaGetSymbolAddress((void**)&wa_bf, g_Wa_bf);

    static int smem_set = 0;
    if (!smem_set) {
        cudaFuncSetAttribute(all_gemm_kernel,
                             cudaFuncAttributeMaxDynamicSharedMemorySize, GEMM_SMEM);
        cudaFuncSetAttribute(scores_softmax_kernel,
                             cudaFuncAttributeMaxDynamicSharedMemorySize, SC_SMEM);
        smem_set = 1;
    }

    // launch 0: input conversions (wtok + memory)
    {
        int n0 = BB * WW * DD / 4;
        int n1 = BB * MM * DD / 4;
        f2bf_inputs_kernel<<<2048, 256>>>(
            (const float4*)wtok, (uint2*)wt_bf, n0,
            (const float4*)memory, (uint2*)m_bf, n1);
    }
    // launch 1: weight conversions
    f2bf4_kernel<<<4 * (DD * DD / 4) / 256, 256>>>(
        (const float4*)Wq, (const float4*)Wk, (const float4*)We, (const float4*)Wa,
        (uint2*)wq_bf, (uint2*)wk_bf, (uint2*)we_bf, (uint2*)wa_bf);

    // launch 2: all four projections (a written NEGATED), 3-stage pipeline
    all_gemm_kernel<<<dim3(BB * WW / GBM, 16), 256, GEMM_SMEM>>>(
        wt_bf, m_bf, wq_bf, we_bf, wa_bf, wk_bf,
        bq, be, ba, bk, qb, e, a, kb);

    // launch 3: fused scores + softmax, 3-stage pipeline
    scores_softmax_kernel<<<BB, 256, SC_SMEM>>>(qb, kb, s);

    // launch 4: scan + layernorm (f32x2)
    update_ln_kernel<<<dim3(4, BB), 256>>>(memory, s, e, a, gamma, beta, out);
}

// round 8
// speedup vs baseline: 1.5498x; 1.2768x over previous
#include <cuda_runtime.h>
#include <cuda_bf16.h>
#include <cstdint>

// Problem constants
#define BB 256   // batch
#define MM 96    // memory slots
#define WW 128   // write tokens
#define DD 512   // embed dim

// ---------------- scratch (static device globals: allocation-free) ----------
__device__ __nv_bfloat16 g_wtok_bf[BB * WW * DD];
__device__ __nv_bfloat16 g_mem_bf[BB * MM * DD];
__device__ __nv_bfloat16 g_Wq_bf[DD * DD];
__device__ __nv_bfloat16 g_Wk_bf[DD * DD];
__device__ __nv_bfloat16 g_We_bf[DD * DD];
__device__ __nv_bfloat16 g_Wa_bf[DD * DD];

__device__ __nv_bfloat16 g_qb[BB * WW * DD];   // q bf16 (scores input)
__device__ __nv_bfloat16 g_kb[BB * MM * DD];   // k bf16 (scores input)
__device__ float g_e[BB * WW * DD];
__device__ float g_a[BB * WW * DD];            // NEGATED tanh (scan convention)
__device__ float g_s[BB * WW * MM];

static __device__ __forceinline__ uint32_t smem_u32(const void* p) {
    uint32_t a;
    asm("{ .reg .u64 t; cvta.to.shared.u64 t, %1; cvt.u32.u64 %0, t; }" : "=r"(a) : "l"(p));
    return a;
}

static __device__ __forceinline__ unsigned long long pk2(float x, float y) {
    unsigned long long r;
    asm("mov.b64 %0, {%1, %2};" : "=l"(r) : "f"(x), "f"(y));
    return r;
}
static __device__ __forceinline__ void upk2(float& x, float& y, unsigned long long r) {
    asm("mov.b64 {%0, %1}, %2;" : "=f"(x), "=f"(y) : "l"(r));
}
static __device__ __forceinline__ unsigned long long fma2(
    unsigned long long a, unsigned long long b, unsigned long long c) {
    unsigned long long d;
    asm("fma.rn.f32x2 %0, %1, %2, %3;" : "=l"(d) : "l"(a), "l"(b), "l"(c));
    return d;
}

// ---------------------------------------------------------------------------
// fp32 -> bf16 conversions
// ---------------------------------------------------------------------------
__global__ __launch_bounds__(256) void f2bf_inputs_kernel(
    const float4* __restrict__ s0, uint2* __restrict__ d0, int n0,
    const float4* __restrict__ s1, uint2* __restrict__ d1, int n1)
{
    int i = blockIdx.x * 256 + threadIdx.x;
    int stride = gridDim.x * 256;
    int ntot = n0 + n1;
    for (; i < ntot; i += stride) {
        const float4* src = (i < n0) ? s0 : s1;
        uint2* dst = (i < n0) ? d0 : d1;
        int off = (i < n0) ? i : i - n0;
        float4 v = src[off];
        __nv_bfloat162 lo = __floats2bfloat162_rn(v.x, v.y);
        __nv_bfloat162 hi = __floats2bfloat162_rn(v.z, v.w);
        uint2 o;
        o.x = *(uint32_t*)&lo;
        o.y = *(uint32_t*)&hi;
        dst[off] = o;
    }
}

__global__ __launch_bounds__(256) void f2bf4_kernel(
    const float4* __restrict__ s0, const float4* __restrict__ s1,
    const float4* __restrict__ s2, const float4* __restrict__ s3,
    uint2* __restrict__ d0, uint2* __restrict__ d1,
    uint2* __restrict__ d2, uint2* __restrict__ d3)
{
    const int n4 = DD * DD / 4;  // 65536
    int i = blockIdx.x * 256 + threadIdx.x;
    int mat = i >> 16;
    int off = i & (n4 - 1);
    const float4* src = (mat == 0) ? s0 : (mat == 1) ? s1 : (mat == 2) ? s2 : s3;
    uint2* dst = (mat == 0) ? d0 : (mat == 1) ? d1 : (mat == 2) ? d2 : d3;
    float4 v = src[off];
    __nv_bfloat162 lo = __floats2bfloat162_rn(v.x, v.y);
    __nv_bfloat162 hi = __floats2bfloat162_rn(v.z, v.w);
    uint2 o;
    o.x = *(uint32_t*)&lo;
    o.y = *(uint32_t*)&hi;
    dst[off] = o;
}

// ---------------------------------------------------------------------------
// mma.sync GEMM core: C = act(A @ Bw^T + bias)
// Tile 128x128x32, 256 threads, warp tile 64x32, m16n8k16 bf16.
// 3-stage cp.async pipeline, ONE __syncthreads per K-step.
// SINGLE instantiation (act is runtime) to keep code size inside L1.5-I.
// act: 1=sigmoid fp32, 2=NEGATED tanh fp32, 3=none bf16 out
// ---------------------------------------------------------------------------
#define GBM 128
#define GBN 128
#define GBK 32
#define LDSK 40
#define NKT (DD / GBK)            // 16
#define GEMM_ASTG (GBM * LDSK)    // bf16 elems per A stage (5120)
#define GEMM_BSTG (GBN * LDSK)
#define GEMM_SMEM ((3 * GEMM_ASTG + 3 * GEMM_BSTG) * 2)   // 61440 B

static __device__ __forceinline__ void gemm_tile(
    const __nv_bfloat16* __restrict__ A,
    const __nv_bfloat16* __restrict__ Bw,
    const float* __restrict__ bias,
    void* __restrict__ Cv,
    long rowbase, int colbase, int act)
{
    extern __shared__ __align__(128) char dsm[];
    const uint32_t sA_base = smem_u32(dsm);
    const uint32_t sB_base = sA_base + 3 * GEMM_ASTG * 2;

    const int tid = threadIdx.x;
    const int wid = tid >> 5;
    const int lane = tid & 31;
    const int wm = wid & 1;
    const int wn = wid >> 1;

    float acc[4][4][4];
#pragma unroll
    for (int mi = 0; mi < 4; mi++)
#pragma unroll
        for (int ni = 0; ni < 4; ni++)
#pragma unroll
            for (int v = 0; v < 4; v++) acc[mi][ni][v] = 0.f;

    const int ar0 = tid >> 2, ac0 = (tid & 3) * 8;
    const int c1 = tid + 256;
    const int ar1 = c1 >> 2, ac1 = (c1 & 3) * 8;

#define STAGE(buf, kt) do {                                                        \
    const int kk_ = (kt) * GBK;                                                    \
    const __nv_bfloat16* ga0 = A  + (rowbase + ar0) * DD + kk_ + ac0;              \
    const __nv_bfloat16* ga1 = A  + (rowbase + ar1) * DD + kk_ + ac1;              \
    const __nv_bfloat16* gb0 = Bw + (long)(colbase + ar0) * DD + kk_ + ac0;        \
    const __nv_bfloat16* gb1 = Bw + (long)(colbase + ar1) * DD + kk_ + ac1;        \
    uint32_t s_;                                                                   \
    s_ = sA_base + (uint32_t)((((buf) * GEMM_ASTG) + ar0 * LDSK + ac0) * 2);       \
    asm volatile("cp.async.cg.shared.global [%0], [%1], 16;\n" :: "r"(s_), "l"(ga0)); \
    s_ = sA_base + (uint32_t)((((buf) * GEMM_ASTG) + ar1 * LDSK + ac1) * 2);       \
    asm volatile("cp.async.cg.shared.global [%0], [%1], 16;\n" :: "r"(s_), "l"(ga1)); \
    s_ = sB_base + (uint32_t)((((buf) * GEMM_BSTG) + ar0 * LDSK + ac0) * 2);       \
    asm volatile("cp.async.cg.shared.global [%0], [%1], 16;\n" :: "r"(s_), "l"(gb0)); \
    s_ = sB_base + (uint32_t)((((buf) * GEMM_BSTG) + ar1 * LDSK + ac1) * 2);       \
    asm volatile("cp.async.cg.shared.global [%0], [%1], 16;\n" :: "r"(s_), "l"(gb1)); \
    asm volatile("cp.async.commit_group;\n");                                      \
} while (0)

    STAGE(0, 0);
    STAGE(1, 1);

    for (int kt = 0; kt < NKT; kt++) {
        if (kt == NKT - 1) asm volatile("cp.async.wait_group 0;\n");
        else               asm volatile("cp.async.wait_group 1;\n");
        __syncthreads();
        if (kt + 2 < NKT) {
            const int nb = (kt + 2) % 3;
            STAGE(nb, kt + 2);
        }

        const int buf = kt % 3;
#pragma unroll
        for (int ks = 0; ks < 2; ks++) {
            const int k0 = ks * 16;

            uint32_t af[4][4];
#pragma unroll
            for (int mi = 0; mi < 4; mi++) {
                const int m0 = wm * 64 + mi * 16;
                uint32_t addr = sA_base + (uint32_t)((buf * GEMM_ASTG +
                    (m0 + (lane & 15)) * LDSK + k0 + ((lane >> 4) * 8)) * 2);
                asm volatile(
                    "ldmatrix.sync.aligned.m8n8.x4.shared.b16 {%0,%1,%2,%3}, [%4];\n"
                    : "=r"(af[mi][0]), "=r"(af[mi][1]), "=r"(af[mi][2]), "=r"(af[mi][3])
                    : "r"(addr));
            }

            uint32_t bfr[4][2];
#pragma unroll
            for (int nj = 0; nj < 2; nj++) {
                const int n0 = wn * 32 + nj * 16;
                uint32_t addr = sB_base + (uint32_t)((buf * GEMM_BSTG +
                    (n0 + (lane & 7) + ((lane >> 4) << 3)) * LDSK +
                    k0 + (((lane >> 3) & 1) * 8)) * 2);
                uint32_t r0, r1, r2, r3;
                asm volatile(
                    "ldmatrix.sync.aligned.m8n8.x4.shared.b16 {%0,%1,%2,%3}, [%4];\n"
                    : "=r"(r0), "=r"(r1), "=r"(r2), "=r"(r3) : "r"(addr));
                bfr[nj * 2][0] = r0;     bfr[nj * 2][1] = r1;
                bfr[nj * 2 + 1][0] = r2; bfr[nj * 2 + 1][1] = r3;
            }

#pragma unroll
            for (int mi = 0; mi < 4; mi++)
#pragma unroll
                for (int ni = 0; ni < 4; ni++)
                    asm volatile(
                        "mma.sync.aligned.m16n8k16.row.col.f32.bf16.bf16.f32 "
                        "{%0,%1,%2,%3}, {%4,%5,%6,%7}, {%8,%9}, {%0,%1,%2,%3};\n"
                        : "+f"(acc[mi][ni][0]), "+f"(acc[mi][ni][1]),
                          "+f"(acc[mi][ni][2]), "+f"(acc[mi][ni][3])
                        : "r"(af[mi][0]), "r"(af[mi][1]), "r"(af[mi][2]), "r"(af[mi][3]),
                          "r"(bfr[ni][0]), "r"(bfr[ni][1]));
        }
    }
#undef STAGE

    // epilogue: bias + activation (runtime act: small code, branch-hoisted)
#pragma unroll
    for (int mi = 0; mi < 4; mi++) {
        const long r0 = rowbase + wm * 64 + mi * 16 + (lane >> 2);
#pragma unroll
        for (int ni = 0; ni < 4; ni++) {
            const int col = colbase + wn * 32 + ni * 8 + (lane & 3) * 2;
            const float b0 = bias[col], b1 = bias[col + 1];
            float v0 = acc[mi][ni][0] + b0;
            float v1 = acc[mi][ni][1] + b1;
            float v2 = acc[mi][ni][2] + b0;
            float v3 = acc[mi][ni][3] + b1;
            if (act == 1) {
                v0 = 1.f / (1.f + __expf(-v0)); v1 = 1.f / (1.f + __expf(-v1));
                v2 = 1.f / (1.f + __expf(-v2)); v3 = 1.f / (1.f + __expf(-v3));
            } else if (act == 2) {
                v0 = -tanhf(v0); v1 = -tanhf(v1);   // negated for scan FFMA2 form
                v2 = -tanhf(v2); v3 = -tanhf(v3);
            }
            if (act == 3) {
                __nv_bfloat16* Cb = (__nv_bfloat16*)Cv;
                *(__nv_bfloat162*)&Cb[r0 * DD + col] = __floats2bfloat162_rn(v0, v1);
                *(__nv_bfloat162*)&Cb[(r0 + 8) * DD + col] = __floats2bfloat162_rn(v2, v3);
            } else {
                float* C = (float*)Cv;
                *(float2*)&C[r0 * DD + col] = make_float2(v0, v1);
                *(float2*)&C[(r0 + 8) * DD + col] = make_float2(v2, v3);
            }
        }
    }
}

// All 4 projections in one launch, ONE gemm_tile call site. blockIdx.y 0..15:
// [0,4)=Wq->bf16 q; [4,8)=We->sigmoid e; [8,12)=Wa->-tanh a; [12,16)=Wk->bf16 k.
__global__ __launch_bounds__(256) void all_gemm_kernel(
    const __nv_bfloat16* __restrict__ Awt, const __nv_bfloat16* __restrict__ Am,
    const __nv_bfloat16* __restrict__ Wq, const __nv_bfloat16* __restrict__ We,
    const __nv_bfloat16* __restrict__ Wa, const __nv_bfloat16* __restrict__ Wk,
    const float* __restrict__ bq, const float* __restrict__ be,
    const float* __restrict__ ba, const float* __restrict__ bk,
    __nv_bfloat16* __restrict__ q_out, float* __restrict__ e_out,
    float* __restrict__ a_out, __nv_bfloat16* __restrict__ k_out)
{
    const int bn = blockIdx.y;
    const int mat = bn >> 2;
    const int colbase = (bn & 3) * GBN;
    const long rowbase = (long)blockIdx.x * GBM;

    const __nv_bfloat16* Asrc;
    const __nv_bfloat16* W;
    const float* bias;
    void* Cv;
    int act;
    if (mat == 0)      { Asrc = Awt; W = Wq; bias = bq; Cv = (void*)q_out; act = 3; }
    else if (mat == 1) { Asrc = Awt; W = We; bias = be; Cv = (void*)e_out; act = 1; }
    else if (mat == 2) { Asrc = Awt; W = Wa; bias = ba; Cv = (void*)a_out; act = 2; }
    else {
        if (blockIdx.x >= BB * MM / GBM) return;   // k has 192 row tiles
        Asrc = Am; W = Wk; bias = bk; Cv = (void*)k_out; act = 3;
    }
    gemm_tile(Asrc, W, bias, Cv, rowbase, colbase, act);
}

// ---------------------------------------------------------------------------
// Fused scores + softmax (mma.sync), 3-stage pipeline, one barrier per K-step.
// ---------------------------------------------------------------------------
#define SC_QSTG (WW * LDSK)
#define SC_KSTG (MM * LDSK)
#define SC_SMEM ((3 * SC_QSTG + 3 * SC_KSTG) * 2 + 2048)

__global__ __launch_bounds__(256) void scores_softmax_kernel(
    const __nv_bfloat16* __restrict__ Q, const __nv_bfloat16* __restrict__ K,
    float* __restrict__ S)
{
    extern __shared__ __align__(128) char dsm[];
    const uint32_t sQ_base = smem_u32(dsm);
    const uint32_t sK_base = sQ_base + 3 * SC_QSTG * 2;
    float* pmax = (float*)(dsm + (3 * SC_QSTG + 3 * SC_KSTG) * 2);
    float* psum = pmax + 2 * WW;

    const int b = blockIdx.x;
    const int tid = threadIdx.x;
    const int wid = tid >> 5;
    const int lane = tid & 31;
    const int wm = wid & 3;
    const int wn = wid >> 2;

    const __nv_bfloat16* Qb = Q + (size_t)b * WW * DD;
    const __nv_bfloat16* Kb = K + (size_t)b * MM * DD;

    float acc[2][6][4];
#pragma unroll
    for (int mi = 0; mi < 2; mi++)
#pragma unroll
        for (int ni = 0; ni < 6; ni++)
#pragma unroll
            for (int v = 0; v < 4; v++) acc[mi][ni][v] = 0.f;

    const int qr0 = tid >> 2, qc0 = (tid & 3) * 8;
    const int qc1i = tid + 256;
    const int qr1 = qc1i >> 2, qc1 = (qc1i & 3) * 8;
    const int kr0 = tid >> 2, kc0 = (tid & 3) * 8;
    const int kr1 = 64 + (tid >> 2), kc1 = (tid & 3) * 8;

#define SSTAGE(buf, kt) do {                                                       \
    const int kk_ = (kt) * GBK;                                                    \
    uint32_t s_;                                                                   \
    s_ = sQ_base + (uint32_t)((((buf) * SC_QSTG) + qr0 * LDSK + qc0) * 2);         \
    asm volatile("cp.async.cg.shared.global [%0], [%1], 16;\n"                     \
                 :: "r"(s_), "l"(Qb + (size_t)qr0 * DD + kk_ + qc0));              \
    s_ = sQ_base + (uint32_t)((((buf) * SC_QSTG) + qr1 * LDSK + qc1) * 2);         \
    asm volatile("cp.async.cg.shared.global [%0], [%1], 16;\n"                     \
                 :: "r"(s_), "l"(Qb + (size_t)qr1 * DD + kk_ + qc1));              \
    s_ = sK_base + (uint32_t)((((buf) * SC_KSTG) + kr0 * LDSK + kc0) * 2);         \
    asm volatile("cp.async.cg.shared.global [%0], [%1], 16;\n"                     \
                 :: "r"(s_), "l"(Kb + (size_t)kr0 * DD + kk_ + kc0));              \
    if (tid < 128) {                                                               \
        s_ = sK_base + (uint32_t)((((buf) * SC_KSTG) + kr1 * LDSK + kc1) * 2);     \
        asm volatile("cp.async.cg.shared.global [%0], [%1], 16;\n"                 \
                     :: "r"(s_), "l"(Kb + (size_t)kr1 * DD + kk_ + kc1));          \
    }                                                                              \
    asm volatile("cp.async.commit_group;\n");                                     \
} while (0)

    SSTAGE(0, 0);
    SSTAGE(1, 1);

    for (int kt = 0; kt < NKT; kt++) {
        if (kt == NKT - 1) asm volatile("cp.async.wait_group 0;\n");
        else               asm volatile("cp.async.wait_group 1;\n");
        __syncthreads();
        if (kt + 2 < NKT) {
            const int nb = (kt + 2) % 3;
            SSTAGE(nb, kt + 2);
        }

        const int buf = kt % 3;
#pragma unroll
        for (int ks = 0; ks < 2; ks++) {
            const int k0 = ks * 16;

            uint32_t af[2][4];
#pragma unroll
            for (int mi = 0; mi < 2; mi++) {
                const int m0 = wm * 32 + mi * 16;
                uint32_t addr = sQ_base + (uint32_t)((buf * SC_QSTG +
                    (m0 + (lane & 15)) * LDSK + k0 + ((lane >> 4) * 8)) * 2);
                asm volatile(
                    "ldmatrix.sync.aligned.m8n8.x4.shared.b16 {%0,%1,%2,%3}, [%4];\n"
                    : "=r"(af[mi][0]), "=r"(af[mi][1]), "=r"(af[mi][2]), "=r"(af[mi][3])
                    : "r"(addr));
            }

            uint32_t bfr[6][2];
#pragma unroll
            for (int nj = 0; nj < 3; nj++) {
                const int n0 = wn * 48 + nj * 16;
                uint32_t addr = sK_base + (uint32_t)((buf * SC_KSTG +
                    (n0 + (lane & 7) + ((lane >> 4) << 3)) * LDSK +
                    k0 + (((lane >> 3) & 1) * 8)) * 2);
                uint32_t r0, r1, r2, r3;
                asm volatile(
                    "ldmatrix.sync.aligned.m8n8.x4.shared.b16 {%0,%1,%2,%3}, [%4];\n"
                    : "=r"(r0), "=r"(r1), "=r"(r2), "=r"(r3) : "r"(addr));
                bfr[nj * 2][0] = r0;     bfr[nj * 2][1] = r1;
                bfr[nj * 2 + 1][0] = r2; bfr[nj * 2 + 1][1] = r3;
            }

#pragma unroll
            for (int mi = 0; mi < 2; mi++)
#pragma unroll
                for (int ni = 0; ni < 6; ni++)
                    asm volatile(
                        "mma.sync.aligned.m16n8k16.row.col.f32.bf16.bf16.f32 "
                        "{%0,%1,%2,%3}, {%4,%5,%6,%7}, {%8,%9}, {%0,%1,%2,%3};\n"
                        : "+f"(acc[mi][ni][0]), "+f"(acc[mi][ni][1]),
                          "+f"(acc[mi][ni][2]), "+f"(acc[mi][ni][3])
                        : "r"(af[mi][0]), "r"(af[mi][1]), "r"(af[mi][2]), "r"(af[mi][3]),
                          "r"(bfr[ni][0]), "r"(bfr[ni][1]));
        }
    }
#undef SSTAGE

    const float scale = 0.04419417382415922f;  // 1/sqrt(512)
#pragma unroll
    for (int mi = 0; mi < 2; mi++)
#pragma unroll
        for (int ni = 0; ni < 6; ni++)
#pragma unroll
            for (int v = 0; v < 4; v++) acc[mi][ni][v] *= scale;

    int rows[2][2];
#pragma unroll
    for (int mi = 0; mi < 2; mi++) {
        rows[mi][0] = wm * 32 + mi * 16 + (lane >> 2);
        rows[mi][1] = rows[mi][0] + 8;
    }

    __syncthreads();   // smem reuse: stages dead, pmax/psum region live

#pragma unroll
    for (int mi = 0; mi < 2; mi++) {
#pragma unroll
        for (int h = 0; h < 2; h++) {
            float mx = -1e30f;
#pragma unroll
            for (int ni = 0; ni < 6; ni++) {
                mx = fmaxf(mx, acc[mi][ni][h * 2 + 0]);
                mx = fmaxf(mx, acc[mi][ni][h * 2 + 1]);
            }
            mx = fmaxf(mx, __shfl_xor_sync(0xffffffffu, mx, 1));
            mx = fmaxf(mx, __shfl_xor_sync(0xffffffffu, mx, 2));
            pmax[wn * WW + rows[mi][h]] = mx;
        }
    }
    __syncthreads();

    float inv[2][2];
#pragma unroll
    for (int mi = 0; mi < 2; mi++) {
#pragma unroll
        for (int h = 0; h < 2; h++) {
            const float gmax = fmaxf(pmax[rows[mi][h]], pmax[WW + rows[mi][h]]);
            float sm = 0.f;
#pragma unroll
            for (int ni = 0; ni < 6; ni++) {
                float e0 = __expf(acc[mi][ni][h * 2 + 0] - gmax);
                float e1 = __expf(acc[mi][ni][h * 2 + 1] - gmax);
                acc[mi][ni][h * 2 + 0] = e0;
                acc[mi][ni][h * 2 + 1] = e1;
                sm += e0 + e1;
            }
            sm += __shfl_xor_sync(0xffffffffu, sm, 1);
            sm += __shfl_xor_sync(0xffffffffu, sm, 2);
            psum[wn * WW + rows[mi][h]] = sm;
        }
    }
    __syncthreads();

#pragma unroll
    for (int mi = 0; mi < 2; mi++)
#pragma unroll
        for (int h = 0; h < 2; h++)
            inv[mi][h] = 1.f / (psum[rows[mi][h]] + psum[WW + rows[mi][h]]);

#pragma unroll
    for (int mi = 0; mi < 2; mi++) {
#pragma unroll
        for (int h = 0; h < 2; h++) {
            float* rowp = S + ((size_t)(b * WW + rows[mi][h])) * MM;
#pragma unroll
            for (int ni = 0; ni < 6; ni++) {
                const int col = wn * 48 + ni * 8 + (lane & 3) * 2;
                *(float2*)(rowp + col) = make_float2(
                    acc[mi][ni][h * 2 + 0] * inv[mi][h],
                    acc[mi][ni][h * 2 + 1] * inv[mi][h]);
            }
        }
    }
}

// ---------------------------------------------------------------------------
// Scan + fused LayerNorm. 512 threads: 128 d-lanes x 4 m-groups of 12 rows
// (m-chunk 48, grid 2 x BB) -> E/A read by only 2 CTAs per batch (was 4).
// State 24 f32x2 pairs/thread (proven reg-safe). attn pre-negated/duplicated
// ULL in dynamic smem (49KB).
// ---------------------------------------------------------------------------
#define UL_ASZ (4 * WW * 12 * 8)                 // 49152
#define UL_SMEM (UL_ASZ + 4 * 4 * 12 * 2 * 4)    // + red 1536 = 50688

__global__ __launch_bounds__(512) void update_ln_kernel(
    const float* __restrict__ mem, const float* __restrict__ attn,
    const float* __restrict__ E, const float* __restrict__ Aneg,
    const float* __restrict__ gamma, const float* __restrict__ beta,
    float* __restrict__ out)
{
    extern __shared__ __align__(16) char dsmu[];
    unsigned long long* a_s2 = (unsigned long long*)dsmu;         // [mg][w][j]
    float (*red)[4][12][2] = (float(*)[4][12][2])(dsmu + UL_ASZ); // [mg][wg][j][2]

    const int b = blockIdx.y;
    const int m0 = blockIdx.x * 48;
    const int tid = threadIdx.x;
    const int dg = tid & 127;    // d-lane: owns floats dg*4 .. dg*4+3
    const int mg = tid >> 7;     // 0..3: rows m0 + mg*12 + j

    unsigned long long s[12][2];
    const float4* memp = (const float4*)mem + ((size_t)(b * MM + m0 + mg * 12)) * 128 + dg;
#pragma unroll
    for (int j = 0; j < 12; j++) {
        float4 v = memp[j * 128];
        s[j][0] = pk2(v.x, v.y);
        s[j][1] = pk2(v.z, v.w);
    }
    for (int idx = tid; idx < WW * 48; idx += 512) {
        int w = idx / 48, mm = idx % 48;
        float c = attn[((size_t)(b * WW + w)) * MM + m0 + mm];
        a_s2[(mm / 12) * (WW * 12) + w * 12 + (mm % 12)] = pk2(-c, -c);
    }
    __syncthreads();

    const ulonglong2* Ep = (const ulonglong2*)E    + (size_t)b * WW * 128 + dg;
    const ulonglong2* Ap = (const ulonglong2*)Aneg + (size_t)b * WW * 128 + dg;
    const unsigned long long* abase = a_s2 + mg * (WW * 12);

    for (int w = 0; w < WW; w++) {
        ulonglong2 eu = Ep[w * 128];
        ulonglong2 au = Ap[w * 128];   // already negated add-vector
        const unsigned long long* crow = abase + w * 12;
#pragma unroll
        for (int j = 0; j < 12; j++) {
            unsigned long long nc = crow[j];
            s[j][0] = fma2(nc, fma2(eu.x, s[j][0], au.x), s[j][0]);
            s[j][1] = fma2(nc, fma2(eu.y, s[j][1], au.y), s[j][1]);
        }
    }

    // per-row LayerNorm: reduce over 128 d-lanes (4 warps per m-group)
    const int wg = (tid >> 5) & 3;
    const int lane = tid & 31;
#pragma unroll
    for (int j = 0; j < 12; j++) {
        float x0, x1, x2, x3;
        upk2(x0, x1, s[j][0]);
        upk2(x2, x3, s[j][1]);
        float sm = x0 + x1 + x2 + x3;
        float sq = fmaf(x0, x0, fmaf(x1, x1, fmaf(x2, x2, x3 * x3)));
#pragma unroll
        for (int o = 16; o > 0; o >>= 1) {
            sm += __shfl_xor_sync(0xffffffffu, sm, o);
            sq += __shfl_xor_sync(0xffffffffu, sq, o);
        }
        if (lane == 0) { red[mg][wg][j][0] = sm; red[mg][wg][j][1] = sq; }
    }
    __syncthreads();

    const float4 g4 = ((const float4*)gamma)[dg];
    const float4 bt4 = ((const float4*)beta)[dg];
    float4* outp = (float4*)out + ((size_t)(b * MM + m0 + mg * 12)) * 128 + dg;

#pragma unroll
    for (int j = 0; j < 12; j++) {
        float Ssum = red[mg][0][j][0] + red[mg][1][j][0] + red[mg][2][j][0] + red[mg][3][j][0];
        float Qsum = red[mg][0][j][1] + red[mg][1][j][1] + red[mg][2][j][1] + red[mg][3][j][1];
        float mu = Ssum * (1.f / 512.f);
        float var = Qsum * (1.f / 512.f) - mu * mu;
        float rs = rsqrtf(var + 1e-5f);
        float x0, x1, x2, x3;
        upk2(x0, x1, s[j][0]);
        upk2(x2, x3, s[j][1]);
        float4 o;
        o.x = fmaf((x0 - mu) * rs, g4.x, bt4.x);
        o.y = fmaf((x1 - mu) * rs, g4.y, bt4.y);
        o.z = fmaf((x2 - mu) * rs, g4.z, bt4.z);
        o.w = fmaf((x3 - mu) * rs, g4.w, bt4.w);
        outp[j * 128] = o;
    }
}

// ---------------------------------------------------------------------------
extern "C" void kernel_launch(void* const* d_in, const int* in_sizes, int n_in,
                              void* d_out, int out_size)
{
    const float* memory = (const float*)d_in[0];
    const float* wtok   = (const float*)d_in[1];
    const float* Wq = (const float*)d_in[2];  const float* bq = (const float*)d_in[3];
    const float* Wk = (const float*)d_in[4];  const float* bk = (const float*)d_in[5];
    const float* We = (const float*)d_in[6];  const float* be = (const float*)d_in[7];
    const float* Wa = (const float*)d_in[8];  const float* ba = (const float*)d_in[9];
    const float* gamma = (const float*)d_in[10];
    const float* beta  = (const float*)d_in[11];
    float* out = (float*)d_out;

    float *e, *a, *s;
    __nv_bfloat16 *qb, *kb, *wt_bf, *m_bf, *wq_bf, *wk_bf, *we_bf, *wa_bf;
    cudaGetSymbolAddress((void**)&e, g_e);
    cudaGetSymbolAddress((void**)&a, g_a);
    cudaGetSymbolAddress((void**)&s, g_s);
    cudaGetSymbolAddress((void**)&qb, g_qb);
    cudaGetSymbolAddress((void**)&kb, g_kb);
    cudaGetSymbolAddress((void**)&wt_bf, g_wtok_bf);
    cudaGetSymbolAddress((void**)&m_bf, g_mem_bf);
    cudaGetSymbolAddress((void**)&wq_bf, g_Wq_bf);
    cudaGetSymbolAddress((void**)&wk_bf, g_Wk_bf);
    cudaGetSymbolAddress((void**)&we_bf, g_We_bf);
    cudaGetSymbolAddress((void**)&wa_bf, g_Wa_bf);

    static int smem_set = 0;
    if (!smem_set) {
        cudaFuncSetAttribute(all_gemm_kernel,
                             cudaFuncAttributeMaxDynamicSharedMemorySize, GEMM_SMEM);
        cudaFuncSetAttribute(scores_softmax_kernel,
                             cudaFuncAttributeMaxDynamicSharedMemorySize, SC_SMEM);
        cudaFuncSetAttribute(update_ln_kernel,
                             cudaFuncAttributeMaxDynamicSharedMemorySize, UL_SMEM);
        smem_set = 1;
    }

    // launch 0: input conversions (wtok + memory)
    {
        int n0 = BB * WW * DD / 4;
        int n1 = BB * MM * DD / 4;
        f2bf_inputs_kernel<<<2048, 256>>>(
            (const float4*)wtok, (uint2*)wt_bf, n0,
            (const float4*)memory, (uint2*)m_bf, n1);
    }
    // launch 1: weight conversions
    f2bf4_kernel<<<4 * (DD * DD / 4) / 256, 256>>>(
        (const float4*)Wq, (const float4*)Wk, (const float4*)We, (const float4*)Wa,
        (uint2*)wq_bf, (uint2*)wk_bf, (uint2*)we_bf, (uint2*)wa_bf);

    // launch 2: all four projections (single gemm_tile instantiation)
    all_gemm_kernel<<<dim3(BB * WW / GBM, 16), 256, GEMM_SMEM>>>(
        wt_bf, m_bf, wq_bf, we_bf, wa_bf, wk_bf,
        bq, be, ba, bk, qb, e, a, kb);

    // launch 3: fused scores + softmax, 3-stage pipeline
    scores_softmax_kernel<<<BB, 256, SC_SMEM>>>(qb, kb, s);

    // launch 4: scan + layernorm (f32x2, halved E/A traffic)
    update_ln_kernel<<<dim3(2, BB), 512, UL_SMEM>>>(memory, s, e, a, gamma, beta, out);
}

// round 9
// speedup vs baseline: 1.5544x; 1.0030x over previous
#include <cuda_runtime.h>
#include <cuda_bf16.h>
#include <cstdint>

// Problem constants
#define BB 256   // batch
#define MM 96    // memory slots
#define WW 128   // write tokens
#define DD 512   // embed dim

// ---------------- scratch (static device globals: allocation-free) ----------
__device__ __nv_bfloat16 g_wtok_bf[BB * WW * DD];
__device__ __nv_bfloat16 g_mem_bf[BB * MM * DD];
__device__ __nv_bfloat16 g_Wq_bf[DD * DD];
__device__ __nv_bfloat16 g_Wk_bf[DD * DD];
__device__ __nv_bfloat16 g_We_bf[DD * DD];
__device__ __nv_bfloat16 g_Wa_bf[DD * DD];

__device__ __nv_bfloat16 g_qb[BB * WW * DD];   // q bf16 (scores input)
__device__ __nv_bfloat16 g_kb[BB * MM * DD];   // k bf16 (scores input)
__device__ float g_e[BB * WW * DD];
__device__ float g_a[BB * WW * DD];            // NEGATED tanh (scan convention)
__device__ float g_s[BB * WW * MM];

static __device__ __forceinline__ uint32_t smem_u32(const void* p) {
    uint32_t a;
    asm("{ .reg .u64 t; cvta.to.shared.u64 t, %1; cvt.u32.u64 %0, t; }" : "=r"(a) : "l"(p));
    return a;
}

static __device__ __forceinline__ unsigned long long pk2(float x, float y) {
    unsigned long long r;
    asm("mov.b64 %0, {%1, %2};" : "=l"(r) : "f"(x), "f"(y));
    return r;
}
static __device__ __forceinline__ void upk2(float& x, float& y, unsigned long long r) {
    asm("mov.b64 {%0, %1}, %2;" : "=f"(x), "=f"(y) : "l"(r));
}
static __device__ __forceinline__ unsigned long long fma2(
    unsigned long long a, unsigned long long b, unsigned long long c) {
    unsigned long long d;
    asm("fma.rn.f32x2 %0, %1, %2, %3;" : "=l"(d) : "l"(a), "l"(b), "l"(c));
    return d;
}

// ---------------------------------------------------------------------------
// fp32 -> bf16: ALL conversions (wtok + memory + 4 weights) in one launch
// ---------------------------------------------------------------------------
#define N4_WT (BB * WW * DD / 4)   // 4194304
#define N4_MEM (BB * MM * DD / 4)  // 3145728
#define N4_W (DD * DD / 4)         // 65536

__global__ __launch_bounds__(256) void f2bf_all_kernel(
    const float4* __restrict__ wt, uint2* __restrict__ wtd,
    const float4* __restrict__ mem, uint2* __restrict__ memd,
    const float4* __restrict__ w0, const float4* __restrict__ w1,
    const float4* __restrict__ w2, const float4* __restrict__ w3,
    uint2* __restrict__ wd0, uint2* __restrict__ wd1,
    uint2* __restrict__ wd2, uint2* __restrict__ wd3)
{
    const int ntot = N4_WT + N4_MEM + 4 * N4_W;
    int i = blockIdx.x * 256 + threadIdx.x;
    const int stride = gridDim.x * 256;
    for (; i < ntot; i += stride) {
        const float4* src;
        uint2* dst;
        int off;
        if (i < N4_WT) { src = wt; dst = wtd; off = i; }
        else if (i < N4_WT + N4_MEM) { src = mem; dst = memd; off = i - N4_WT; }
        else {
            int j = i - N4_WT - N4_MEM;
            int mat = j >> 16;
            off = j & (N4_W - 1);
            src = (mat == 0) ? w0 : (mat == 1) ? w1 : (mat == 2) ? w2 : w3;
            dst = (mat == 0) ? wd0 : (mat == 1) ? wd1 : (mat == 2) ? wd2 : wd3;
        }
        float4 v = src[off];
        __nv_bfloat162 lo = __floats2bfloat162_rn(v.x, v.y);
        __nv_bfloat162 hi = __floats2bfloat162_rn(v.z, v.w);
        uint2 o;
        o.x = *(uint32_t*)&lo;
        o.y = *(uint32_t*)&hi;
        dst[off] = o;
    }
}

// ---------------------------------------------------------------------------
// mma.sync GEMM core: C = act(A @ Bw^T + bias)
// Tile 128x128x32, 256 threads, warp tile 64x32, m16n8k16 bf16.
// 3-stage cp.async pipeline, ONE __syncthreads per K-step.
// All 12 LDSM (both k16 sub-steps) hoisted before the 32 HMMA burst.
// act: 1=sigmoid fp32, 2=NEGATED tanh fp32, 3=none bf16 out
// ---------------------------------------------------------------------------
#define GBM 128
#define GBN 128
#define GBK 32
#define LDSK 40
#define NKT (DD / GBK)            // 16
#define GEMM_ASTG (GBM * LDSK)    // bf16 elems per A stage (5120)
#define GEMM_BSTG (GBN * LDSK)
#define GEMM_SMEM ((3 * GEMM_ASTG + 3 * GEMM_BSTG) * 2)   // 61440 B

static __device__ __forceinline__ void gemm_tile(
    const __nv_bfloat16* __restrict__ A,
    const __nv_bfloat16* __restrict__ Bw,
    const float* __restrict__ bias,
    void* __restrict__ Cv,
    long rowbase, int colbase, int act)
{
    extern __shared__ __align__(128) char dsm[];
    const uint32_t sA_base = smem_u32(dsm);
    const uint32_t sB_base = sA_base + 3 * GEMM_ASTG * 2;

    const int tid = threadIdx.x;
    const int wid = tid >> 5;
    const int lane = tid & 31;
    const int wm = wid & 1;
    const int wn = wid >> 1;

    float acc[4][4][4];
#pragma unroll
    for (int mi = 0; mi < 4; mi++)
#pragma unroll
        for (int ni = 0; ni < 4; ni++)
#pragma unroll
            for (int v = 0; v < 4; v++) acc[mi][ni][v] = 0.f;

    const int ar0 = tid >> 2, ac0 = (tid & 3) * 8;
    const int c1 = tid + 256;
    const int ar1 = c1 >> 2, ac1 = (c1 & 3) * 8;

#define STAGE(buf, kt) do {                                                        \
    const int kk_ = (kt) * GBK;                                                    \
    const __nv_bfloat16* ga0 = A  + (rowbase + ar0) * DD + kk_ + ac0;              \
    const __nv_bfloat16* ga1 = A  + (rowbase + ar1) * DD + kk_ + ac1;              \
    const __nv_bfloat16* gb0 = Bw + (long)(colbase + ar0) * DD + kk_ + ac0;        \
    const __nv_bfloat16* gb1 = Bw + (long)(colbase + ar1) * DD + kk_ + ac1;        \
    uint32_t s_;                                                                   \
    s_ = sA_base + (uint32_t)((((buf) * GEMM_ASTG) + ar0 * LDSK + ac0) * 2);       \
    asm volatile("cp.async.cg.shared.global [%0], [%1], 16;\n" :: "r"(s_), "l"(ga0)); \
    s_ = sA_base + (uint32_t)((((buf) * GEMM_ASTG) + ar1 * LDSK + ac1) * 2);       \
    asm volatile("cp.async.cg.shared.global [%0], [%1], 16;\n" :: "r"(s_), "l"(ga1)); \
    s_ = sB_base + (uint32_t)((((buf) * GEMM_BSTG) + ar0 * LDSK + ac0) * 2);       \
    asm volatile("cp.async.cg.shared.global [%0], [%1], 16;\n" :: "r"(s_), "l"(gb0)); \
    s_ = sB_base + (uint32_t)((((buf) * GEMM_BSTG) + ar1 * LDSK + ac1) * 2);       \
    asm volatile("cp.async.cg.shared.global [%0], [%1], 16;\n" :: "r"(s_), "l"(gb1)); \
    asm volatile("cp.async.commit_group;\n");                                      \
} while (0)

    STAGE(0, 0);
    STAGE(1, 1);

    for (int kt = 0; kt < NKT; kt++) {
        if (kt == NKT - 1) asm volatile("cp.async.wait_group 0;\n");
        else               asm volatile("cp.async.wait_group 1;\n");
        __syncthreads();
        if (kt + 2 < NKT) {
            const int nb = (kt + 2) % 3;
            STAGE(nb, kt + 2);
        }

        const int buf = kt % 3;

        // ---- hoisted fragment loads: both k16 sub-steps (12 LDSM) ----
        uint32_t af[2][4][4];
        uint32_t bfr[2][4][2];
#pragma unroll
        for (int ks = 0; ks < 2; ks++) {
            const int k0 = ks * 16;
#pragma unroll
            for (int mi = 0; mi < 4; mi++) {
                const int m0 = wm * 64 + mi * 16;
                uint32_t addr = sA_base + (uint32_t)((buf * GEMM_ASTG +
                    (m0 + (lane & 15)) * LDSK + k0 + ((lane >> 4) * 8)) * 2);
                asm volatile(
                    "ldmatrix.sync.aligned.m8n8.x4.shared.b16 {%0,%1,%2,%3}, [%4];\n"
                    : "=r"(af[ks][mi][0]), "=r"(af[ks][mi][1]),
                      "=r"(af[ks][mi][2]), "=r"(af[ks][mi][3])
                    : "r"(addr));
            }
#pragma unroll
            for (int nj = 0; nj < 2; nj++) {
                const int n0 = wn * 32 + nj * 16;
                uint32_t addr = sB_base + (uint32_t)((buf * GEMM_BSTG +
                    (n0 + (lane & 7) + ((lane >> 4) << 3)) * LDSK +
                    k0 + (((lane >> 3) & 1) * 8)) * 2);
                uint32_t r0, r1, r2, r3;
                asm volatile(
                    "ldmatrix.sync.aligned.m8n8.x4.shared.b16 {%0,%1,%2,%3}, [%4];\n"
                    : "=r"(r0), "=r"(r1), "=r"(r2), "=r"(r3) : "r"(addr));
                bfr[ks][nj * 2][0] = r0;     bfr[ks][nj * 2][1] = r1;
                bfr[ks][nj * 2 + 1][0] = r2; bfr[ks][nj * 2 + 1][1] = r3;
            }
        }

        // ---- dense HMMA burst (32) ----
#pragma unroll
        for (int ks = 0; ks < 2; ks++)
#pragma unroll
            for (int mi = 0; mi < 4; mi++)
#pragma unroll
                for (int ni = 0; ni < 4; ni++)
                    asm volatile(
                        "mma.sync.aligned.m16n8k16.row.col.f32.bf16.bf16.f32 "
                        "{%0,%1,%2,%3}, {%4,%5,%6,%7}, {%8,%9}, {%0,%1,%2,%3};\n"
                        : "+f"(acc[mi][ni][0]), "+f"(acc[mi][ni][1]),
                          "+f"(acc[mi][ni][2]), "+f"(acc[mi][ni][3])
                        : "r"(af[ks][mi][0]), "r"(af[ks][mi][1]),
                          "r"(af[ks][mi][2]), "r"(af[ks][mi][3]),
                          "r"(bfr[ks][ni][0]), "r"(bfr[ks][ni][1]));
    }
#undef STAGE

    // epilogue: bias + activation (runtime act)
#pragma unroll
    for (int mi = 0; mi < 4; mi++) {
        const long r0 = rowbase + wm * 64 + mi * 16 + (lane >> 2);
#pragma unroll
        for (int ni = 0; ni < 4; ni++) {
            const int col = colbase + wn * 32 + ni * 8 + (lane & 3) * 2;
            const float b0 = bias[col], b1 = bias[col + 1];
            float v0 = acc[mi][ni][0] + b0;
            float v1 = acc[mi][ni][1] + b1;
            float v2 = acc[mi][ni][2] + b0;
            float v3 = acc[mi][ni][3] + b1;
            if (act == 1) {
                v0 = 1.f / (1.f + __expf(-v0)); v1 = 1.f / (1.f + __expf(-v1));
                v2 = 1.f / (1.f + __expf(-v2)); v3 = 1.f / (1.f + __expf(-v3));
            } else if (act == 2) {
                v0 = -tanhf(v0); v1 = -tanhf(v1);   // negated for scan FFMA2 form
                v2 = -tanhf(v2); v3 = -tanhf(v3);
            }
            if (act == 3) {
                __nv_bfloat16* Cb = (__nv_bfloat16*)Cv;
                *(__nv_bfloat162*)&Cb[r0 * DD + col] = __floats2bfloat162_rn(v0, v1);
                *(__nv_bfloat162*)&Cb[(r0 + 8) * DD + col] = __floats2bfloat162_rn(v2, v3);
            } else {
                float* C = (float*)Cv;
                *(float2*)&C[r0 * DD + col] = make_float2(v0, v1);
                *(float2*)&C[(r0 + 8) * DD + col] = make_float2(v2, v3);
            }
        }
    }
}

// All 4 projections, ONE gemm_tile call site. Grid: x = (mat,col) 0..15
// (consecutive CTAs share a rowtile -> A stays hot in L2), y = rowtile.
// [0,4)=Wq->bf16 q; [4,8)=We->sigmoid e; [8,12)=Wa->-tanh a; [12,16)=Wk->bf16 k.
__global__ __launch_bounds__(256) void all_gemm_kernel(
    const __nv_bfloat16* __restrict__ Awt, const __nv_bfloat16* __restrict__ Am,
    const __nv_bfloat16* __restrict__ Wq, const __nv_bfloat16* __restrict__ We,
    const __nv_bfloat16* __restrict__ Wa, const __nv_bfloat16* __restrict__ Wk,
    const float* __restrict__ bq, const float* __restrict__ be,
    const float* __restrict__ ba, const float* __restrict__ bk,
    __nv_bfloat16* __restrict__ q_out, float* __restrict__ e_out,
    float* __restrict__ a_out, __nv_bfloat16* __restrict__ k_out)
{
    const int bn = blockIdx.x;
    const int mat = bn >> 2;
    const int colbase = (bn & 3) * GBN;
    const long rowbase = (long)blockIdx.y * GBM;

    const __nv_bfloat16* Asrc;
    const __nv_bfloat16* W;
    const float* bias;
    void* Cv;
    int act;
    if (mat == 0)      { Asrc = Awt; W = Wq; bias = bq; Cv = (void*)q_out; act = 3; }
    else if (mat == 1) { Asrc = Awt; W = We; bias = be; Cv = (void*)e_out; act = 1; }
    else if (mat == 2) { Asrc = Awt; W = Wa; bias = ba; Cv = (void*)a_out; act = 2; }
    else {
        if (blockIdx.y >= BB * MM / GBM) return;   // k has 192 row tiles
        Asrc = Am; W = Wk; bias = bk; Cv = (void*)k_out; act = 3;
    }
    gemm_tile(Asrc, W, bias, Cv, rowbase, colbase, act);
}

// ---------------------------------------------------------------------------
// Fused scores + softmax (mma.sync), 3-stage pipeline, one barrier per K-step.
// ---------------------------------------------------------------------------
#define SC_QSTG (WW * LDSK)
#define SC_KSTG (MM * LDSK)
#define SC_SMEM ((3 * SC_QSTG + 3 * SC_KSTG) * 2 + 2048)

__global__ __launch_bounds__(256) void scores_softmax_kernel(
    const __nv_bfloat16* __restrict__ Q, const __nv_bfloat16* __restrict__ K,
    float* __restrict__ S)
{
    extern __shared__ __align__(128) char dsm[];
    const uint32_t sQ_base = smem_u32(dsm);
    const uint32_t sK_base = sQ_base + 3 * SC_QSTG * 2;
    float* pmax = (float*)(dsm + (3 * SC_QSTG + 3 * SC_KSTG) * 2);
    float* psum = pmax + 2 * WW;

    const int b = blockIdx.x;
    const int tid = threadIdx.x;
    const int wid = tid >> 5;
    const int lane = tid & 31;
    const int wm = wid & 3;
    const int wn = wid >> 2;

    const __nv_bfloat16* Qb = Q + (size_t)b * WW * DD;
    const __nv_bfloat16* Kb = K + (size_t)b * MM * DD;

    float acc[2][6][4];
#pragma unroll
    for (int mi = 0; mi < 2; mi++)
#pragma unroll
        for (int ni = 0; ni < 6; ni++)
#pragma unroll
            for (int v = 0; v < 4; v++) acc[mi][ni][v] = 0.f;

    const int qr0 = tid >> 2, qc0 = (tid & 3) * 8;
    const int qc1i = tid + 256;
    const int qr1 = qc1i >> 2, qc1 = (qc1i & 3) * 8;
    const int kr0 = tid >> 2, kc0 = (tid & 3) * 8;
    const int kr1 = 64 + (tid >> 2), kc1 = (tid & 3) * 8;

#define SSTAGE(buf, kt) do {                                                       \
    const int kk_ = (kt) * GBK;                                                    \
    uint32_t s_;                                                                   \
    s_ = sQ_base + (uint32_t)((((buf) * SC_QSTG) + qr0 * LDSK + qc0) * 2);         \
    asm volatile("cp.async.cg.shared.global [%0], [%1], 16;\n"                     \
                 :: "r"(s_), "l"(Qb + (size_t)qr0 * DD + kk_ + qc0));              \
    s_ = sQ_base + (uint32_t)((((buf) * SC_QSTG) + qr1 * LDSK + qc1) * 2);         \
    asm volatile("cp.async.cg.shared.global [%0], [%1], 16;\n"                     \
                 :: "r"(s_), "l"(Qb + (size_t)qr1 * DD + kk_ + qc1));              \
    s_ = sK_base + (uint32_t)((((buf) * SC_KSTG) + kr0 * LDSK + kc0) * 2);         \
    asm volatile("cp.async.cg.shared.global [%0], [%1], 16;\n"                     \
                 :: "r"(s_), "l"(Kb + (size_t)kr0 * DD + kk_ + kc0));              \
    if (tid < 128) {                                                               \
        s_ = sK_base + (uint32_t)((((buf) * SC_KSTG) + kr1 * LDSK + kc1) * 2);     \
        asm volatile("cp.async.cg.shared.global [%0], [%1], 16;\n"                 \
                     :: "r"(s_), "l"(Kb + (size_t)kr1 * DD + kk_ + kc1));          \
    }                                                                              \
    asm volatile("cp.async.commit_group;\n");                                     \
} while (0)

    SSTAGE(0, 0);
    SSTAGE(1, 1);

    for (int kt = 0; kt < NKT; kt++) {
        if (kt == NKT - 1) asm volatile("cp.async.wait_group 0;\n");
        else               asm volatile("cp.async.wait_group 1;\n");
        __syncthreads();
        if (kt + 2 < NKT) {
            const int nb = (kt + 2) % 3;
            SSTAGE(nb, kt + 2);
        }

        const int buf = kt % 3;
#pragma unroll
        for (int ks = 0; ks < 2; ks++) {
            const int k0 = ks * 16;

            uint32_t af[2][4];
#pragma unroll
            for (int mi = 0; mi < 2; mi++) {
                const int m0 = wm * 32 + mi * 16;
                uint32_t addr = sQ_base + (uint32_t)((buf * SC_QSTG +
                    (m0 + (lane & 15)) * LDSK + k0 + ((lane >> 4) * 8)) * 2);
                asm volatile(
                    "ldmatrix.sync.aligned.m8n8.x4.shared.b16 {%0,%1,%2,%3}, [%4];\n"
                    : "=r"(af[mi][0]), "=r"(af[mi][1]), "=r"(af[mi][2]), "=r"(af[mi][3])
                    : "r"(addr));
            }

            uint32_t bfr[6][2];
#pragma unroll
            for (int nj = 0; nj < 3; nj++) {
                const int n0 = wn * 48 + nj * 16;
                uint32_t addr = sK_base + (uint32_t)((buf * SC_KSTG +
                    (n0 + (lane & 7) + ((lane >> 4) << 3)) * LDSK +
                    k0 + (((lane >> 3) & 1) * 8)) * 2);
                uint32_t r0, r1, r2, r3;
                asm volatile(
                    "ldmatrix.sync.aligned.m8n8.x4.shared.b16 {%0,%1,%2,%3}, [%4];\n"
                    : "=r"(r0), "=r"(r1), "=r"(r2), "=r"(r3) : "r"(addr));
                bfr[nj * 2][0] = r0;     bfr[nj * 2][1] = r1;
                bfr[nj * 2 + 1][0] = r2; bfr[nj * 2 + 1][1] = r3;
            }

#pragma unroll
            for (int mi = 0; mi < 2; mi++)
#pragma unroll
                for (int ni = 0; ni < 6; ni++)
                    asm volatile(
                        "mma.sync.aligned.m16n8k16.row.col.f32.bf16.bf16.f32 "
                        "{%0,%1,%2,%3}, {%4,%5,%6,%7}, {%8,%9}, {%0,%1,%2,%3};\n"
                        : "+f"(acc[mi][ni][0]), "+f"(acc[mi][ni][1]),
                          "+f"(acc[mi][ni][2]), "+f"(acc[mi][ni][3])
                        : "r"(af[mi][0]), "r"(af[mi][1]), "r"(af[mi][2]), "r"(af[mi][3]),
                          "r"(bfr[ni][0]), "r"(bfr[ni][1]));
        }
    }
#undef SSTAGE

    const float scale = 0.04419417382415922f;  // 1/sqrt(512)
#pragma unroll
    for (int mi = 0; mi < 2; mi++)
#pragma unroll
        for (int ni = 0; ni < 6; ni++)
#pragma unroll
            for (int v = 0; v < 4; v++) acc[mi][ni][v] *= scale;

    int rows[2][2];
#pragma unroll
    for (int mi = 0; mi < 2; mi++) {
        rows[mi][0] = wm * 32 + mi * 16 + (lane >> 2);
        rows[mi][1] = rows[mi][0] + 8;
    }

    __syncthreads();   // smem reuse: stages dead, pmax/psum region live

#pragma unroll
    for (int mi = 0; mi < 2; mi++) {
#pragma unroll
        for (int h = 0; h < 2; h++) {
            float mx = -1e30f;
#pragma unroll
            for (int ni = 0; ni < 6; ni++) {
                mx = fmaxf(mx, acc[mi][ni][h * 2 + 0]);
                mx = fmaxf(mx, acc[mi][ni][h * 2 + 1]);
            }
            mx = fmaxf(mx, __shfl_xor_sync(0xffffffffu, mx, 1));
            mx = fmaxf(mx, __shfl_xor_sync(0xffffffffu, mx, 2));
            pmax[wn * WW + rows[mi][h]] = mx;
        }
    }
    __syncthreads();

    float inv[2][2];
#pragma unroll
    for (int mi = 0; mi < 2; mi++) {
#pragma unroll
        for (int h = 0; h < 2; h++) {
            const float gmax = fmaxf(pmax[rows[mi][h]], pmax[WW + rows[mi][h]]);
            float sm = 0.f;
#pragma unroll
            for (int ni = 0; ni < 6; ni++) {
                float e0 = __expf(acc[mi][ni][h * 2 + 0] - gmax);
                float e1 = __expf(acc[mi][ni][h * 2 + 1] - gmax);
                acc[mi][ni][h * 2 + 0] = e0;
                acc[mi][ni][h * 2 + 1] = e1;
                sm += e0 + e1;
            }
            sm += __shfl_xor_sync(0xffffffffu, sm, 1);
            sm += __shfl_xor_sync(0xffffffffu, sm, 2);
            psum[wn * WW + rows[mi][h]] = sm;
        }
    }
    __syncthreads();

#pragma unroll
    for (int mi = 0; mi < 2; mi++)
#pragma unroll
        for (int h = 0; h < 2; h++)
            inv[mi][h] = 1.f / (psum[rows[mi][h]] + psum[WW + rows[mi][h]]);

#pragma unroll
    for (int mi = 0; mi < 2; mi++) {
#pragma unroll
        for (int h = 0; h < 2; h++) {
            float* rowp = S + ((size_t)(b * WW + rows[mi][h])) * MM;
#pragma unroll
            for (int ni = 0; ni < 6; ni++) {
                const int col = wn * 48 + ni * 8 + (lane & 3) * 2;
                *(float2*)(rowp + col) = make_float2(
                    acc[mi][ni][h * 2 + 0] * inv[mi][h],
                    acc[mi][ni][h * 2 + 1] * inv[mi][h]);
            }
        }
    }
}

// ---------------------------------------------------------------------------
// Scan + fused LayerNorm. 512 threads: 128 d-lanes x 4 m-groups of 12 rows
// (m-chunk 48, grid 2 x BB). State 24 f32x2 pairs/thread.
// ---------------------------------------------------------------------------
#define UL_ASZ (4 * WW * 12 * 8)                 // 49152
#define UL_SMEM (UL_ASZ + 4 * 4 * 12 * 2 * 4)    // + red 1536 = 50688

__global__ __launch_bounds__(512) void update_ln_kernel(
    const float* __restrict__ mem, const float* __restrict__ attn,
    const float* __restrict__ E, const float* __restrict__ Aneg,
    const float* __restrict__ gamma, const float* __restrict__ beta,
    float* __restrict__ out)
{
    extern __shared__ __align__(16) char dsmu[];
    unsigned long long* a_s2 = (unsigned long long*)dsmu;         // [mg][w][j]
    float (*red)[4][12][2] = (float(*)[4][12][2])(dsmu + UL_ASZ); // [mg][wg][j][2]

    const int b = blockIdx.y;
    const int m0 = blockIdx.x * 48;
    const int tid = threadIdx.x;
    const int dg = tid & 127;    // d-lane: owns floats dg*4 .. dg*4+3
    const int mg = tid >> 7;     // 0..3: rows m0 + mg*12 + j

    unsigned long long s[12][2];
    const float4* memp = (const float4*)mem + ((size_t)(b * MM + m0 + mg * 12)) * 128 + dg;
#pragma unroll
    for (int j = 0; j < 12; j++) {
        float4 v = memp[j * 128];
        s[j][0] = pk2(v.x, v.y);
        s[j][1] = pk2(v.z, v.w);
    }
    for (int idx = tid; idx < WW * 48; idx += 512) {
        int w = idx / 48, mm = idx % 48;
        float c = attn[((size_t)(b * WW + w)) * MM + m0 + mm];
        a_s2[(mm / 12) * (WW * 12) + w * 12 + (mm % 12)] = pk2(-c, -c);
    }
    __syncthreads();

    const ulonglong2* Ep = (const ulonglong2*)E    + (size_t)b * WW * 128 + dg;
    const ulonglong2* Ap = (const ulonglong2*)Aneg + (size_t)b * WW * 128 + dg;
    const unsigned long long* abase = a_s2 + mg * (WW * 12);

    for (int w = 0; w < WW; w++) {
        ulonglong2 eu = Ep[w * 128];
        ulonglong2 au = Ap[w * 128];   // already negated add-vector
        const unsigned long long* crow = abase + w * 12;
#pragma unroll
        for (int j = 0; j < 12; j++) {
            unsigned long long nc = crow[j];
            s[j][0] = fma2(nc, fma2(eu.x, s[j][0], au.x), s[j][0]);
            s[j][1] = fma2(nc, fma2(eu.y, s[j][1], au.y), s[j][1]);
        }
    }

    // per-row LayerNorm: reduce over 128 d-lanes (4 warps per m-group)
    const int wg = (tid >> 5) & 3;
    const int lane = tid & 31;
#pragma unroll
    for (int j = 0; j < 12; j++) {
        float x0, x1, x2, x3;
        upk2(x0, x1, s[j][0]);
        upk2(x2, x3, s[j][1]);
        float sm = x0 + x1 + x2 + x3;
        float sq = fmaf(x0, x0, fmaf(x1, x1, fmaf(x2, x2, x3 * x3)));
#pragma unroll
        for (int o = 16; o > 0; o >>= 1) {
            sm += __shfl_xor_sync(0xffffffffu, sm, o);
            sq += __shfl_xor_sync(0xffffffffu, sq, o);
        }
        if (lane == 0) { red[mg][wg][j][0] = sm; red[mg][wg][j][1] = sq; }
    }
    __syncthreads();

    const float4 g4 = ((const float4*)gamma)[dg];
    const float4 bt4 = ((const float4*)beta)[dg];
    float4* outp = (float4*)out + ((size_t)(b * MM + m0 + mg * 12)) * 128 + dg;

#pragma unroll
    for (int j = 0; j < 12; j++) {
        float Ssum = red[mg][0][j][0] + red[mg][1][j][0] + red[mg][2][j][0] + red[mg][3][j][0];
        float Qsum = red[mg][0][j][1] + red[mg][1][j][1] + red[mg][2][j][1] + red[mg][3][j][1];
        float mu = Ssum * (1.f / 512.f);
        float var = Qsum * (1.f / 512.f) - mu * mu;
        float rs = rsqrtf(var + 1e-5f);
        float x0, x1, x2, x3;
        upk2(x0, x1, s[j][0]);
        upk2(x2, x3, s[j][1]);
        float4 o;
        o.x = fmaf((x0 - mu) * rs, g4.x, bt4.x);
        o.y = fmaf((x1 - mu) * rs, g4.y, bt4.y);
        o.z = fmaf((x2 - mu) * rs, g4.z, bt4.z);
        o.w = fmaf((x3 - mu) * rs, g4.w, bt4.w);
        outp[j * 128] = o;
    }
}

// ---------------------------------------------------------------------------
extern "C" void kernel_launch(void* const* d_in, const int* in_sizes, int n_in,
                              void* d_out, int out_size)
{
    const float* memory = (const float*)d_in[0];
    const float* wtok   = (const float*)d_in[1];
    const float* Wq = (const float*)d_in[2];  const float* bq = (const float*)d_in[3];
    const float* Wk = (const float*)d_in[4];  const float* bk = (const float*)d_in[5];
    const float* We = (const float*)d_in[6];  const float* be = (const float*)d_in[7];
    const float* Wa = (const float*)d_in[8];  const float* ba = (const float*)d_in[9];
    const float* gamma = (const float*)d_in[10];
    const float* beta  = (const float*)d_in[11];
    float* out = (float*)d_out;

    float *e, *a, *s;
    __nv_bfloat16 *qb, *kb, *wt_bf, *m_bf, *wq_bf, *wk_bf, *we_bf, *wa_bf;
    cudaGetSymbolAddress((void**)&e, g_e);
    cudaGetSymbolAddress((void**)&a, g_a);
    cudaGetSymbolAddress((void**)&s, g_s);
    cudaGetSymbolAddress((void**)&qb, g_qb);
    cudaGetSymbolAddress((void**)&kb, g_kb);
    cudaGetSymbolAddress((void**)&wt_bf, g_wtok_bf);
    cudaGetSymbolAddress((void**)&m_bf, g_mem_bf);
    cudaGetSymbolAddress((void**)&wq_bf, g_Wq_bf);
    cudaGetSymbolAddress((void**)&wk_bf, g_Wk_bf);
    cudaGetSymbolAddress((void**)&we_bf, g_We_bf);
    cudaGetSymbolAddress((void**)&wa_bf, g_Wa_bf);

    static int smem_set = 0;
    if (!smem_set) {
        cudaFuncSetAttribute(all_gemm_kernel,
                             cudaFuncAttributeMaxDynamicSharedMemorySize, GEMM_SMEM);
        cudaFuncSetAttribute(scores_softmax_kernel,
                             cudaFuncAttributeMaxDynamicSharedMemorySize, SC_SMEM);
        cudaFuncSetAttribute(update_ln_kernel,
                             cudaFuncAttributeMaxDynamicSharedMemorySize, UL_SMEM);
        smem_set = 1;
    }

    // launch 0: ALL fp32->bf16 conversions
    f2bf_all_kernel<<<2048, 256>>>(
        (const float4*)wtok, (uint2*)wt_bf,
        (const float4*)memory, (uint2*)m_bf,
        (const float4*)Wq, (const float4*)Wk, (const float4*)We, (const float4*)Wa,
        (uint2*)wq_bf, (uint2*)wk_bf, (uint2*)we_bf, (uint2*)wa_bf);

    // launch 1: all four projections (grid transposed for A L2 reuse)
    all_gemm_kernel<<<dim3(16, BB * WW / GBM), 256, GEMM_SMEM>>>(
        wt_bf, m_bf, wq_bf, we_bf, wa_bf, wk_bf,
        bq, be, ba, bk, qb, e, a, kb);

    // launch 2: fused scores + softmax
    scores_softmax_kernel<<<BB, 256, SC_SMEM>>>(qb, kb, s);

    // launch 3: scan + layernorm (f32x2)
    update_ln_kernel<<<dim3(2, BB), 512, UL_SMEM>>>(memory, s, e, a, gamma, beta, out);
}

// round 10
// speedup vs baseline: 1.5592x; 1.0031x over previous
#include <cuda_runtime.h>
#include <cuda_bf16.h>
#include <cstdint>

// Problem constants
#define BB 256   // batch
#define MM 96    // memory slots
#define WW 128   // write tokens
#define DD 512   // embed dim

// ---------------- scratch (static device globals: allocation-free) ----------
__device__ __nv_bfloat16 g_wtok_bf[BB * WW * DD];
__device__ __nv_bfloat16 g_mem_bf[BB * MM * DD];
__device__ __nv_bfloat16 g_Wq_bf[DD * DD];
__device__ __nv_bfloat16 g_Wk_bf[DD * DD];
__device__ __nv_bfloat16 g_We_bf[DD * DD];
__device__ __nv_bfloat16 g_Wa_bf[DD * DD];

__device__ __nv_bfloat16 g_qb[BB * WW * DD];   // q bf16 (scores input)
__device__ __nv_bfloat16 g_kb[BB * MM * DD];   // k bf16 (scores input)
__device__ float g_e[BB * WW * DD];
__device__ float g_a[BB * WW * DD];            // NEGATED tanh (scan convention)
__device__ float g_s[BB * WW * MM];

static __device__ __forceinline__ uint32_t smem_u32(const void* p) {
    uint32_t a;
    asm("{ .reg .u64 t; cvta.to.shared.u64 t, %1; cvt.u32.u64 %0, t; }" : "=r"(a) : "l"(p));
    return a;
}

static __device__ __forceinline__ unsigned long long pk2(float x, float y) {
    unsigned long long r;
    asm("mov.b64 %0, {%1, %2};" : "=l"(r) : "f"(x), "f"(y));
    return r;
}
static __device__ __forceinline__ void upk2(float& x, float& y, unsigned long long r) {
    asm("mov.b64 {%0, %1}, %2;" : "=f"(x), "=f"(y) : "l"(r));
}
static __device__ __forceinline__ unsigned long long fma2(
    unsigned long long a, unsigned long long b, unsigned long long c) {
    unsigned long long d;
    asm("fma.rn.f32x2 %0, %1, %2, %3;" : "=l"(d) : "l"(a), "l"(b), "l"(c));
    return d;
}

// ---------------------------------------------------------------------------
// fp32 -> bf16: ALL conversions (wtok + memory + 4 weights) in one launch
// ---------------------------------------------------------------------------
#define N4_WT (BB * WW * DD / 4)   // 4194304
#define N4_MEM (BB * MM * DD / 4)  // 3145728
#define N4_W (DD * DD / 4)         // 65536

__global__ __launch_bounds__(256) void f2bf_all_kernel(
    const float4* __restrict__ wt, uint2* __restrict__ wtd,
    const float4* __restrict__ mem, uint2* __restrict__ memd,
    const float4* __restrict__ w0, const float4* __restrict__ w1,
    const float4* __restrict__ w2, const float4* __restrict__ w3,
    uint2* __restrict__ wd0, uint2* __restrict__ wd1,
    uint2* __restrict__ wd2, uint2* __restrict__ wd3)
{
    const int ntot = N4_WT + N4_MEM + 4 * N4_W;
    int i = blockIdx.x * 256 + threadIdx.x;
    const int stride = gridDim.x * 256;
    for (; i < ntot; i += stride) {
        const float4* src;
        uint2* dst;
        int off;
        if (i < N4_WT) { src = wt; dst = wtd; off = i; }
        else if (i < N4_WT + N4_MEM) { src = mem; dst = memd; off = i - N4_WT; }
        else {
            int j = i - N4_WT - N4_MEM;
            int mat = j >> 16;
            off = j & (N4_W - 1);
            src = (mat == 0) ? w0 : (mat == 1) ? w1 : (mat == 2) ? w2 : w3;
            dst = (mat == 0) ? wd0 : (mat == 1) ? wd1 : (mat == 2) ? wd2 : wd3;
        }
        float4 v = src[off];
        __nv_bfloat162 lo = __floats2bfloat162_rn(v.x, v.y);
        __nv_bfloat162 hi = __floats2bfloat162_rn(v.z, v.w);
        uint2 o;
        o.x = *(uint32_t*)&lo;
        o.y = *(uint32_t*)&hi;
        dst[off] = o;
    }
}

// ---------------------------------------------------------------------------
// mma.sync GEMM core: C = act(A @ Bw^T + bias)
// Tile 128x128x32, 256 threads, warp tile 64x32, m16n8k16 bf16.
// 3-stage cp.async pipeline, ONE __syncthreads per K-step.
// act: 1=sigmoid fp32, 2=NEGATED tanh fp32, 3=none bf16 out
// ---------------------------------------------------------------------------
#define GBM 128
#define GBN 128
#define GBK 32
#define LDSK 40
#define NKT (DD / GBK)            // 16
#define GEMM_ASTG (GBM * LDSK)    // bf16 elems per A stage (5120)
#define GEMM_BSTG (GBN * LDSK)
#define GEMM_SMEM ((3 * GEMM_ASTG + 3 * GEMM_BSTG) * 2)   // 61440 B

static __device__ __forceinline__ void gemm_tile(
    const __nv_bfloat16* __restrict__ A,
    const __nv_bfloat16* __restrict__ Bw,
    const float* __restrict__ bias,
    void* __restrict__ Cv,
    long rowbase, int colbase, int act)
{
    extern __shared__ __align__(128) char dsm[];
    const uint32_t sA_base = smem_u32(dsm);
    const uint32_t sB_base = sA_base + 3 * GEMM_ASTG * 2;

    const int tid = threadIdx.x;
    const int wid = tid >> 5;
    const int lane = tid & 31;
    const int wm = wid & 1;
    const int wn = wid >> 1;

    float acc[4][4][4];
#pragma unroll
    for (int mi = 0; mi < 4; mi++)
#pragma unroll
        for (int ni = 0; ni < 4; ni++)
#pragma unroll
            for (int v = 0; v < 4; v++) acc[mi][ni][v] = 0.f;

    const int ar0 = tid >> 2, ac0 = (tid & 3) * 8;
    const int c1 = tid + 256;
    const int ar1 = c1 >> 2, ac1 = (c1 & 3) * 8;

#define STAGE(buf, kt) do {                                                        \
    const int kk_ = (kt) * GBK;                                                    \
    const __nv_bfloat16* ga0 = A  + (rowbase + ar0) * DD + kk_ + ac0;              \
    const __nv_bfloat16* ga1 = A  + (rowbase + ar1) * DD + kk_ + ac1;              \
    const __nv_bfloat16* gb0 = Bw + (long)(colbase + ar0) * DD + kk_ + ac0;        \
    const __nv_bfloat16* gb1 = Bw + (long)(colbase + ar1) * DD + kk_ + ac1;        \
    uint32_t s_;                                                                   \
    s_ = sA_base + (uint32_t)((((buf) * GEMM_ASTG) + ar0 * LDSK + ac0) * 2);       \
    asm volatile("cp.async.cg.shared.global [%0], [%1], 16;\n" :: "r"(s_), "l"(ga0)); \
    s_ = sA_base + (uint32_t)((((buf) * GEMM_ASTG) + ar1 * LDSK + ac1) * 2);       \
    asm volatile("cp.async.cg.shared.global [%0], [%1], 16;\n" :: "r"(s_), "l"(ga1)); \
    s_ = sB_base + (uint32_t)((((buf) * GEMM_BSTG) + ar0 * LDSK + ac0) * 2);       \
    asm volatile("cp.async.cg.shared.global [%0], [%1], 16;\n" :: "r"(s_), "l"(gb0)); \
    s_ = sB_base + (uint32_t)((((buf) * GEMM_BSTG) + ar1 * LDSK + ac1) * 2);       \
    asm volatile("cp.async.cg.shared.global [%0], [%1], 16;\n" :: "r"(s_), "l"(gb1)); \
    asm volatile("cp.async.commit_group;\n");                                      \
} while (0)

    STAGE(0, 0);
    STAGE(1, 1);

    for (int kt = 0; kt < NKT; kt++) {
        if (kt == NKT - 1) asm volatile("cp.async.wait_group 0;\n");
        else               asm volatile("cp.async.wait_group 1;\n");
        __syncthreads();
        if (kt + 2 < NKT) {
            const int nb = (kt + 2) % 3;
            STAGE(nb, kt + 2);
        }

        const int buf = kt % 3;

        uint32_t af[2][4][4];
        uint32_t bfr[2][4][2];
#pragma unroll
        for (int ks = 0; ks < 2; ks++) {
            const int k0 = ks * 16;
#pragma unroll
            for (int mi = 0; mi < 4; mi++) {
                const int m0 = wm * 64 + mi * 16;
                uint32_t addr = sA_base + (uint32_t)((buf * GEMM_ASTG +
                    (m0 + (lane & 15)) * LDSK + k0 + ((lane >> 4) * 8)) * 2);
                asm volatile(
                    "ldmatrix.sync.aligned.m8n8.x4.shared.b16 {%0,%1,%2,%3}, [%4];\n"
                    : "=r"(af[ks][mi][0]), "=r"(af[ks][mi][1]),
                      "=r"(af[ks][mi][2]), "=r"(af[ks][mi][3])
                    : "r"(addr));
            }
#pragma unroll
            for (int nj = 0; nj < 2; nj++) {
                const int n0 = wn * 32 + nj * 16;
                uint32_t addr = sB_base + (uint32_t)((buf * GEMM_BSTG +
                    (n0 + (lane & 7) + ((lane >> 4) << 3)) * LDSK +
                    k0 + (((lane >> 3) & 1) * 8)) * 2);
                uint32_t r0, r1, r2, r3;
                asm volatile(
                    "ldmatrix.sync.aligned.m8n8.x4.shared.b16 {%0,%1,%2,%3}, [%4];\n"
                    : "=r"(r0), "=r"(r1), "=r"(r2), "=r"(r3) : "r"(addr));
                bfr[ks][nj * 2][0] = r0;     bfr[ks][nj * 2][1] = r1;
                bfr[ks][nj * 2 + 1][0] = r2; bfr[ks][nj * 2 + 1][1] = r3;
            }
        }

#pragma unroll
        for (int ks = 0; ks < 2; ks++)
#pragma unroll
            for (int mi = 0; mi < 4; mi++)
#pragma unroll
                for (int ni = 0; ni < 4; ni++)
                    asm volatile(
                        "mma.sync.aligned.m16n8k16.row.col.f32.bf16.bf16.f32 "
                        "{%0,%1,%2,%3}, {%4,%5,%6,%7}, {%8,%9}, {%0,%1,%2,%3};\n"
                        : "+f"(acc[mi][ni][0]), "+f"(acc[mi][ni][1]),
                          "+f"(acc[mi][ni][2]), "+f"(acc[mi][ni][3])
                        : "r"(af[ks][mi][0]), "r"(af[ks][mi][1]),
                          "r"(af[ks][mi][2]), "r"(af[ks][mi][3]),
                          "r"(bfr[ks][ni][0]), "r"(bfr[ks][ni][1]));
    }
#undef STAGE

    // epilogue: bias + activation (runtime act)
#pragma unroll
    for (int mi = 0; mi < 4; mi++) {
        const long r0 = rowbase + wm * 64 + mi * 16 + (lane >> 2);
#pragma unroll
        for (int ni = 0; ni < 4; ni++) {
            const int col = colbase + wn * 32 + ni * 8 + (lane & 3) * 2;
            const float b0 = bias[col], b1 = bias[col + 1];
            float v0 = acc[mi][ni][0] + b0;
            float v1 = acc[mi][ni][1] + b1;
            float v2 = acc[mi][ni][2] + b0;
            float v3 = acc[mi][ni][3] + b1;
            if (act == 1) {
                v0 = 1.f / (1.f + __expf(-v0)); v1 = 1.f / (1.f + __expf(-v1));
                v2 = 1.f / (1.f + __expf(-v2)); v3 = 1.f / (1.f + __expf(-v3));
            } else if (act == 2) {
                v0 = -tanhf(v0); v1 = -tanhf(v1);   // negated for scan FFMA2 form
                v2 = -tanhf(v2); v3 = -tanhf(v3);
            }
            if (act == 3) {
                __nv_bfloat16* Cb = (__nv_bfloat16*)Cv;
                *(__nv_bfloat162*)&Cb[r0 * DD + col] = __floats2bfloat162_rn(v0, v1);
                *(__nv_bfloat162*)&Cb[(r0 + 8) * DD + col] = __floats2bfloat162_rn(v2, v3);
            } else {
                float* C = (float*)Cv;
                *(float2*)&C[r0 * DD + col] = make_float2(v0, v1);
                *(float2*)&C[(r0 + 8) * DD + col] = make_float2(v2, v3);
            }
        }
    }
}

// All 4 projections, ONE gemm_tile call site. Grid: x = (mat,col), y = rowtile.
__global__ __launch_bounds__(256) void all_gemm_kernel(
    const __nv_bfloat16* __restrict__ Awt, const __nv_bfloat16* __restrict__ Am,
    const __nv_bfloat16* __restrict__ Wq, const __nv_bfloat16* __restrict__ We,
    const __nv_bfloat16* __restrict__ Wa, const __nv_bfloat16* __restrict__ Wk,
    const float* __restrict__ bq, const float* __restrict__ be,
    const float* __restrict__ ba, const float* __restrict__ bk,
    __nv_bfloat16* __restrict__ q_out, float* __restrict__ e_out,
    float* __restrict__ a_out, __nv_bfloat16* __restrict__ k_out)
{
    const int bn = blockIdx.x;
    const int mat = bn >> 2;
    const int colbase = (bn & 3) * GBN;
    const long rowbase = (long)blockIdx.y * GBM;

    const __nv_bfloat16* Asrc;
    const __nv_bfloat16* W;
    const float* bias;
    void* Cv;
    int act;
    if (mat == 0)      { Asrc = Awt; W = Wq; bias = bq; Cv = (void*)q_out; act = 3; }
    else if (mat == 1) { Asrc = Awt; W = We; bias = be; Cv = (void*)e_out; act = 1; }
    else if (mat == 2) { Asrc = Awt; W = Wa; bias = ba; Cv = (void*)a_out; act = 2; }
    else {
        if (blockIdx.y >= BB * MM / GBM) return;   // k has 192 row tiles
        Asrc = Am; W = Wk; bias = bk; Cv = (void*)k_out; act = 3;
    }
    gemm_tile(Asrc, W, bias, Cv, rowbase, colbase, act);
}

// ---------------------------------------------------------------------------
// Fused scores + softmax (mma.sync), 3-stage pipeline, one barrier per K-step.
// ---------------------------------------------------------------------------
#define SC_QSTG (WW * LDSK)
#define SC_KSTG (MM * LDSK)
#define SC_SMEM ((3 * SC_QSTG + 3 * SC_KSTG) * 2 + 2048)

__global__ __launch_bounds__(256) void scores_softmax_kernel(
    const __nv_bfloat16* __restrict__ Q, const __nv_bfloat16* __restrict__ K,
    float* __restrict__ S)
{
    extern __shared__ __align__(128) char dsm[];
    const uint32_t sQ_base = smem_u32(dsm);
    const uint32_t sK_base = sQ_base + 3 * SC_QSTG * 2;
    float* pmax = (float*)(dsm + (3 * SC_QSTG + 3 * SC_KSTG) * 2);
    float* psum = pmax + 2 * WW;

    const int b = blockIdx.x;
    const int tid = threadIdx.x;
    const int wid = tid >> 5;
    const int lane = tid & 31;
    const int wm = wid & 3;
    const int wn = wid >> 2;

    const __nv_bfloat16* Qb = Q + (size_t)b * WW * DD;
    const __nv_bfloat16* Kb = K + (size_t)b * MM * DD;

    float acc[2][6][4];
#pragma unroll
    for (int mi = 0; mi < 2; mi++)
#pragma unroll
        for (int ni = 0; ni < 6; ni++)
#pragma unroll
            for (int v = 0; v < 4; v++) acc[mi][ni][v] = 0.f;

    const int qr0 = tid >> 2, qc0 = (tid & 3) * 8;
    const int qc1i = tid + 256;
    const int qr1 = qc1i >> 2, qc1 = (qc1i & 3) * 8;
    const int kr0 = tid >> 2, kc0 = (tid & 3) * 8;
    const int kr1 = 64 + (tid >> 2), kc1 = (tid & 3) * 8;

#define SSTAGE(buf, kt) do {                                                       \
    const int kk_ = (kt) * GBK;                                                    \
    uint32_t s_;                                                                   \
    s_ = sQ_base + (uint32_t)((((buf) * SC_QSTG) + qr0 * LDSK + qc0) * 2);         \
    asm volatile("cp.async.cg.shared.global [%0], [%1], 16;\n"                     \
                 :: "r"(s_), "l"(Qb + (size_t)qr0 * DD + kk_ + qc0));              \
    s_ = sQ_base + (uint32_t)((((buf) * SC_QSTG) + qr1 * LDSK + qc1) * 2);         \
    asm volatile("cp.async.cg.shared.global [%0], [%1], 16;\n"                     \
                 :: "r"(s_), "l"(Qb + (size_t)qr1 * DD + kk_ + qc1));              \
    s_ = sK_base + (uint32_t)((((buf) * SC_KSTG) + kr0 * LDSK + kc0) * 2);         \
    asm volatile("cp.async.cg.shared.global [%0], [%1], 16;\n"                     \
                 :: "r"(s_), "l"(Kb + (size_t)kr0 * DD + kk_ + kc0));              \
    if (tid < 128) {                                                               \
        s_ = sK_base + (uint32_t)((((buf) * SC_KSTG) + kr1 * LDSK + kc1) * 2);     \
        asm volatile("cp.async.cg.shared.global [%0], [%1], 16;\n"                 \
                     :: "r"(s_), "l"(Kb + (size_t)kr1 * DD + kk_ + kc1));          \
    }                                                                              \
    asm volatile("cp.async.commit_group;\n");                                     \
} while (0)

    SSTAGE(0, 0);
    SSTAGE(1, 1);

    for (int kt = 0; kt < NKT; kt++) {
        if (kt == NKT - 1) asm volatile("cp.async.wait_group 0;\n");
        else               asm volatile("cp.async.wait_group 1;\n");
        __syncthreads();
        if (kt + 2 < NKT) {
            const int nb = (kt + 2) % 3;
            SSTAGE(nb, kt + 2);
        }

        const int buf = kt % 3;
#pragma unroll
        for (int ks = 0; ks < 2; ks++) {
            const int k0 = ks * 16;

            uint32_t af[2][4];
#pragma unroll
            for (int mi = 0; mi < 2; mi++) {
                const int m0 = wm * 32 + mi * 16;
                uint32_t addr = sQ_base + (uint32_t)((buf * SC_QSTG +
                    (m0 + (lane & 15)) * LDSK + k0 + ((lane >> 4) * 8)) * 2);
                asm volatile(
                    "ldmatrix.sync.aligned.m8n8.x4.shared.b16 {%0,%1,%2,%3}, [%4];\n"
                    : "=r"(af[mi][0]), "=r"(af[mi][1]), "=r"(af[mi][2]), "=r"(af[mi][3])
                    : "r"(addr));
            }

            uint32_t bfr[6][2];
#pragma unroll
            for (int nj = 0; nj < 3; nj++) {
                const int n0 = wn * 48 + nj * 16;
                uint32_t addr = sK_base + (uint32_t)((buf * SC_KSTG +
                    (n0 + (lane & 7) + ((lane >> 4) << 3)) * LDSK +
                    k0 + (((lane >> 3) & 1) * 8)) * 2);
                uint32_t r0, r1, r2, r3;
                asm volatile(
                    "ldmatrix.sync.aligned.m8n8.x4.shared.b16 {%0,%1,%2,%3}, [%4];\n"
                    : "=r"(r0), "=r"(r1), "=r"(r2), "=r"(r3) : "r"(addr));
                bfr[nj * 2][0] = r0;     bfr[nj * 2][1] = r1;
                bfr[nj * 2 + 1][0] = r2; bfr[nj * 2 + 1][1] = r3;
            }

#pragma unroll
            for (int mi = 0; mi < 2; mi++)
#pragma unroll
                for (int ni = 0; ni < 6; ni++)
                    asm volatile(
                        "mma.sync.aligned.m16n8k16.row.col.f32.bf16.bf16.f32 "
                        "{%0,%1,%2,%3}, {%4,%5,%6,%7}, {%8,%9}, {%0,%1,%2,%3};\n"
                        : "+f"(acc[mi][ni][0]), "+f"(acc[mi][ni][1]),
                          "+f"(acc[mi][ni][2]), "+f"(acc[mi][ni][3])
                        : "r"(af[mi][0]), "r"(af[mi][1]), "r"(af[mi][2]), "r"(af[mi][3]),
                          "r"(bfr[ni][0]), "r"(bfr[ni][1]));
        }
    }
#undef SSTAGE

    const float scale = 0.04419417382415922f;  // 1/sqrt(512)
#pragma unroll
    for (int mi = 0; mi < 2; mi++)
#pragma unroll
        for (int ni = 0; ni < 6; ni++)
#pragma unroll
            for (int v = 0; v < 4; v++) acc[mi][ni][v] *= scale;

    int rows[2][2];
#pragma unroll
    for (int mi = 0; mi < 2; mi++) {
        rows[mi][0] = wm * 32 + mi * 16 + (lane >> 2);
        rows[mi][1] = rows[mi][0] + 8;
    }

    __syncthreads();   // smem reuse: stages dead, pmax/psum region live

#pragma unroll
    for (int mi = 0; mi < 2; mi++) {
#pragma unroll
        for (int h = 0; h < 2; h++) {
            float mx = -1e30f;
#pragma unroll
            for (int ni = 0; ni < 6; ni++) {
                mx = fmaxf(mx, acc[mi][ni][h * 2 + 0]);
                mx = fmaxf(mx, acc[mi][ni][h * 2 + 1]);
            }
            mx = fmaxf(mx, __shfl_xor_sync(0xffffffffu, mx, 1));
            mx = fmaxf(mx, __shfl_xor_sync(0xffffffffu, mx, 2));
            pmax[wn * WW + rows[mi][h]] = mx;
        }
    }
    __syncthreads();

    float inv[2][2];
#pragma unroll
    for (int mi = 0; mi < 2; mi++) {
#pragma unroll
        for (int h = 0; h < 2; h++) {
            const float gmax = fmaxf(pmax[rows[mi][h]], pmax[WW + rows[mi][h]]);
            float sm = 0.f;
#pragma unroll
            for (int ni = 0; ni < 6; ni++) {
                float e0 = __expf(acc[mi][ni][h * 2 + 0] - gmax);
                float e1 = __expf(acc[mi][ni][h * 2 + 1] - gmax);
                acc[mi][ni][h * 2 + 0] = e0;
                acc[mi][ni][h * 2 + 1] = e1;
                sm += e0 + e1;
            }
            sm += __shfl_xor_sync(0xffffffffu, sm, 1);
            sm += __shfl_xor_sync(0xffffffffu, sm, 2);
            psum[wn * WW + rows[mi][h]] = sm;
        }
    }
    __syncthreads();

#pragma unroll
    for (int mi = 0; mi < 2; mi++)
#pragma unroll
        for (int h = 0; h < 2; h++)
            inv[mi][h] = 1.f / (psum[rows[mi][h]] + psum[WW + rows[mi][h]]);

#pragma unroll
    for (int mi = 0; mi < 2; mi++) {
#pragma unroll
        for (int h = 0; h < 2; h++) {
            float* rowp = S + ((size_t)(b * WW + rows[mi][h])) * MM;
#pragma unroll
            for (int ni = 0; ni < 6; ni++) {
                const int col = wn * 48 + ni * 8 + (lane & 3) * 2;
                *(float2*)(rowp + col) = make_float2(
                    acc[mi][ni][h * 2 + 0] * inv[mi][h],
                    acc[mi][ni][h * 2 + 1] * inv[mi][h]);
            }
        }
    }
}

// ---------------------------------------------------------------------------
// Scan + fused LayerNorm, cp.async-pipelined E/A stream.
// 512 threads: 128 d-lanes x 4 m-groups of 12 rows (m-chunk 48, grid 2 x BB).
// E/A staged in a 4-deep smem ring (2 w-rows per stage, 8KB/stage); each
// thread cp.asyncs one 16B chunk per pair-step; consumers use LDS.128.
// One __syncthreads + one wait_group per 2 w's.
// ---------------------------------------------------------------------------
#define UL_ASZ (4 * WW * 12 * 8)                 // attn: 49152
#define UL_STG_OFF UL_ASZ
#define UL_DEPTH 4
#define UL_STG_BYTES (UL_DEPTH * 8192)           // 32768
#define UL_RED_OFF (UL_STG_OFF + UL_STG_BYTES)   // 81920
#define UL_SMEM (UL_RED_OFF + 4 * 4 * 12 * 2 * 4)  // +1536 = 83456
#define UL_NP (WW / 2)                           // 64 pair-steps

__global__ __launch_bounds__(512) void update_ln_kernel(
    const float* __restrict__ mem, const float* __restrict__ attn,
    const float* __restrict__ E, const float* __restrict__ Aneg,
    const float* __restrict__ gamma, const float* __restrict__ beta,
    float* __restrict__ out)
{
    extern __shared__ __align__(16) char dsmu[];
    unsigned long long* a_s2 = (unsigned long long*)dsmu;          // [mg][w][j]
    float (*red)[4][12][2] = (float(*)[4][12][2])(dsmu + UL_RED_OFF);
    const uint32_t stg_base = smem_u32(dsmu) + UL_STG_OFF;

    const int b = blockIdx.y;
    const int m0 = blockIdx.x * 48;
    const int tid = threadIdx.x;
    const int dg = tid & 127;    // d-lane: owns floats dg*4 .. dg*4+3
    const int mg = tid >> 7;     // 0..3: rows m0 + mg*12 + j

    // staging geometry: one 16B chunk per thread per pair
    const int st_w = tid >> 8;           // 0/1: which w of the pair
    const int st_isA = (tid >> 7) & 1;   // 0=E, 1=Aneg
    const int st_dg = tid & 127;
    const float* st_src_base =
        (st_isA ? Aneg : E) + (size_t)b * WW * DD + st_dg * 4;
    const uint32_t st_dst_off = (uint32_t)((st_w * 2 + st_isA) * 2048 + st_dg * 16);

#define ULSTAGE(sbuf, p) do {                                                  \
    const float* src_ = st_src_base + (size_t)(2 * (p) + st_w) * DD;           \
    uint32_t dst_ = stg_base + (sbuf) * 8192 + st_dst_off;                     \
    asm volatile("cp.async.cg.shared.global [%0], [%1], 16;\n"                 \
                 :: "r"(dst_), "l"(src_));                                     \
    asm volatile("cp.async.commit_group;\n");                                  \
} while (0)

    unsigned long long s[12][2];
    const float4* memp = (const float4*)mem + ((size_t)(b * MM + m0 + mg * 12)) * 128 + dg;
#pragma unroll
    for (int j = 0; j < 12; j++) {
        float4 v = memp[j * 128];
        s[j][0] = pk2(v.x, v.y);
        s[j][1] = pk2(v.z, v.w);
    }

    // prologue stages (groups 0..UL_DEPTH-1)
#pragma unroll
    for (int p = 0; p < UL_DEPTH; p++) ULSTAGE(p, p);

    // attn -> smem, pre-negated & duplicated
    for (int idx = tid; idx < WW * 48; idx += 512) {
        int w = idx / 48, mm = idx % 48;
        float c = attn[((size_t)(b * WW + w)) * MM + m0 + mm];
        a_s2[(mm / 12) * (WW * 12) + w * 12 + (mm % 12)] = pk2(-c, -c);
    }
    __syncthreads();   // attn ready (stage readiness handled by wait_group)

    const unsigned long long* abase = a_s2 + mg * (WW * 12);
    const char* stg_cp = dsmu + UL_STG_OFF;

    for (int wp = 0; wp < UL_NP; wp++) {
        if (wp >= UL_NP - 2) asm volatile("cp.async.wait_group 0;\n");
        else                 asm volatile("cp.async.wait_group 2;\n");
        __syncthreads();
        if (wp >= 1 && (wp - 1 + UL_DEPTH) < UL_NP)
            ULSTAGE((wp - 1) & (UL_DEPTH - 1), wp - 1 + UL_DEPTH);

        const int sbuf = wp & (UL_DEPTH - 1);
#pragma unroll
        for (int h = 0; h < 2; h++) {
            const ulonglong2 eu = *(const ulonglong2*)
                (stg_cp + sbuf * 8192 + (h * 2 + 0) * 2048 + dg * 16);
            const ulonglong2 au = *(const ulonglong2*)
                (stg_cp + sbuf * 8192 + (h * 2 + 1) * 2048 + dg * 16);
            const unsigned long long* crow = abase + (2 * wp + h) * 12;
#pragma unroll
            for (int j = 0; j < 12; j++) {
                unsigned long long nc = crow[j];
                s[j][0] = fma2(nc, fma2(eu.x, s[j][0], au.x), s[j][0]);
                s[j][1] = fma2(nc, fma2(eu.y, s[j][1], au.y), s[j][1]);
            }
        }
    }
#undef ULSTAGE

    // per-row LayerNorm: reduce over 128 d-lanes (4 warps per m-group)
    const int wg = (tid >> 5) & 3;
    const int lane = tid & 31;
#pragma unroll
    for (int j = 0; j < 12; j++) {
        float x0, x1, x2, x3;
        upk2(x0, x1, s[j][0]);
        upk2(x2, x3, s[j][1]);
        float sm = x0 + x1 + x2 + x3;
        float sq = fmaf(x0, x0, fmaf(x1, x1, fmaf(x2, x2, x3 * x3)));
#pragma unroll
        for (int o = 16; o > 0; o >>= 1) {
            sm += __shfl_xor_sync(0xffffffffu, sm, o);
            sq += __shfl_xor_sync(0xffffffffu, sq, o);
        }
        if (lane == 0) { red[mg][wg][j][0] = sm; red[mg][wg][j][1] = sq; }
    }
    __syncthreads();

    const float4 g4 = ((const float4*)gamma)[dg];
    const float4 bt4 = ((const float4*)beta)[dg];
    float4* outp = (float4*)out + ((size_t)(b * MM + m0 + mg * 12)) * 128 + dg;

#pragma unroll
    for (int j = 0; j < 12; j++) {
        float Ssum = red[mg][0][j][0] + red[mg][1][j][0] + red[mg][2][j][0] + red[mg][3][j][0];
        float Qsum = red[mg][0][j][1] + red[mg][1][j][1] + red[mg][2][j][1] + red[mg][3][j][1];
        float mu = Ssum * (1.f / 512.f);
        float var = Qsum * (1.f / 512.f) - mu * mu;
        float rs = rsqrtf(var + 1e-5f);
        float x0, x1, x2, x3;
        upk2(x0, x1, s[j][0]);
        upk2(x2, x3, s[j][1]);
        float4 o;
        o.x = fmaf((x0 - mu) * rs, g4.x, bt4.x);
        o.y = fmaf((x1 - mu) * rs, g4.y, bt4.y);
        o.z = fmaf((x2 - mu) * rs, g4.z, bt4.z);
        o.w = fmaf((x3 - mu) * rs, g4.w, bt4.w);
        outp[j * 128] = o;
    }
}

// ---------------------------------------------------------------------------
extern "C" void kernel_launch(void* const* d_in, const int* in_sizes, int n_in,
                              void* d_out, int out_size)
{
    const float* memory = (const float*)d_in[0];
    const float* wtok   = (const float*)d_in[1];
    const float* Wq = (const float*)d_in[2];  const float* bq = (const float*)d_in[3];
    const float* Wk = (const float*)d_in[4];  const float* bk = (const float*)d_in[5];
    const float* We = (const float*)d_in[6];  const float* be = (const float*)d_in[7];
    const float* Wa = (const float*)d_in[8];  const float* ba = (const float*)d_in[9];
    const float* gamma = (const float*)d_in[10];
    const float* beta  = (const float*)d_in[11];
    float* out = (float*)d_out;

    float *e, *a, *s;
    __nv_bfloat16 *qb, *kb, *wt_bf, *m_bf, *wq_bf, *wk_bf, *we_bf, *wa_bf;
    cudaGetSymbolAddress((void**)&e, g_e);
    cudaGetSymbolAddress((void**)&a, g_a);
    cudaGetSymbolAddress((void**)&s, g_s);
    cudaGetSymbolAddress((void**)&qb, g_qb);
    cudaGetSymbolAddress((void**)&kb, g_kb);
    cudaGetSymbolAddress((void**)&wt_bf, g_wtok_bf);
    cudaGetSymbolAddress((void**)&m_bf, g_mem_bf);
    cudaGetSymbolAddress((void**)&wq_bf, g_Wq_bf);
    cudaGetSymbolAddress((void**)&wk_bf, g_Wk_bf);
    cudaGetSymbolAddress((void**)&we_bf, g_We_bf);
    cudaGetSymbolAddress((void**)&wa_bf, g_Wa_bf);

    static int smem_set = 0;
    if (!smem_set) {
        cudaFuncSetAttribute(all_gemm_kernel,
                             cudaFuncAttributeMaxDynamicSharedMemorySize, GEMM_SMEM);
        cudaFuncSetAttribute(scores_softmax_kernel,
                             cudaFuncAttributeMaxDynamicSharedMemorySize, SC_SMEM);
        cudaFuncSetAttribute(update_ln_kernel,
                             cudaFuncAttributeMaxDynamicSharedMemorySize, UL_SMEM);
        smem_set = 1;
    }

    // launch 0: ALL fp32->bf16 conversions
    f2bf_all_kernel<<<2048, 256>>>(
        (const float4*)wtok, (uint2*)wt_bf,
        (const float4*)memory, (uint2*)m_bf,
        (const float4*)Wq, (const float4*)Wk, (const float4*)We, (const float4*)Wa,
        (uint2*)wq_bf, (uint2*)wk_bf, (uint2*)we_bf, (uint2*)wa_bf);

    // launch 1: all four projections
    all_gemm_kernel<<<dim3(16, BB * WW / GBM), 256, GEMM_SMEM>>>(
        wt_bf, m_bf, wq_bf, we_bf, wa_bf, wk_bf,
        bq, be, ba, bk, qb, e, a, kb);

    // launch 2: fused scores + softmax
    scores_softmax_kernel<<<BB, 256, SC_SMEM>>>(qb, kb, s);

    // launch 3: scan + layernorm (cp.async-pipelined E/A)
    update_ln_kernel<<<dim3(2, BB), 512, UL_SMEM>>>(memory, s, e, a, gamma, beta, out);
}

// round 11
// speedup vs baseline: 1.6254x; 1.0424x over previous
#include <cuda_runtime.h>
#include <cuda_bf16.h>
#include <cstdint>

// Problem constants
#define BB 256   // batch
#define MM 96    // memory slots
#define WW 128   // write tokens
#define DD 512   // embed dim

// ---------------- scratch (static device globals: allocation-free) ----------
__device__ __nv_bfloat16 g_wtok_bf[BB * WW * DD];
__device__ __nv_bfloat16 g_mem_bf[BB * MM * DD];
__device__ __nv_bfloat16 g_Wq_bf[DD * DD];
__device__ __nv_bfloat16 g_Wk_bf[DD * DD];
__device__ __nv_bfloat16 g_We_bf[DD * DD];
__device__ __nv_bfloat16 g_Wa_bf[DD * DD];

__device__ __nv_bfloat16 g_qb[BB * WW * DD];   // q bf16 (scores input)
__device__ __nv_bfloat16 g_kb[BB * MM * DD];   // k bf16 (scores input)
__device__ float g_e[BB * WW * DD];
__device__ float g_a[BB * WW * DD];            // NEGATED tanh (scan convention)
__device__ float g_s[BB * WW * MM];

static __device__ __forceinline__ uint32_t smem_u32(const void* p) {
    uint32_t a;
    asm("{ .reg .u64 t; cvta.to.shared.u64 t, %1; cvt.u32.u64 %0, t; }" : "=r"(a) : "l"(p));
    return a;
}

static __device__ __forceinline__ unsigned long long pk2(float x, float y) {
    unsigned long long r;
    asm("mov.b64 %0, {%1, %2};" : "=l"(r) : "f"(x), "f"(y));
    return r;
}
static __device__ __forceinline__ void upk2(float& x, float& y, unsigned long long r) {
    asm("mov.b64 {%0, %1}, %2;" : "=f"(x), "=f"(y) : "l"(r));
}
static __device__ __forceinline__ unsigned long long fma2(
    unsigned long long a, unsigned long long b, unsigned long long c) {
    unsigned long long d;
    asm("fma.rn.f32x2 %0, %1, %2, %3;" : "=l"(d) : "l"(a), "l"(b), "l"(c));
    return d;
}

// ---------------------------------------------------------------------------
// fp32 -> bf16: ALL conversions (wtok + memory + 4 weights) in one launch
// ---------------------------------------------------------------------------
#define N4_WT (BB * WW * DD / 4)   // 4194304
#define N4_MEM (BB * MM * DD / 4)  // 3145728
#define N4_W (DD * DD / 4)         // 65536

__global__ __launch_bounds__(256) void f2bf_all_kernel(
    const float4* __restrict__ wt, uint2* __restrict__ wtd,
    const float4* __restrict__ mem, uint2* __restrict__ memd,
    const float4* __restrict__ w0, const float4* __restrict__ w1,
    const float4* __restrict__ w2, const float4* __restrict__ w3,
    uint2* __restrict__ wd0, uint2* __restrict__ wd1,
    uint2* __restrict__ wd2, uint2* __restrict__ wd3)
{
    const int ntot = N4_WT + N4_MEM + 4 * N4_W;
    int i = blockIdx.x * 256 + threadIdx.x;
    const int stride = gridDim.x * 256;
    for (; i < ntot; i += stride) {
        const float4* src;
        uint2* dst;
        int off;
        if (i < N4_WT) { src = wt; dst = wtd; off = i; }
        else if (i < N4_WT + N4_MEM) { src = mem; dst = memd; off = i - N4_WT; }
        else {
            int j = i - N4_WT - N4_MEM;
            int mat = j >> 16;
            off = j & (N4_W - 1);
            src = (mat == 0) ? w0 : (mat == 1) ? w1 : (mat == 2) ? w2 : w3;
            dst = (mat == 0) ? wd0 : (mat == 1) ? wd1 : (mat == 2) ? wd2 : wd3;
        }
        float4 v = src[off];
        __nv_bfloat162 lo = __floats2bfloat162_rn(v.x, v.y);
        __nv_bfloat162 hi = __floats2bfloat162_rn(v.z, v.w);
        uint2 o;
        o.x = *(uint32_t*)&lo;
        o.y = *(uint32_t*)&hi;
        dst[off] = o;
    }
}

// ---------------------------------------------------------------------------
// mma.sync GEMM core: C = act(A @ Bw^T + bias)
// Tile 128x128x32, 256 threads, warp tile 64x32, m16n8k16 bf16.
// 3-stage cp.async pipeline, ONE __syncthreads per K-step.
// act: 1=sigmoid fp32, 2=NEGATED tanh fp32, 3=none bf16 out
// ---------------------------------------------------------------------------
#define GBM 128
#define GBN 128
#define GBK 32
#define LDSK 40
#define NKT (DD / GBK)            // 16
#define GEMM_ASTG (GBM * LDSK)    // bf16 elems per A stage (5120)
#define GEMM_BSTG (GBN * LDSK)
#define GEMM_SMEM ((3 * GEMM_ASTG + 3 * GEMM_BSTG) * 2)   // 61440 B

static __device__ __forceinline__ void gemm_tile(
    const __nv_bfloat16* __restrict__ A,
    const __nv_bfloat16* __restrict__ Bw,
    const float* __restrict__ bias,
    void* __restrict__ Cv,
    long rowbase, int colbase, int act)
{
    extern __shared__ __align__(128) char dsm[];
    const uint32_t sA_base = smem_u32(dsm);
    const uint32_t sB_base = sA_base + 3 * GEMM_ASTG * 2;

    const int tid = threadIdx.x;
    const int wid = tid >> 5;
    const int lane = tid & 31;
    const int wm = wid & 1;
    const int wn = wid >> 1;

    float acc[4][4][4];
#pragma unroll
    for (int mi = 0; mi < 4; mi++)
#pragma unroll
        for (int ni = 0; ni < 4; ni++)
#pragma unroll
            for (int v = 0; v < 4; v++) acc[mi][ni][v] = 0.f;

    const int ar0 = tid >> 2, ac0 = (tid & 3) * 8;
    const int c1 = tid + 256;
    const int ar1 = c1 >> 2, ac1 = (c1 & 3) * 8;

#define STAGE(buf, kt) do {                                                        \
    const int kk_ = (kt) * GBK;                                                    \
    const __nv_bfloat16* ga0 = A  + (rowbase + ar0) * DD + kk_ + ac0;              \
    const __nv_bfloat16* ga1 = A  + (rowbase + ar1) * DD + kk_ + ac1;              \
    const __nv_bfloat16* gb0 = Bw + (long)(colbase + ar0) * DD + kk_ + ac0;        \
    const __nv_bfloat16* gb1 = Bw + (long)(colbase + ar1) * DD + kk_ + ac1;        \
    uint32_t s_;                                                                   \
    s_ = sA_base + (uint32_t)((((buf) * GEMM_ASTG) + ar0 * LDSK + ac0) * 2);       \
    asm volatile("cp.async.cg.shared.global [%0], [%1], 16;\n" :: "r"(s_), "l"(ga0)); \
    s_ = sA_base + (uint32_t)((((buf) * GEMM_ASTG) + ar1 * LDSK + ac1) * 2);       \
    asm volatile("cp.async.cg.shared.global [%0], [%1], 16;\n" :: "r"(s_), "l"(ga1)); \
    s_ = sB_base + (uint32_t)((((buf) * GEMM_BSTG) + ar0 * LDSK + ac0) * 2);       \
    asm volatile("cp.async.cg.shared.global [%0], [%1], 16;\n" :: "r"(s_), "l"(gb0)); \
    s_ = sB_base + (uint32_t)((((buf) * GEMM_BSTG) + ar1 * LDSK + ac1) * 2);       \
    asm volatile("cp.async.cg.shared.global [%0], [%1], 16;\n" :: "r"(s_), "l"(gb1)); \
    asm volatile("cp.async.commit_group;\n");                                      \
} while (0)

    STAGE(0, 0);
    STAGE(1, 1);

    for (int kt = 0; kt < NKT; kt++) {
        if (kt == NKT - 1) asm volatile("cp.async.wait_group 0;\n");
        else               asm volatile("cp.async.wait_group 1;\n");
        __syncthreads();
        if (kt + 2 < NKT) {
            const int nb = (kt + 2) % 3;
            STAGE(nb, kt + 2);
        }

        const int buf = kt % 3;

        uint32_t af[2][4][4];
        uint32_t bfr[2][4][2];
#pragma unroll
        for (int ks = 0; ks < 2; ks++) {
            const int k0 = ks * 16;
#pragma unroll
            for (int mi = 0; mi < 4; mi++) {
                const int m0 = wm * 64 + mi * 16;
                uint32_t addr = sA_base + (uint32_t)((buf * GEMM_ASTG +
                    (m0 + (lane & 15)) * LDSK + k0 + ((lane >> 4) * 8)) * 2);
                asm volatile(
                    "ldmatrix.sync.aligned.m8n8.x4.shared.b16 {%0,%1,%2,%3}, [%4];\n"
                    : "=r"(af[ks][mi][0]), "=r"(af[ks][mi][1]),
                      "=r"(af[ks][mi][2]), "=r"(af[ks][mi][3])
                    : "r"(addr));
            }
#pragma unroll
            for (int nj = 0; nj < 2; nj++) {
                const int n0 = wn * 32 + nj * 16;
                uint32_t addr = sB_base + (uint32_t)((buf * GEMM_BSTG +
                    (n0 + (lane & 7) + ((lane >> 4) << 3)) * LDSK +
                    k0 + (((lane >> 3) & 1) * 8)) * 2);
                uint32_t r0, r1, r2, r3;
                asm volatile(
                    "ldmatrix.sync.aligned.m8n8.x4.shared.b16 {%0,%1,%2,%3}, [%4];\n"
                    : "=r"(r0), "=r"(r1), "=r"(r2), "=r"(r3) : "r"(addr));
                bfr[ks][nj * 2][0] = r0;     bfr[ks][nj * 2][1] = r1;
                bfr[ks][nj * 2 + 1][0] = r2; bfr[ks][nj * 2 + 1][1] = r3;
            }
        }

#pragma unroll
        for (int ks = 0; ks < 2; ks++)
#pragma unroll
            for (int mi = 0; mi < 4; mi++)
#pragma unroll
                for (int ni = 0; ni < 4; ni++)
                    asm volatile(
                        "mma.sync.aligned.m16n8k16.row.col.f32.bf16.bf16.f32 "
                        "{%0,%1,%2,%3}, {%4,%5,%6,%7}, {%8,%9}, {%0,%1,%2,%3};\n"
                        : "+f"(acc[mi][ni][0]), "+f"(acc[mi][ni][1]),
                          "+f"(acc[mi][ni][2]), "+f"(acc[mi][ni][3])
                        : "r"(af[ks][mi][0]), "r"(af[ks][mi][1]),
                          "r"(af[ks][mi][2]), "r"(af[ks][mi][3]),
                          "r"(bfr[ks][ni][0]), "r"(bfr[ks][ni][1]));
    }
#undef STAGE

    // epilogue: bias + activation (runtime act)
#pragma unroll
    for (int mi = 0; mi < 4; mi++) {
        const long r0 = rowbase + wm * 64 + mi * 16 + (lane >> 2);
#pragma unroll
        for (int ni = 0; ni < 4; ni++) {
            const int col = colbase + wn * 32 + ni * 8 + (lane & 3) * 2;
            const float b0 = bias[col], b1 = bias[col + 1];
            float v0 = acc[mi][ni][0] + b0;
            float v1 = acc[mi][ni][1] + b1;
            float v2 = acc[mi][ni][2] + b0;
            float v3 = acc[mi][ni][3] + b1;
            if (act == 1) {
                v0 = 1.f / (1.f + __expf(-v0)); v1 = 1.f / (1.f + __expf(-v1));
                v2 = 1.f / (1.f + __expf(-v2)); v3 = 1.f / (1.f + __expf(-v3));
            } else if (act == 2) {
                v0 = -tanhf(v0); v1 = -tanhf(v1);   // negated for scan FFMA2 form
                v2 = -tanhf(v2); v3 = -tanhf(v3);
            }
            if (act == 3) {
                __nv_bfloat16* Cb = (__nv_bfloat16*)Cv;
                *(__nv_bfloat162*)&Cb[r0 * DD + col] = __floats2bfloat162_rn(v0, v1);
                *(__nv_bfloat162*)&Cb[(r0 + 8) * DD + col] = __floats2bfloat162_rn(v2, v3);
            } else {
                float* C = (float*)Cv;
                *(float2*)&C[r0 * DD + col] = make_float2(v0, v1);
                *(float2*)&C[(r0 + 8) * DD + col] = make_float2(v2, v3);
            }
        }
    }
}

// All 4 projections, ONE gemm_tile call site. Grid: x = (mat,col), y = rowtile.
__global__ __launch_bounds__(256) void all_gemm_kernel(
    const __nv_bfloat16* __restrict__ Awt, const __nv_bfloat16* __restrict__ Am,
    const __nv_bfloat16* __restrict__ Wq, const __nv_bfloat16* __restrict__ We,
    const __nv_bfloat16* __restrict__ Wa, const __nv_bfloat16* __restrict__ Wk,
    const float* __restrict__ bq, const float* __restrict__ be,
    const float* __restrict__ ba, const float* __restrict__ bk,
    __nv_bfloat16* __restrict__ q_out, float* __restrict__ e_out,
    float* __restrict__ a_out, __nv_bfloat16* __restrict__ k_out)
{
    const int bn = blockIdx.x;
    const int mat = bn >> 2;
    const int colbase = (bn & 3) * GBN;
    const long rowbase = (long)blockIdx.y * GBM;

    const __nv_bfloat16* Asrc;
    const __nv_bfloat16* W;
    const float* bias;
    void* Cv;
    int act;
    if (mat == 0)      { Asrc = Awt; W = Wq; bias = bq; Cv = (void*)q_out; act = 3; }
    else if (mat == 1) { Asrc = Awt; W = We; bias = be; Cv = (void*)e_out; act = 1; }
    else if (mat == 2) { Asrc = Awt; W = Wa; bias = ba; Cv = (void*)a_out; act = 2; }
    else {
        if (blockIdx.y >= BB * MM / GBM) return;   // k has 192 row tiles
        Asrc = Am; W = Wk; bias = bk; Cv = (void*)k_out; act = 3;
    }
    gemm_tile(Asrc, W, bias, Cv, rowbase, colbase, act);
}

// ---------------------------------------------------------------------------
// Fused scores + softmax (mma.sync), 3-stage pipeline, one barrier per K-step.
// ---------------------------------------------------------------------------
#define SC_QSTG (WW * LDSK)
#define SC_KSTG (MM * LDSK)
#define SC_SMEM ((3 * SC_QSTG + 3 * SC_KSTG) * 2 + 2048)

__global__ __launch_bounds__(256) void scores_softmax_kernel(
    const __nv_bfloat16* __restrict__ Q, const __nv_bfloat16* __restrict__ K,
    float* __restrict__ S)
{
    extern __shared__ __align__(128) char dsm[];
    const uint32_t sQ_base = smem_u32(dsm);
    const uint32_t sK_base = sQ_base + 3 * SC_QSTG * 2;
    float* pmax = (float*)(dsm + (3 * SC_QSTG + 3 * SC_KSTG) * 2);
    float* psum = pmax + 2 * WW;

    const int b = blockIdx.x;
    const int tid = threadIdx.x;
    const int wid = tid >> 5;
    const int lane = tid & 31;
    const int wm = wid & 3;
    const int wn = wid >> 2;

    const __nv_bfloat16* Qb = Q + (size_t)b * WW * DD;
    const __nv_bfloat16* Kb = K + (size_t)b * MM * DD;

    float acc[2][6][4];
#pragma unroll
    for (int mi = 0; mi < 2; mi++)
#pragma unroll
        for (int ni = 0; ni < 6; ni++)
#pragma unroll
            for (int v = 0; v < 4; v++) acc[mi][ni][v] = 0.f;

    const int qr0 = tid >> 2, qc0 = (tid & 3) * 8;
    const int qc1i = tid + 256;
    const int qr1 = qc1i >> 2, qc1 = (qc1i & 3) * 8;
    const int kr0 = tid >> 2, kc0 = (tid & 3) * 8;
    const int kr1 = 64 + (tid >> 2), kc1 = (tid & 3) * 8;

#define SSTAGE(buf, kt) do {                                                       \
    const int kk_ = (kt) * GBK;                                                    \
    uint32_t s_;                                                                   \
    s_ = sQ_base + (uint32_t)((((buf) * SC_QSTG) + qr0 * LDSK + qc0) * 2);         \
    asm volatile("cp.async.cg.shared.global [%0], [%1], 16;\n"                     \
                 :: "r"(s_), "l"(Qb + (size_t)qr0 * DD + kk_ + qc0));              \
    s_ = sQ_base + (uint32_t)((((buf) * SC_QSTG) + qr1 * LDSK + qc1) * 2);         \
    asm volatile("cp.async.cg.shared.global [%0], [%1], 16;\n"                     \
                 :: "r"(s_), "l"(Qb + (size_t)qr1 * DD + kk_ + qc1));              \
    s_ = sK_base + (uint32_t)((((buf) * SC_KSTG) + kr0 * LDSK + kc0) * 2);         \
    asm volatile("cp.async.cg.shared.global [%0], [%1], 16;\n"                     \
                 :: "r"(s_), "l"(Kb + (size_t)kr0 * DD + kk_ + kc0));              \
    if (tid < 128) {                                                               \
        s_ = sK_base + (uint32_t)((((buf) * SC_KSTG) + kr1 * LDSK + kc1) * 2);     \
        asm volatile("cp.async.cg.shared.global [%0], [%1], 16;\n"                 \
                     :: "r"(s_), "l"(Kb + (size_t)kr1 * DD + kk_ + kc1));          \
    }                                                                              \
    asm volatile("cp.async.commit_group;\n");                                     \
} while (0)

    SSTAGE(0, 0);
    SSTAGE(1, 1);

    for (int kt = 0; kt < NKT; kt++) {
        if (kt == NKT - 1) asm volatile("cp.async.wait_group 0;\n");
        else               asm volatile("cp.async.wait_group 1;\n");
        __syncthreads();
        if (kt + 2 < NKT) {
            const int nb = (kt + 2) % 3;
            SSTAGE(nb, kt + 2);
        }

        const int buf = kt % 3;
#pragma unroll
        for (int ks = 0; ks < 2; ks++) {
            const int k0 = ks * 16;

            uint32_t af[2][4];
#pragma unroll
            for (int mi = 0; mi < 2; mi++) {
                const int m0 = wm * 32 + mi * 16;
                uint32_t addr = sQ_base + (uint32_t)((buf * SC_QSTG +
                    (m0 + (lane & 15)) * LDSK + k0 + ((lane >> 4) * 8)) * 2);
                asm volatile(
                    "ldmatrix.sync.aligned.m8n8.x4.shared.b16 {%0,%1,%2,%3}, [%4];\n"
                    : "=r"(af[mi][0]), "=r"(af[mi][1]), "=r"(af[mi][2]), "=r"(af[mi][3])
                    : "r"(addr));
            }

            uint32_t bfr[6][2];
#pragma unroll
            for (int nj = 0; nj < 3; nj++) {
                const int n0 = wn * 48 + nj * 16;
                uint32_t addr = sK_base + (uint32_t)((buf * SC_KSTG +
                    (n0 + (lane & 7) + ((lane >> 4) << 3)) * LDSK +
                    k0 + (((lane >> 3) & 1) * 8)) * 2);
                uint32_t r0, r1, r2, r3;
                asm volatile(
                    "ldmatrix.sync.aligned.m8n8.x4.shared.b16 {%0,%1,%2,%3}, [%4];\n"
                    : "=r"(r0), "=r"(r1), "=r"(r2), "=r"(r3) : "r"(addr));
                bfr[nj * 2][0] = r0;     bfr[nj * 2][1] = r1;
                bfr[nj * 2 + 1][0] = r2; bfr[nj * 2 + 1][1] = r3;
            }

#pragma unroll
            for (int mi = 0; mi < 2; mi++)
#pragma unroll
                for (int ni = 0; ni < 6; ni++)
                    asm volatile(
                        "mma.sync.aligned.m16n8k16.row.col.f32.bf16.bf16.f32 "
                        "{%0,%1,%2,%3}, {%4,%5,%6,%7}, {%8,%9}, {%0,%1,%2,%3};\n"
                        : "+f"(acc[mi][ni][0]), "+f"(acc[mi][ni][1]),
                          "+f"(acc[mi][ni][2]), "+f"(acc[mi][ni][3])
                        : "r"(af[mi][0]), "r"(af[mi][1]), "r"(af[mi][2]), "r"(af[mi][3]),
                          "r"(bfr[ni][0]), "r"(bfr[ni][1]));
        }
    }
#undef SSTAGE

    const float scale = 0.04419417382415922f;  // 1/sqrt(512)
#pragma unroll
    for (int mi = 0; mi < 2; mi++)
#pragma unroll
        for (int ni = 0; ni < 6; ni++)
#pragma unroll
            for (int v = 0; v < 4; v++) acc[mi][ni][v] *= scale;

    int rows[2][2];
#pragma unroll
    for (int mi = 0; mi < 2; mi++) {
        rows[mi][0] = wm * 32 + mi * 16 + (lane >> 2);
        rows[mi][1] = rows[mi][0] + 8;
    }

    __syncthreads();   // smem reuse: stages dead, pmax/psum region live

#pragma unroll
    for (int mi = 0; mi < 2; mi++) {
#pragma unroll
        for (int h = 0; h < 2; h++) {
            float mx = -1e30f;
#pragma unroll
            for (int ni = 0; ni < 6; ni++) {
                mx = fmaxf(mx, acc[mi][ni][h * 2 + 0]);
                mx = fmaxf(mx, acc[mi][ni][h * 2 + 1]);
            }
            mx = fmaxf(mx, __shfl_xor_sync(0xffffffffu, mx, 1));
            mx = fmaxf(mx, __shfl_xor_sync(0xffffffffu, mx, 2));
            pmax[wn * WW + rows[mi][h]] = mx;
        }
    }
    __syncthreads();

    float inv[2][2];
#pragma unroll
    for (int mi = 0; mi < 2; mi++) {
#pragma unroll
        for (int h = 0; h < 2; h++) {
            const float gmax = fmaxf(pmax[rows[mi][h]], pmax[WW + rows[mi][h]]);
            float sm = 0.f;
#pragma unroll
            for (int ni = 0; ni < 6; ni++) {
                float e0 = __expf(acc[mi][ni][h * 2 + 0] - gmax);
                float e1 = __expf(acc[mi][ni][h * 2 + 1] - gmax);
                acc[mi][ni][h * 2 + 0] = e0;
                acc[mi][ni][h * 2 + 1] = e1;
                sm += e0 + e1;
            }
            sm += __shfl_xor_sync(0xffffffffu, sm, 1);
            sm += __shfl_xor_sync(0xffffffffu, sm, 2);
            psum[wn * WW + rows[mi][h]] = sm;
        }
    }
    __syncthreads();

#pragma unroll
    for (int mi = 0; mi < 2; mi++)
#pragma unroll
        for (int h = 0; h < 2; h++)
            inv[mi][h] = 1.f / (psum[rows[mi][h]] + psum[WW + rows[mi][h]]);

#pragma unroll
    for (int mi = 0; mi < 2; mi++) {
#pragma unroll
        for (int h = 0; h < 2; h++) {
            float* rowp = S + ((size_t)(b * WW + rows[mi][h])) * MM;
#pragma unroll
            for (int ni = 0; ni < 6; ni++) {
                const int col = wn * 48 + ni * 8 + (lane & 3) * 2;
                *(float2*)(rowp + col) = make_float2(
                    acc[mi][ni][h * 2 + 0] * inv[mi][h],
                    acc[mi][ni][h * 2 + 1] * inv[mi][h]);
            }
        }
    }
}

// ---------------------------------------------------------------------------
// Scan + fused LayerNorm — occupancy build: 8 rows/thread (32 state regs),
// __launch_bounds__(512, 2) -> 2 CTAs/SM (32 warps) for LDS-latency hiding.
// m-chunk 32, grid 3 x BB. E/A via 4-deep cp.async ring (2 w per stage).
// ---------------------------------------------------------------------------
#define UL_ROWS 8
#define UL_ASZ (4 * WW * UL_ROWS * 8)            // attn: 32768
#define UL_STG_OFF UL_ASZ
#define UL_DEPTH 4
#define UL_STG_BYTES (UL_DEPTH * 8192)           // 32768
#define UL_RED_OFF (UL_STG_OFF + UL_STG_BYTES)   // 65536
#define UL_SMEM (UL_RED_OFF + 4 * 4 * UL_ROWS * 2 * 4)  // +1024 = 66560
#define UL_NP (WW / 2)                           // 64 pair-steps

__global__ __launch_bounds__(512, 2) void update_ln_kernel(
    const float* __restrict__ mem, const float* __restrict__ attn,
    const float* __restrict__ E, const float* __restrict__ Aneg,
    const float* __restrict__ gamma, const float* __restrict__ beta,
    float* __restrict__ out)
{
    extern __shared__ __align__(16) char dsmu[];
    unsigned long long* a_s2 = (unsigned long long*)dsmu;          // [mg][w][j]
    float (*red)[4][UL_ROWS][2] = (float(*)[4][UL_ROWS][2])(dsmu + UL_RED_OFF);
    const uint32_t stg_base = smem_u32(dsmu) + UL_STG_OFF;

    const int b = blockIdx.y;
    const int m0 = blockIdx.x * (4 * UL_ROWS);   // 32 rows per CTA
    const int tid = threadIdx.x;
    const int dg = tid & 127;    // d-lane: owns floats dg*4 .. dg*4+3
    const int mg = tid >> 7;     // 0..3: rows m0 + mg*UL_ROWS + j

    // staging geometry: one 16B chunk per thread per pair
    const int st_w = tid >> 8;           // 0/1: which w of the pair
    const int st_isA = (tid >> 7) & 1;   // 0=E, 1=Aneg
    const int st_dg = tid & 127;
    const float* st_src_base =
        (st_isA ? Aneg : E) + (size_t)b * WW * DD + st_dg * 4;
    const uint32_t st_dst_off = (uint32_t)((st_w * 2 + st_isA) * 2048 + st_dg * 16);

#define ULSTAGE(sbuf, p) do {                                                  \
    const float* src_ = st_src_base + (size_t)(2 * (p) + st_w) * DD;           \
    uint32_t dst_ = stg_base + (sbuf) * 8192 + st_dst_off;                     \
    asm volatile("cp.async.cg.shared.global [%0], [%1], 16;\n"                 \
                 :: "r"(dst_), "l"(src_));                                     \
    asm volatile("cp.async.commit_group;\n");                                  \
} while (0)

    unsigned long long s[UL_ROWS][2];
    const float4* memp = (const float4*)mem +
        ((size_t)(b * MM + m0 + mg * UL_ROWS)) * 128 + dg;
#pragma unroll
    for (int j = 0; j < UL_ROWS; j++) {
        float4 v = memp[j * 128];
        s[j][0] = pk2(v.x, v.y);
        s[j][1] = pk2(v.z, v.w);
    }

    // prologue stages
#pragma unroll
    for (int p = 0; p < UL_DEPTH; p++) ULSTAGE(p, p);

    // attn -> smem, pre-negated & duplicated
    for (int idx = tid; idx < WW * 4 * UL_ROWS; idx += 512) {
        int w = idx / (4 * UL_ROWS), mm = idx % (4 * UL_ROWS);
        float c = attn[((size_t)(b * WW + w)) * MM + m0 + mm];
        a_s2[(mm / UL_ROWS) * (WW * UL_ROWS) + w * UL_ROWS + (mm % UL_ROWS)] =
            pk2(-c, -c);
    }
    __syncthreads();

    const unsigned long long* abase = a_s2 + mg * (WW * UL_ROWS);
    const char* stg_cp = dsmu + UL_STG_OFF;

    for (int wp = 0; wp < UL_NP; wp++) {
        if (wp >= UL_NP - 2) asm volatile("cp.async.wait_group 0;\n");
        else                 asm volatile("cp.async.wait_group 2;\n");
        __syncthreads();
        if (wp >= 1 && (wp - 1 + UL_DEPTH) < UL_NP)
            ULSTAGE((wp - 1) & (UL_DEPTH - 1), wp - 1 + UL_DEPTH);

        const int sbuf = wp & (UL_DEPTH - 1);
#pragma unroll
        for (int h = 0; h < 2; h++) {
            const ulonglong2 eu = *(const ulonglong2*)
                (stg_cp + sbuf * 8192 + (h * 2 + 0) * 2048 + dg * 16);
            const ulonglong2 au = *(const ulonglong2*)
                (stg_cp + sbuf * 8192 + (h * 2 + 1) * 2048 + dg * 16);
            const unsigned long long* crow = abase + (2 * wp + h) * UL_ROWS;
#pragma unroll
            for (int j = 0; j < UL_ROWS; j++) {
                unsigned long long nc = crow[j];
                s[j][0] = fma2(nc, fma2(eu.x, s[j][0], au.x), s[j][0]);
                s[j][1] = fma2(nc, fma2(eu.y, s[j][1], au.y), s[j][1]);
            }
        }
    }
#undef ULSTAGE

    // per-row LayerNorm: reduce over 128 d-lanes (4 warps per m-group)
    const int wg = (tid >> 5) & 3;
    const int lane = tid & 31;
#pragma unroll
    for (int j = 0; j < UL_ROWS; j++) {
        float x0, x1, x2, x3;
        upk2(x0, x1, s[j][0]);
        upk2(x2, x3, s[j][1]);
        float sm = x0 + x1 + x2 + x3;
        float sq = fmaf(x0, x0, fmaf(x1, x1, fmaf(x2, x2, x3 * x3)));
#pragma unroll
        for (int o = 16; o > 0; o >>= 1) {
            sm += __shfl_xor_sync(0xffffffffu, sm, o);
            sq += __shfl_xor_sync(0xffffffffu, sq, o);
        }
        if (lane == 0) { red[mg][wg][j][0] = sm; red[mg][wg][j][1] = sq; }
    }
    __syncthreads();

    const float4 g4 = ((const float4*)gamma)[dg];
    const float4 bt4 = ((const float4*)beta)[dg];
    float4* outp = (float4*)out + ((size_t)(b * MM + m0 + mg * UL_ROWS)) * 128 + dg;

#pragma unroll
    for (int j = 0; j < UL_ROWS; j++) {
        float Ssum = red[mg][0][j][0] + red[mg][1][j][0] + red[mg][2][j][0] + red[mg][3][j][0];
        float Qsum = red[mg][0][j][1] + red[mg][1][j][1] + red[mg][2][j][1] + red[mg][3][j][1];
        float mu = Ssum * (1.f / 512.f);
        float var = Qsum * (1.f / 512.f) - mu * mu;
        float rs = rsqrtf(var + 1e-5f);
        float x0, x1, x2, x3;
        upk2(x0, x1, s[j][0]);
        upk2(x2, x3, s[j][1]);
        float4 o;
        o.x = fmaf((x0 - mu) * rs, g4.x, bt4.x);
        o.y = fmaf((x1 - mu) * rs, g4.y, bt4.y);
        o.z = fmaf((x2 - mu) * rs, g4.z, bt4.z);
        o.w = fmaf((x3 - mu) * rs, g4.w, bt4.w);
        outp[j * 128] = o;
    }
}

// ---------------------------------------------------------------------------
extern "C" void kernel_launch(void* const* d_in, const int* in_sizes, int n_in,
                              void* d_out, int out_size)
{
    const float* memory = (const float*)d_in[0];
    const float* wtok   = (const float*)d_in[1];
    const float* Wq = (const float*)d_in[2];  const float* bq = (const float*)d_in[3];
    const float* Wk = (const float*)d_in[4];  const float* bk = (const float*)d_in[5];
    const float* We = (const float*)d_in[6];  const float* be = (const float*)d_in[7];
    const float* Wa = (const float*)d_in[8];  const float* ba = (const float*)d_in[9];
    const float* gamma = (const float*)d_in[10];
    const float* beta  = (const float*)d_in[11];
    float* out = (float*)d_out;

    float *e, *a, *s;
    __nv_bfloat16 *qb, *kb, *wt_bf, *m_bf, *wq_bf, *wk_bf, *we_bf, *wa_bf;
    cudaGetSymbolAddress((void**)&e, g_e);
    cudaGetSymbolAddress((void**)&a, g_a);
    cudaGetSymbolAddress((void**)&s, g_s);
    cudaGetSymbolAddress((void**)&qb, g_qb);
    cudaGetSymbolAddress((void**)&kb, g_kb);
    cudaGetSymbolAddress((void**)&wt_bf, g_wtok_bf);
    cudaGetSymbolAddress((void**)&m_bf, g_mem_bf);
    cudaGetSymbolAddress((void**)&wq_bf, g_Wq_bf);
    cudaGetSymbolAddress((void**)&wk_bf, g_Wk_bf);
    cudaGetSymbolAddress((void**)&we_bf, g_We_bf);
    cudaGetSymbolAddress((void**)&wa_bf, g_Wa_bf);

    static int smem_set = 0;
    if (!smem_set) {
        cudaFuncSetAttribute(all_gemm_kernel,
                             cudaFuncAttributeMaxDynamicSharedMemorySize, GEMM_SMEM);
        cudaFuncSetAttribute(scores_softmax_kernel,
                             cudaFuncAttributeMaxDynamicSharedMemorySize, SC_SMEM);
        cudaFuncSetAttribute(update_ln_kernel,
                             cudaFuncAttributeMaxDynamicSharedMemorySize, UL_SMEM);
        smem_set = 1;
    }

    // launch 0: ALL fp32->bf16 conversions
    f2bf_all_kernel<<<2048, 256>>>(
        (const float4*)wtok, (uint2*)wt_bf,
        (const float4*)memory, (uint2*)m_bf,
        (const float4*)Wq, (const float4*)Wk, (const float4*)We, (const float4*)Wa,
        (uint2*)wq_bf, (uint2*)wk_bf, (uint2*)we_bf, (uint2*)wa_bf);

    // launch 1: all four projections
    all_gemm_kernel<<<dim3(16, BB * WW / GBM), 256, GEMM_SMEM>>>(
        wt_bf, m_bf, wq_bf, we_bf, wa_bf, wk_bf,
        bq, be, ba, bk, qb, e, a, kb);

    // launch 2: fused scores + softmax
    scores_softmax_kernel<<<BB, 256, SC_SMEM>>>(qb, kb, s);

    // launch 3: scan + layernorm (8 rows/thread, 2 CTAs/SM)
    update_ln_kernel<<<dim3(3, BB), 512, UL_SMEM>>>(memory, s, e, a, gamma, beta, out);
}

// round 12
// speedup vs baseline: 1.6592x; 1.0208x over previous
#include <cuda_runtime.h>
#include <cuda_bf16.h>
#include <cstdint>

// Problem constants
#define BB 256   // batch
#define MM 96    // memory slots
#define WW 128   // write tokens
#define DD 512   // embed dim

// ---------------- scratch (static device globals: allocation-free) ----------
__device__ __nv_bfloat16 g_wtok_bf[BB * WW * DD];
__device__ __nv_bfloat16 g_mem_bf[BB * MM * DD];
__device__ __nv_bfloat16 g_Wq_bf[DD * DD];
__device__ __nv_bfloat16 g_Wk_bf[DD * DD];
__device__ __nv_bfloat16 g_We_bf[DD * DD];
__device__ __nv_bfloat16 g_Wa_bf[DD * DD];

__device__ __nv_bfloat16 g_qb[BB * WW * DD];   // q bf16 (scores input)
__device__ __nv_bfloat16 g_kb[BB * MM * DD];   // k bf16 (scores input)
__device__ float g_e[BB * WW * DD];
__device__ float g_a[BB * WW * DD];            // NEGATED tanh (scan convention)
__device__ float g_s[BB * WW * MM];

static __device__ __forceinline__ uint32_t smem_u32(const void* p) {
    uint32_t a;
    asm("{ .reg .u64 t; cvta.to.shared.u64 t, %1; cvt.u32.u64 %0, t; }" : "=r"(a) : "l"(p));
    return a;
}

static __device__ __forceinline__ unsigned long long pk2(float x, float y) {
    unsigned long long r;
    asm("mov.b64 %0, {%1, %2};" : "=l"(r) : "f"(x), "f"(y));
    return r;
}
static __device__ __forceinline__ void upk2(float& x, float& y, unsigned long long r) {
    asm("mov.b64 {%0, %1}, %2;" : "=f"(x), "=f"(y) : "l"(r));
}
static __device__ __forceinline__ unsigned long long fma2(
    unsigned long long a, unsigned long long b, unsigned long long c) {
    unsigned long long d;
    asm("fma.rn.f32x2 %0, %1, %2, %3;" : "=l"(d) : "l"(a), "l"(b), "l"(c));
    return d;
}

// ---------------------------------------------------------------------------
// fp32 -> bf16: ALL conversions (wtok + memory + 4 weights) in one launch
// ---------------------------------------------------------------------------
#define N4_WT (BB * WW * DD / 4)   // 4194304
#define N4_MEM (BB * MM * DD / 4)  // 3145728
#define N4_W (DD * DD / 4)         // 65536

__global__ __launch_bounds__(256) void f2bf_all_kernel(
    const float4* __restrict__ wt, uint2* __restrict__ wtd,
    const float4* __restrict__ mem, uint2* __restrict__ memd,
    const float4* __restrict__ w0, const float4* __restrict__ w1,
    const float4* __restrict__ w2, const float4* __restrict__ w3,
    uint2* __restrict__ wd0, uint2* __restrict__ wd1,
    uint2* __restrict__ wd2, uint2* __restrict__ wd3)
{
    const int ntot = N4_WT + N4_MEM + 4 * N4_W;
    int i = blockIdx.x * 256 + threadIdx.x;
    const int stride = gridDim.x * 256;
    for (; i < ntot; i += stride) {
        const float4* src;
        uint2* dst;
        int off;
        if (i < N4_WT) { src = wt; dst = wtd; off = i; }
        else if (i < N4_WT + N4_MEM) { src = mem; dst = memd; off = i - N4_WT; }
        else {
            int j = i - N4_WT - N4_MEM;
            int mat = j >> 16;
            off = j & (N4_W - 1);
            src = (mat == 0) ? w0 : (mat == 1) ? w1 : (mat == 2) ? w2 : w3;
            dst = (mat == 0) ? wd0 : (mat == 1) ? wd1 : (mat == 2) ? wd2 : wd3;
        }
        float4 v = src[off];
        __nv_bfloat162 lo = __floats2bfloat162_rn(v.x, v.y);
        __nv_bfloat162 hi = __floats2bfloat162_rn(v.z, v.w);
        uint2 o;
        o.x = *(uint32_t*)&lo;
        o.y = *(uint32_t*)&hi;
        dst[off] = o;
    }
}

// ---------------------------------------------------------------------------
// mma.sync GEMM core: C = act(A @ Bw^T + bias)
// Tile 128x128x32, 256 threads, warp tile 64x32, m16n8k16 bf16.
// 3-stage cp.async pipeline, ONE __syncthreads per K-step.
// act: 1=sigmoid fp32, 2=NEGATED tanh fp32, 3=none bf16 out
// ---------------------------------------------------------------------------
#define GBM 128
#define GBN 128
#define GBK 32
#define LDSK 40
#define NKT (DD / GBK)            // 16
#define GEMM_ASTG (GBM * LDSK)    // bf16 elems per A stage (5120)
#define GEMM_BSTG (GBN * LDSK)
#define GEMM_SMEM ((3 * GEMM_ASTG + 3 * GEMM_BSTG) * 2)   // 61440 B

static __device__ __forceinline__ void gemm_tile(
    const __nv_bfloat16* __restrict__ A,
    const __nv_bfloat16* __restrict__ Bw,
    const float* __restrict__ bias,
    void* __restrict__ Cv,
    long rowbase, int colbase, int act)
{
    extern __shared__ __align__(128) char dsm[];
    const uint32_t sA_base = smem_u32(dsm);
    const uint32_t sB_base = sA_base + 3 * GEMM_ASTG * 2;

    const int tid = threadIdx.x;
    const int wid = tid >> 5;
    const int lane = tid & 31;
    const int wm = wid & 1;
    const int wn = wid >> 1;

    float acc[4][4][4];
#pragma unroll
    for (int mi = 0; mi < 4; mi++)
#pragma unroll
        for (int ni = 0; ni < 4; ni++)
#pragma unroll
            for (int v = 0; v < 4; v++) acc[mi][ni][v] = 0.f;

    const int ar0 = tid >> 2, ac0 = (tid & 3) * 8;
    const int c1 = tid + 256;
    const int ar1 = c1 >> 2, ac1 = (c1 & 3) * 8;

#define STAGE(buf, kt) do {                                                        \
    const int kk_ = (kt) * GBK;                                                    \
    const __nv_bfloat16* ga0 = A  + (rowbase + ar0) * DD + kk_ + ac0;              \
    const __nv_bfloat16* ga1 = A  + (rowbase + ar1) * DD + kk_ + ac1;              \
    const __nv_bfloat16* gb0 = Bw + (long)(colbase + ar0) * DD + kk_ + ac0;        \
    const __nv_bfloat16* gb1 = Bw + (long)(colbase + ar1) * DD + kk_ + ac1;        \
    uint32_t s_;                                                                   \
    s_ = sA_base + (uint32_t)((((buf) * GEMM_ASTG) + ar0 * LDSK + ac0) * 2);       \
    asm volatile("cp.async.cg.shared.global [%0], [%1], 16;\n" :: "r"(s_), "l"(ga0)); \
    s_ = sA_base + (uint32_t)((((buf) * GEMM_ASTG) + ar1 * LDSK + ac1) * 2);       \
    asm volatile("cp.async.cg.shared.global [%0], [%1], 16;\n" :: "r"(s_), "l"(ga1)); \
    s_ = sB_base + (uint32_t)((((buf) * GEMM_BSTG) + ar0 * LDSK + ac0) * 2);       \
    asm volatile("cp.async.cg.shared.global [%0], [%1], 16;\n" :: "r"(s_), "l"(gb0)); \
    s_ = sB_base + (uint32_t)((((buf) * GEMM_BSTG) + ar1 * LDSK + ac1) * 2);       \
    asm volatile("cp.async.cg.shared.global [%0], [%1], 16;\n" :: "r"(s_), "l"(gb1)); \
    asm volatile("cp.async.commit_group;\n");                                      \
} while (0)

    STAGE(0, 0);
    STAGE(1, 1);

    for (int kt = 0; kt < NKT; kt++) {
        if (kt == NKT - 1) asm volatile("cp.async.wait_group 0;\n");
        else               asm volatile("cp.async.wait_group 1;\n");
        __syncthreads();
        if (kt + 2 < NKT) {
            const int nb = (kt + 2) % 3;
            STAGE(nb, kt + 2);
        }

        const int buf = kt % 3;

        uint32_t af[2][4][4];
        uint32_t bfr[2][4][2];
#pragma unroll
        for (int ks = 0; ks < 2; ks++) {
            const int k0 = ks * 16;
#pragma unroll
            for (int mi = 0; mi < 4; mi++) {
                const int m0 = wm * 64 + mi * 16;
                uint32_t addr = sA_base + (uint32_t)((buf * GEMM_ASTG +
                    (m0 + (lane & 15)) * LDSK + k0 + ((lane >> 4) * 8)) * 2);
                asm volatile(
                    "ldmatrix.sync.aligned.m8n8.x4.shared.b16 {%0,%1,%2,%3}, [%4];\n"
                    : "=r"(af[ks][mi][0]), "=r"(af[ks][mi][1]),
                      "=r"(af[ks][mi][2]), "=r"(af[ks][mi][3])
                    : "r"(addr));
            }
#pragma unroll
            for (int nj = 0; nj < 2; nj++) {
                const int n0 = wn * 32 + nj * 16;
                uint32_t addr = sB_base + (uint32_t)((buf * GEMM_BSTG +
                    (n0 + (lane & 7) + ((lane >> 4) << 3)) * LDSK +
                    k0 + (((lane >> 3) & 1) * 8)) * 2);
                uint32_t r0, r1, r2, r3;
                asm volatile(
                    "ldmatrix.sync.aligned.m8n8.x4.shared.b16 {%0,%1,%2,%3}, [%4];\n"
                    : "=r"(r0), "=r"(r1), "=r"(r2), "=r"(r3) : "r"(addr));
                bfr[ks][nj * 2][0] = r0;     bfr[ks][nj * 2][1] = r1;
                bfr[ks][nj * 2 + 1][0] = r2; bfr[ks][nj * 2 + 1][1] = r3;
            }
        }

#pragma unroll
        for (int ks = 0; ks < 2; ks++)
#pragma unroll
            for (int mi = 0; mi < 4; mi++)
#pragma unroll
                for (int ni = 0; ni < 4; ni++)
                    asm volatile(
                        "mma.sync.aligned.m16n8k16.row.col.f32.bf16.bf16.f32 "
                        "{%0,%1,%2,%3}, {%4,%5,%6,%7}, {%8,%9}, {%0,%1,%2,%3};\n"
                        : "+f"(acc[mi][ni][0]), "+f"(acc[mi][ni][1]),
                          "+f"(acc[mi][ni][2]), "+f"(acc[mi][ni][3])
                        : "r"(af[ks][mi][0]), "r"(af[ks][mi][1]),
                          "r"(af[ks][mi][2]), "r"(af[ks][mi][3]),
                          "r"(bfr[ks][ni][0]), "r"(bfr[ks][ni][1]));
    }
#undef STAGE

    // epilogue: bias + activation (runtime act)
#pragma unroll
    for (int mi = 0; mi < 4; mi++) {
        const long r0 = rowbase + wm * 64 + mi * 16 + (lane >> 2);
#pragma unroll
        for (int ni = 0; ni < 4; ni++) {
            const int col = colbase + wn * 32 + ni * 8 + (lane & 3) * 2;
            const float b0 = bias[col], b1 = bias[col + 1];
            float v0 = acc[mi][ni][0] + b0;
            float v1 = acc[mi][ni][1] + b1;
            float v2 = acc[mi][ni][2] + b0;
            float v3 = acc[mi][ni][3] + b1;
            if (act == 1) {
                v0 = 1.f / (1.f + __expf(-v0)); v1 = 1.f / (1.f + __expf(-v1));
                v2 = 1.f / (1.f + __expf(-v2)); v3 = 1.f / (1.f + __expf(-v3));
            } else if (act == 2) {
                v0 = -tanhf(v0); v1 = -tanhf(v1);   // negated for scan FFMA2 form
                v2 = -tanhf(v2); v3 = -tanhf(v3);
            }
            if (act == 3) {
                __nv_bfloat16* Cb = (__nv_bfloat16*)Cv;
                *(__nv_bfloat162*)&Cb[r0 * DD + col] = __floats2bfloat162_rn(v0, v1);
                *(__nv_bfloat162*)&Cb[(r0 + 8) * DD + col] = __floats2bfloat162_rn(v2, v3);
            } else {
                float* C = (float*)Cv;
                *(float2*)&C[r0 * DD + col] = make_float2(v0, v1);
                *(float2*)&C[(r0 + 8) * DD + col] = make_float2(v2, v3);
            }
        }
    }
}

// All 4 projections, ONE gemm_tile call site. Grid: x = (mat,col), y = rowtile.
__global__ __launch_bounds__(256) void all_gemm_kernel(
    const __nv_bfloat16* __restrict__ Awt, const __nv_bfloat16* __restrict__ Am,
    const __nv_bfloat16* __restrict__ Wq, const __nv_bfloat16* __restrict__ We,
    const __nv_bfloat16* __restrict__ Wa, const __nv_bfloat16* __restrict__ Wk,
    const float* __restrict__ bq, const float* __restrict__ be,
    const float* __restrict__ ba, const float* __restrict__ bk,
    __nv_bfloat16* __restrict__ q_out, float* __restrict__ e_out,
    float* __restrict__ a_out, __nv_bfloat16* __restrict__ k_out)
{
    const int bn = blockIdx.x;
    const int mat = bn >> 2;
    const int colbase = (bn & 3) * GBN;
    const long rowbase = (long)blockIdx.y * GBM;

    const __nv_bfloat16* Asrc;
    const __nv_bfloat16* W;
    const float* bias;
    void* Cv;
    int act;
    if (mat == 0)      { Asrc = Awt; W = Wq; bias = bq; Cv = (void*)q_out; act = 3; }
    else if (mat == 1) { Asrc = Awt; W = We; bias = be; Cv = (void*)e_out; act = 1; }
    else if (mat == 2) { Asrc = Awt; W = Wa; bias = ba; Cv = (void*)a_out; act = 2; }
    else {
        if (blockIdx.y >= BB * MM / GBM) return;   // k has 192 row tiles
        Asrc = Am; W = Wk; bias = bk; Cv = (void*)k_out; act = 3;
    }
    gemm_tile(Asrc, W, bias, Cv, rowbase, colbase, act);
}

// ---------------------------------------------------------------------------
// Fused scores + softmax (mma.sync), 3-stage pipeline, one barrier per K-step.
// ---------------------------------------------------------------------------
#define SC_QSTG (WW * LDSK)
#define SC_KSTG (MM * LDSK)
#define SC_SMEM ((3 * SC_QSTG + 3 * SC_KSTG) * 2 + 2048)

__global__ __launch_bounds__(256) void scores_softmax_kernel(
    const __nv_bfloat16* __restrict__ Q, const __nv_bfloat16* __restrict__ K,
    float* __restrict__ S)
{
    extern __shared__ __align__(128) char dsm[];
    const uint32_t sQ_base = smem_u32(dsm);
    const uint32_t sK_base = sQ_base + 3 * SC_QSTG * 2;
    float* pmax = (float*)(dsm + (3 * SC_QSTG + 3 * SC_KSTG) * 2);
    float* psum = pmax + 2 * WW;

    const int b = blockIdx.x;
    const int tid = threadIdx.x;
    const int wid = tid >> 5;
    const int lane = tid & 31;
    const int wm = wid & 3;
    const int wn = wid >> 2;

    const __nv_bfloat16* Qb = Q + (size_t)b * WW * DD;
    const __nv_bfloat16* Kb = K + (size_t)b * MM * DD;

    float acc[2][6][4];
#pragma unroll
    for (int mi = 0; mi < 2; mi++)
#pragma unroll
        for (int ni = 0; ni < 6; ni++)
#pragma unroll
            for (int v = 0; v < 4; v++) acc[mi][ni][v] = 0.f;

    const int qr0 = tid >> 2, qc0 = (tid & 3) * 8;
    const int qc1i = tid + 256;
    const int qr1 = qc1i >> 2, qc1 = (qc1i & 3) * 8;
    const int kr0 = tid >> 2, kc0 = (tid & 3) * 8;
    const int kr1 = 64 + (tid >> 2), kc1 = (tid & 3) * 8;

#define SSTAGE(buf, kt) do {                                                       \
    const int kk_ = (kt) * GBK;                                                    \
    uint32_t s_;                                                                   \
    s_ = sQ_base + (uint32_t)((((buf) * SC_QSTG) + qr0 * LDSK + qc0) * 2);         \
    asm volatile("cp.async.cg.shared.global [%0], [%1], 16;\n"                     \
                 :: "r"(s_), "l"(Qb + (size_t)qr0 * DD + kk_ + qc0));              \
    s_ = sQ_base + (uint32_t)((((buf) * SC_QSTG) + qr1 * LDSK + qc1) * 2);         \
    asm volatile("cp.async.cg.shared.global [%0], [%1], 16;\n"                     \
                 :: "r"(s_), "l"(Qb + (size_t)qr1 * DD + kk_ + qc1));              \
    s_ = sK_base + (uint32_t)((((buf) * SC_KSTG) + kr0 * LDSK + kc0) * 2);         \
    asm volatile("cp.async.cg.shared.global [%0], [%1], 16;\n"                     \
                 :: "r"(s_), "l"(Kb + (size_t)kr0 * DD + kk_ + kc0));              \
    if (tid < 128) {                                                               \
        s_ = sK_base + (uint32_t)((((buf) * SC_KSTG) + kr1 * LDSK + kc1) * 2);     \
        asm volatile("cp.async.cg.shared.global [%0], [%1], 16;\n"                 \
                     :: "r"(s_), "l"(Kb + (size_t)kr1 * DD + kk_ + kc1));          \
    }                                                                              \
    asm volatile("cp.async.commit_group;\n");                                     \
} while (0)

    SSTAGE(0, 0);
    SSTAGE(1, 1);

    for (int kt = 0; kt < NKT; kt++) {
        if (kt == NKT - 1) asm volatile("cp.async.wait_group 0;\n");
        else               asm volatile("cp.async.wait_group 1;\n");
        __syncthreads();
        if (kt + 2 < NKT) {
            const int nb = (kt + 2) % 3;
            SSTAGE(nb, kt + 2);
        }

        const int buf = kt % 3;
#pragma unroll
        for (int ks = 0; ks < 2; ks++) {
            const int k0 = ks * 16;

            uint32_t af[2][4];
#pragma unroll
            for (int mi = 0; mi < 2; mi++) {
                const int m0 = wm * 32 + mi * 16;
                uint32_t addr = sQ_base + (uint32_t)((buf * SC_QSTG +
                    (m0 + (lane & 15)) * LDSK + k0 + ((lane >> 4) * 8)) * 2);
                asm volatile(
                    "ldmatrix.sync.aligned.m8n8.x4.shared.b16 {%0,%1,%2,%3}, [%4];\n"
                    : "=r"(af[mi][0]), "=r"(af[mi][1]), "=r"(af[mi][2]), "=r"(af[mi][3])
                    : "r"(addr));
            }

            uint32_t bfr[6][2];
#pragma unroll
            for (int nj = 0; nj < 3; nj++) {
                const int n0 = wn * 48 + nj * 16;
                uint32_t addr = sK_base + (uint32_t)((buf * SC_KSTG +
                    (n0 + (lane & 7) + ((lane >> 4) << 3)) * LDSK +
                    k0 + (((lane >> 3) & 1) * 8)) * 2);
                uint32_t r0, r1, r2, r3;
                asm volatile(
                    "ldmatrix.sync.aligned.m8n8.x4.shared.b16 {%0,%1,%2,%3}, [%4];\n"
                    : "=r"(r0), "=r"(r1), "=r"(r2), "=r"(r3) : "r"(addr));
                bfr[nj * 2][0] = r0;     bfr[nj * 2][1] = r1;
                bfr[nj * 2 + 1][0] = r2; bfr[nj * 2 + 1][1] = r3;
            }

#pragma unroll
            for (int mi = 0; mi < 2; mi++)
#pragma unroll
                for (int ni = 0; ni < 6; ni++)
                    asm volatile(
                        "mma.sync.aligned.m16n8k16.row.col.f32.bf16.bf16.f32 "
                        "{%0,%1,%2,%3}, {%4,%5,%6,%7}, {%8,%9}, {%0,%1,%2,%3};\n"
                        : "+f"(acc[mi][ni][0]), "+f"(acc[mi][ni][1]),
                          "+f"(acc[mi][ni][2]), "+f"(acc[mi][ni][3])
                        : "r"(af[mi][0]), "r"(af[mi][1]), "r"(af[mi][2]), "r"(af[mi][3]),
                          "r"(bfr[ni][0]), "r"(bfr[ni][1]));
        }
    }
#undef SSTAGE

    const float scale = 0.04419417382415922f;  // 1/sqrt(512)
#pragma unroll
    for (int mi = 0; mi < 2; mi++)
#pragma unroll
        for (int ni = 0; ni < 6; ni++)
#pragma unroll
            for (int v = 0; v < 4; v++) acc[mi][ni][v] *= scale;

    int rows[2][2];
#pragma unroll
    for (int mi = 0; mi < 2; mi++) {
        rows[mi][0] = wm * 32 + mi * 16 + (lane >> 2);
        rows[mi][1] = rows[mi][0] + 8;
    }

    __syncthreads();   // smem reuse: stages dead, pmax/psum region live

#pragma unroll
    for (int mi = 0; mi < 2; mi++) {
#pragma unroll
        for (int h = 0; h < 2; h++) {
            float mx = -1e30f;
#pragma unroll
            for (int ni = 0; ni < 6; ni++) {
                mx = fmaxf(mx, acc[mi][ni][h * 2 + 0]);
                mx = fmaxf(mx, acc[mi][ni][h * 2 + 1]);
            }
            mx = fmaxf(mx, __shfl_xor_sync(0xffffffffu, mx, 1));
            mx = fmaxf(mx, __shfl_xor_sync(0xffffffffu, mx, 2));
            pmax[wn * WW + rows[mi][h]] = mx;
        }
    }
    __syncthreads();

    float inv[2][2];
#pragma unroll
    for (int mi = 0; mi < 2; mi++) {
#pragma unroll
        for (int h = 0; h < 2; h++) {
            const float gmax = fmaxf(pmax[rows[mi][h]], pmax[WW + rows[mi][h]]);
            float sm = 0.f;
#pragma unroll
            for (int ni = 0; ni < 6; ni++) {
                float e0 = __expf(acc[mi][ni][h * 2 + 0] - gmax);
                float e1 = __expf(acc[mi][ni][h * 2 + 1] - gmax);
                acc[mi][ni][h * 2 + 0] = e0;
                acc[mi][ni][h * 2 + 1] = e1;
                sm += e0 + e1;
            }
            sm += __shfl_xor_sync(0xffffffffu, sm, 1);
            sm += __shfl_xor_sync(0xffffffffu, sm, 2);
            psum[wn * WW + rows[mi][h]] = sm;
        }
    }
    __syncthreads();

#pragma unroll
    for (int mi = 0; mi < 2; mi++)
#pragma unroll
        for (int h = 0; h < 2; h++)
            inv[mi][h] = 1.f / (psum[rows[mi][h]] + psum[WW + rows[mi][h]]);

#pragma unroll
    for (int mi = 0; mi < 2; mi++) {
#pragma unroll
        for (int h = 0; h < 2; h++) {
            float* rowp = S + ((size_t)(b * WW + rows[mi][h])) * MM;
#pragma unroll
            for (int ni = 0; ni < 6; ni++) {
                const int col = wn * 48 + ni * 8 + (lane & 3) * 2;
                *(float2*)(rowp + col) = make_float2(
                    acc[mi][ni][h * 2 + 0] * inv[mi][h],
                    acc[mi][ni][h * 2 + 1] * inv[mi][h]);
            }
        }
    }
}

// ---------------------------------------------------------------------------
// Scan + fused LayerNorm — issue-diet build.
// 512 threads: 128 d-lanes x 4 m-groups of 8 rows (m-chunk 32, grid 3 x BB).
// E/A in a 6-deep cp.async ring (2 w per 8KB stage). Processed 2 stages per
// barrier: one wait_group + one __syncthreads per 4 w's (32 barriers total).
// crow read as ulonglong2 (LDS.128) pairs. 2 CTAs/SM via launch_bounds.
// ---------------------------------------------------------------------------
#define UL_ROWS 8
#define UL_ASZ (4 * WW * UL_ROWS * 8)            // attn: 32768
#define UL_STG_OFF UL_ASZ
#define UL_DEPTH 6
#define UL_STG_BYTES (UL_DEPTH * 8192)           // 49152
#define UL_RED_OFF (UL_STG_OFF + UL_STG_BYTES)   // 81920
#define UL_SMEM (UL_RED_OFF + 4 * 4 * UL_ROWS * 2 * 4)  // +1024 = 82944
#define UL_NP (WW / 2)                           // 64 pair-steps (stages)

__global__ __launch_bounds__(512, 2) void update_ln_kernel(
    const float* __restrict__ mem, const float* __restrict__ attn,
    const float* __restrict__ E, const float* __restrict__ Aneg,
    const float* __restrict__ gamma, const float* __restrict__ beta,
    float* __restrict__ out)
{
    extern __shared__ __align__(16) char dsmu[];
    unsigned long long* a_s2 = (unsigned long long*)dsmu;          // [mg][w][j]
    float (*red)[4][UL_ROWS][2] = (float(*)[4][UL_ROWS][2])(dsmu + UL_RED_OFF);
    const uint32_t stg_base = smem_u32(dsmu) + UL_STG_OFF;

    const int b = blockIdx.y;
    const int m0 = blockIdx.x * (4 * UL_ROWS);   // 32 rows per CTA
    const int tid = threadIdx.x;
    const int dg = tid & 127;    // d-lane: owns floats dg*4 .. dg*4+3
    const int mg = tid >> 7;     // 0..3: rows m0 + mg*UL_ROWS + j

    // staging geometry: one 16B chunk per thread per stage (2 w's per stage)
    const int st_w = tid >> 8;           // 0/1: which w of the pair
    const int st_isA = (tid >> 7) & 1;   // 0=E, 1=Aneg
    const int st_dg = tid & 127;
    const float* st_src_base =
        (st_isA ? Aneg : E) + (size_t)b * WW * DD + st_dg * 4;
    const uint32_t st_dst_off = (uint32_t)((st_w * 2 + st_isA) * 2048 + st_dg * 16);

#define ULSTAGE(p) do {                                                        \
    const float* src_ = st_src_base + (size_t)(2 * (p) + st_w) * DD;           \
    uint32_t dst_ = stg_base + ((p) % UL_DEPTH) * 8192 + st_dst_off;           \
    asm volatile("cp.async.cg.shared.global [%0], [%1], 16;\n"                 \
                 :: "r"(dst_), "l"(src_));                                     \
    asm volatile("cp.async.commit_group;\n");                                  \
} while (0)

    unsigned long long s[UL_ROWS][2];
    const float4* memp = (const float4*)mem +
        ((size_t)(b * MM + m0 + mg * UL_ROWS)) * 128 + dg;
#pragma unroll
    for (int j = 0; j < UL_ROWS; j++) {
        float4 v = memp[j * 128];
        s[j][0] = pk2(v.x, v.y);
        s[j][1] = pk2(v.z, v.w);
    }

    // prologue: stages 0..3
#pragma unroll
    for (int p = 0; p < 4; p++) ULSTAGE(p);

    // attn -> smem, pre-negated & duplicated
    for (int idx = tid; idx < WW * 4 * UL_ROWS; idx += 512) {
        int w = idx / (4 * UL_ROWS), mm = idx % (4 * UL_ROWS);
        float c = attn[((size_t)(b * WW + w)) * MM + m0 + mm];
        a_s2[(mm / UL_ROWS) * (WW * UL_ROWS) + w * UL_ROWS + (mm % UL_ROWS)] =
            pk2(-c, -c);
    }
    __syncthreads();

    const unsigned long long* abase = a_s2 + mg * (WW * UL_ROWS);
    const char* stg_cp = dsmu + UL_STG_OFF;

    // main loop: 2 stages (4 w's) per barrier
    for (int p = 0; p < UL_NP; p += 2) {
        if (p >= UL_NP - 2) asm volatile("cp.async.wait_group 0;\n");
        else                asm volatile("cp.async.wait_group 2;\n");
        __syncthreads();
        // refill stages p+4, p+5 (slots held stages p-2, p-1: consumed last iter)
        if (p + 4 < UL_NP) ULSTAGE(p + 4);
        if (p + 5 < UL_NP) ULSTAGE(p + 5);

#pragma unroll
        for (int q = 0; q < 2; q++) {          // stage p+q
            const int sbuf = (p + q) % UL_DEPTH;
#pragma unroll
            for (int h = 0; h < 2; h++) {      // w = 2*(p+q)+h
                const ulonglong2 eu = *(const ulonglong2*)
                    (stg_cp + sbuf * 8192 + (h * 2 + 0) * 2048 + dg * 16);
                const ulonglong2 au = *(const ulonglong2*)
                    (stg_cp + sbuf * 8192 + (h * 2 + 1) * 2048 + dg * 16);
                const ulonglong2* crow2 = (const ulonglong2*)
                    (abase + (2 * (p + q) + h) * UL_ROWS);
#pragma unroll
                for (int t = 0; t < UL_ROWS / 2; t++) {
                    ulonglong2 cc = crow2[t];
                    const int j0 = 2 * t, j1 = 2 * t + 1;
                    s[j0][0] = fma2(cc.x, fma2(eu.x, s[j0][0], au.x), s[j0][0]);
                    s[j0][1] = fma2(cc.x, fma2(eu.y, s[j0][1], au.y), s[j0][1]);
                    s[j1][0] = fma2(cc.y, fma2(eu.x, s[j1][0], au.x), s[j1][0]);
                    s[j1][1] = fma2(cc.y, fma2(eu.y, s[j1][1], au.y), s[j1][1]);
                }
            }
        }
    }
#undef ULSTAGE

    // per-row LayerNorm: reduce over 128 d-lanes (4 warps per m-group)
    const int wg = (tid >> 5) & 3;
    const int lane = tid & 31;
#pragma unroll
    for (int j = 0; j < UL_ROWS; j++) {
        float x0, x1, x2, x3;
        upk2(x0, x1, s[j][0]);
        upk2(x2, x3, s[j][1]);
        float sm = x0 + x1 + x2 + x3;
        float sq = fmaf(x0, x0, fmaf(x1, x1, fmaf(x2, x2, x3 * x3)));
#pragma unroll
        for (int o = 16; o > 0; o >>= 1) {
            sm += __shfl_xor_sync(0xffffffffu, sm, o);
            sq += __shfl_xor_sync(0xffffffffu, sq, o);
        }
        if (lane == 0) { red[mg][wg][j][0] = sm; red[mg][wg][j][1] = sq; }
    }
    __syncthreads();

    const float4 g4 = ((const float4*)gamma)[dg];
    const float4 bt4 = ((const float4*)beta)[dg];
    float4* outp = (float4*)out + ((size_t)(b * MM + m0 + mg * UL_ROWS)) * 128 + dg;

#pragma unroll
    for (int j = 0; j < UL_ROWS; j++) {
        float Ssum = red[mg][0][j][0] + red[mg][1][j][0] + red[mg][2][j][0] + red[mg][3][j][0];
        float Qsum = red[mg][0][j][1] + red[mg][1][j][1] + red[mg][2][j][1] + red[mg][3][j][1];
        float mu = Ssum * (1.f / 512.f);
        float var = Qsum * (1.f / 512.f) - mu * mu;
        float rs = rsqrtf(var + 1e-5f);
        float x0, x1, x2, x3;
        upk2(x0, x1, s[j][0]);
        upk2(x2, x3, s[j][1]);
        float4 o;
        o.x = fmaf((x0 - mu) * rs, g4.x, bt4.x);
        o.y = fmaf((x1 - mu) * rs, g4.y, bt4.y);
        o.z = fmaf((x2 - mu) * rs, g4.z, bt4.z);
        o.w = fmaf((x3 - mu) * rs, g4.w, bt4.w);
        outp[j * 128] = o;
    }
}

// ---------------------------------------------------------------------------
extern "C" void kernel_launch(void* const* d_in, const int* in_sizes, int n_in,
                              void* d_out, int out_size)
{
    const float* memory = (const float*)d_in[0];
    const float* wtok   = (const float*)d_in[1];
    const float* Wq = (const float*)d_in[2];  const float* bq = (const float*)d_in[3];
    const float* Wk = (const float*)d_in[4];  const float* bk = (const float*)d_in[5];
    const float* We = (const float*)d_in[6];  const float* be = (const float*)d_in[7];
    const float* Wa = (const float*)d_in[8];  const float* ba = (const float*)d_in[9];
    const float* gamma = (const float*)d_in[10];
    const float* beta  = (const float*)d_in[11];
    float* out = (float*)d_out;

    float *e, *a, *s;
    __nv_bfloat16 *qb, *kb, *wt_bf, *m_bf, *wq_bf, *wk_bf, *we_bf, *wa_bf;
    cudaGetSymbolAddress((void**)&e, g_e);
    cudaGetSymbolAddress((void**)&a, g_a);
    cudaGetSymbolAddress((void**)&s, g_s);
    cudaGetSymbolAddress((void**)&qb, g_qb);
    cudaGetSymbolAddress((void**)&kb, g_kb);
    cudaGetSymbolAddress((void**)&wt_bf, g_wtok_bf);
    cudaGetSymbolAddress((void**)&m_bf, g_mem_bf);
    cudaGetSymbolAddress((void**)&wq_bf, g_Wq_bf);
    cudaGetSymbolAddress((void**)&wk_bf, g_Wk_bf);
    cudaGetSymbolAddress((void**)&we_bf, g_We_bf);
    cudaGetSymbolAddress((void**)&wa_bf, g_Wa_bf);

    static int smem_set = 0;
    if (!smem_set) {
        cudaFuncSetAttribute(all_gemm_kernel,
                             cudaFuncAttributeMaxDynamicSharedMemorySize, GEMM_SMEM);
        cudaFuncSetAttribute(scores_softmax_kernel,
                             cudaFuncAttributeMaxDynamicSharedMemorySize, SC_SMEM);
        cudaFuncSetAttribute(update_ln_kernel,
                             cudaFuncAttributeMaxDynamicSharedMemorySize, UL_SMEM);
        smem_set = 1;
    }

    // launch 0: ALL fp32->bf16 conversions
    f2bf_all_kernel<<<2048, 256>>>(
        (const float4*)wtok, (uint2*)wt_bf,
        (const float4*)memory, (uint2*)m_bf,
        (const float4*)Wq, (const float4*)Wk, (const float4*)We, (const float4*)Wa,
        (uint2*)wq_bf, (uint2*)wk_bf, (uint2*)we_bf, (uint2*)wa_bf);

    // launch 1: all four projections
    all_gemm_kernel<<<dim3(16, BB * WW / GBM), 256, GEMM_SMEM>>>(
        wt_bf, m_bf, wq_bf, we_bf, wa_bf, wk_bf,
        bq, be, ba, bk, qb, e, a, kb);

    // launch 2: fused scores + softmax
    scores_softmax_kernel<<<BB, 256, SC_SMEM>>>(qb, kb, s);

    // launch 3: scan + layernorm (issue-diet: LDS.128 crow, half barriers)
    update_ln_kernel<<<dim3(3, BB), 512, UL_SMEM>>>(memory, s, e, a, gamma, beta, out);
}

// round 13
// speedup vs baseline: 1.7130x; 1.0324x over previous
#include <cuda_runtime.h>
#include <cuda_bf16.h>
#include <cstdint>

// Problem constants
#define BB 256   // batch
#define MM 96    // memory slots
#define WW 128   // write tokens
#define DD 512   // embed dim

// ---------------- scratch (static device globals: allocation-free) ----------
__device__ __nv_bfloat16 g_wtok_bf[BB * WW * DD];
__device__ __nv_bfloat16 g_mem_bf[BB * MM * DD];
__device__ __nv_bfloat16 g_Wq_bf[DD * DD];
__device__ __nv_bfloat16 g_Wk_bf[DD * DD];
__device__ __nv_bfloat16 g_We_bf[DD * DD];
__device__ __nv_bfloat16 g_Wa_bf[DD * DD];

__device__ __nv_bfloat16 g_qb[BB * WW * DD];   // q bf16 (scores input)
__device__ __nv_bfloat16 g_kb[BB * MM * DD];   // k bf16 (scores input)
__device__ float g_e[BB * WW * DD];
__device__ float g_a[BB * WW * DD];            // NEGATED tanh (scan convention)
__device__ float g_s[BB * WW * MM];

static __device__ __forceinline__ uint32_t smem_u32(const void* p) {
    uint32_t a;
    asm("{ .reg .u64 t; cvta.to.shared.u64 t, %1; cvt.u32.u64 %0, t; }" : "=r"(a) : "l"(p));
    return a;
}

static __device__ __forceinline__ unsigned long long pk2(float x, float y) {
    unsigned long long r;
    asm("mov.b64 %0, {%1, %2};" : "=l"(r) : "f"(x), "f"(y));
    return r;
}
static __device__ __forceinline__ void upk2(float& x, float& y, unsigned long long r) {
    asm("mov.b64 {%0, %1}, %2;" : "=f"(x), "=f"(y) : "l"(r));
}
static __device__ __forceinline__ unsigned long long fma2(
    unsigned long long a, unsigned long long b, unsigned long long c) {
    unsigned long long d;
    asm("fma.rn.f32x2 %0, %1, %2, %3;" : "=l"(d) : "l"(a), "l"(b), "l"(c));
    return d;
}

// ---------------------------------------------------------------------------
// fp32 -> bf16: ALL conversions (wtok + memory + 4 weights) in one launch
// ---------------------------------------------------------------------------
#define N4_WT (BB * WW * DD / 4)   // 4194304
#define N4_MEM (BB * MM * DD / 4)  // 3145728
#define N4_W (DD * DD / 4)         // 65536

__global__ __launch_bounds__(256) void f2bf_all_kernel(
    const float4* __restrict__ wt, uint2* __restrict__ wtd,
    const float4* __restrict__ mem, uint2* __restrict__ memd,
    const float4* __restrict__ w0, const float4* __restrict__ w1,
    const float4* __restrict__ w2, const float4* __restrict__ w3,
    uint2* __restrict__ wd0, uint2* __restrict__ wd1,
    uint2* __restrict__ wd2, uint2* __restrict__ wd3)
{
    const int ntot = N4_WT + N4_MEM + 4 * N4_W;
    int i = blockIdx.x * 256 + threadIdx.x;
    const int stride = gridDim.x * 256;
    for (; i < ntot; i += stride) {
        const float4* src;
        uint2* dst;
        int off;
        if (i < N4_WT) { src = wt; dst = wtd; off = i; }
        else if (i < N4_WT + N4_MEM) { src = mem; dst = memd; off = i - N4_WT; }
        else {
            int j = i - N4_WT - N4_MEM;
            int mat = j >> 16;
            off = j & (N4_W - 1);
            src = (mat == 0) ? w0 : (mat == 1) ? w1 : (mat == 2) ? w2 : w3;
            dst = (mat == 0) ? wd0 : (mat == 1) ? wd1 : (mat == 2) ? wd2 : wd3;
        }
        float4 v = src[off];
        __nv_bfloat162 lo = __floats2bfloat162_rn(v.x, v.y);
        __nv_bfloat162 hi = __floats2bfloat162_rn(v.z, v.w);
        uint2 o;
        o.x = *(uint32_t*)&lo;
        o.y = *(uint32_t*)&hi;
        dst[off] = o;
    }
}

// ---------------------------------------------------------------------------
// mma.sync GEMM core: C = act(A @ Bw^T + bias)
// Tile 128x128x32, 256 threads, warp tile 64x32, m16n8k16 bf16.
// 3-stage cp.async pipeline, ONE __syncthreads per K-step.
// act: 1=sigmoid fp32, 2=NEGATED tanh fp32, 3=none bf16 out
// ---------------------------------------------------------------------------
#define GBM 128
#define GBN 128
#define GBK 32
#define LDSK 40
#define NKT (DD / GBK)            // 16
#define GEMM_ASTG (GBM * LDSK)    // bf16 elems per A stage (5120)
#define GEMM_BSTG (GBN * LDSK)
#define GEMM_SMEM ((3 * GEMM_ASTG + 3 * GEMM_BSTG) * 2)   // 61440 B

static __device__ __forceinline__ void gemm_tile(
    const __nv_bfloat16* __restrict__ A,
    const __nv_bfloat16* __restrict__ Bw,
    const float* __restrict__ bias,
    void* __restrict__ Cv,
    long rowbase, int colbase, int act)
{
    extern __shared__ __align__(128) char dsm[];
    const uint32_t sA_base = smem_u32(dsm);
    const uint32_t sB_base = sA_base + 3 * GEMM_ASTG * 2;

    const int tid = threadIdx.x;
    const int wid = tid >> 5;
    const int lane = tid & 31;
    const int wm = wid & 1;
    const int wn = wid >> 1;

    float acc[4][4][4];
#pragma unroll
    for (int mi = 0; mi < 4; mi++)
#pragma unroll
        for (int ni = 0; ni < 4; ni++)
#pragma unroll
            for (int v = 0; v < 4; v++) acc[mi][ni][v] = 0.f;

    const int ar0 = tid >> 2, ac0 = (tid & 3) * 8;
    const int c1 = tid + 256;
    const int ar1 = c1 >> 2, ac1 = (c1 & 3) * 8;

#define STAGE(buf, kt) do {                                                        \
    const int kk_ = (kt) * GBK;                                                    \
    const __nv_bfloat16* ga0 = A  + (rowbase + ar0) * DD + kk_ + ac0;              \
    const __nv_bfloat16* ga1 = A  + (rowbase + ar1) * DD + kk_ + ac1;              \
    const __nv_bfloat16* gb0 = Bw + (long)(colbase + ar0) * DD + kk_ + ac0;        \
    const __nv_bfloat16* gb1 = Bw + (long)(colbase + ar1) * DD + kk_ + ac1;        \
    uint32_t s_;                                                                   \
    s_ = sA_base + (uint32_t)((((buf) * GEMM_ASTG) + ar0 * LDSK + ac0) * 2);       \
    asm volatile("cp.async.cg.shared.global [%0], [%1], 16;\n" :: "r"(s_), "l"(ga0)); \
    s_ = sA_base + (uint32_t)((((buf) * GEMM_ASTG) + ar1 * LDSK + ac1) * 2);       \
    asm volatile("cp.async.cg.shared.global [%0], [%1], 16;\n" :: "r"(s_), "l"(ga1)); \
    s_ = sB_base + (uint32_t)((((buf) * GEMM_BSTG) + ar0 * LDSK + ac0) * 2);       \
    asm volatile("cp.async.cg.shared.global [%0], [%1], 16;\n" :: "r"(s_), "l"(gb0)); \
    s_ = sB_base + (uint32_t)((((buf) * GEMM_BSTG) + ar1 * LDSK + ac1) * 2);       \
    asm volatile("cp.async.cg.shared.global [%0], [%1], 16;\n" :: "r"(s_), "l"(gb1)); \
    asm volatile("cp.async.commit_group;\n");                                      \
} while (0)

    STAGE(0, 0);
    STAGE(1, 1);

    for (int kt = 0; kt < NKT; kt++) {
        if (kt == NKT - 1) asm volatile("cp.async.wait_group 0;\n");
        else               asm volatile("cp.async.wait_group 1;\n");
        __syncthreads();
        if (kt + 2 < NKT) {
            const int nb = (kt + 2) % 3;
            STAGE(nb, kt + 2);
        }

        const int buf = kt % 3;

        uint32_t af[2][4][4];
        uint32_t bfr[2][4][2];
#pragma unroll
        for (int ks = 0; ks < 2; ks++) {
            const int k0 = ks * 16;
#pragma unroll
            for (int mi = 0; mi < 4; mi++) {
                const int m0 = wm * 64 + mi * 16;
                uint32_t addr = sA_base + (uint32_t)((buf * GEMM_ASTG +
                    (m0 + (lane & 15)) * LDSK + k0 + ((lane >> 4) * 8)) * 2);
                asm volatile(
                    "ldmatrix.sync.aligned.m8n8.x4.shared.b16 {%0,%1,%2,%3}, [%4];\n"
                    : "=r"(af[ks][mi][0]), "=r"(af[ks][mi][1]),
                      "=r"(af[ks][mi][2]), "=r"(af[ks][mi][3])
                    : "r"(addr));
            }
#pragma unroll
            for (int nj = 0; nj < 2; nj++) {
                const int n0 = wn * 32 + nj * 16;
                uint32_t addr = sB_base + (uint32_t)((buf * GEMM_BSTG +
                    (n0 + (lane & 7) + ((lane >> 4) << 3)) * LDSK +
                    k0 + (((lane >> 3) & 1) * 8)) * 2);
                uint32_t r0, r1, r2, r3;
                asm volatile(
                    "ldmatrix.sync.aligned.m8n8.x4.shared.b16 {%0,%1,%2,%3}, [%4];\n"
                    : "=r"(r0), "=r"(r1), "=r"(r2), "=r"(r3) : "r"(addr));
                bfr[ks][nj * 2][0] = r0;     bfr[ks][nj * 2][1] = r1;
                bfr[ks][nj * 2 + 1][0] = r2; bfr[ks][nj * 2 + 1][1] = r3;
            }
        }

#pragma unroll
        for (int ks = 0; ks < 2; ks++)
#pragma unroll
            for (int mi = 0; mi < 4; mi++)
#pragma unroll
                for (int ni = 0; ni < 4; ni++)
                    asm volatile(
                        "mma.sync.aligned.m16n8k16.row.col.f32.bf16.bf16.f32 "
                        "{%0,%1,%2,%3}, {%4,%5,%6,%7}, {%8,%9}, {%0,%1,%2,%3};\n"
                        : "+f"(acc[mi][ni][0]), "+f"(acc[mi][ni][1]),
                          "+f"(acc[mi][ni][2]), "+f"(acc[mi][ni][3])
                        : "r"(af[ks][mi][0]), "r"(af[ks][mi][1]),
                          "r"(af[ks][mi][2]), "r"(af[ks][mi][3]),
                          "r"(bfr[ks][ni][0]), "r"(bfr[ks][ni][1]));
    }
#undef STAGE

    // epilogue: bias + activation (runtime act)
#pragma unroll
    for (int mi = 0; mi < 4; mi++) {
        const long r0 = rowbase + wm * 64 + mi * 16 + (lane >> 2);
#pragma unroll
        for (int ni = 0; ni < 4; ni++) {
            const int col = colbase + wn * 32 + ni * 8 + (lane & 3) * 2;
            const float b0 = bias[col], b1 = bias[col + 1];
            float v0 = acc[mi][ni][0] + b0;
            float v1 = acc[mi][ni][1] + b1;
            float v2 = acc[mi][ni][2] + b0;
            float v3 = acc[mi][ni][3] + b1;
            if (act == 1) {
                v0 = 1.f / (1.f + __expf(-v0)); v1 = 1.f / (1.f + __expf(-v1));
                v2 = 1.f / (1.f + __expf(-v2)); v3 = 1.f / (1.f + __expf(-v3));
            } else if (act == 2) {
                v0 = -tanhf(v0); v1 = -tanhf(v1);   // negated for scan FFMA2 form
                v2 = -tanhf(v2); v3 = -tanhf(v3);
            }
            if (act == 3) {
                __nv_bfloat16* Cb = (__nv_bfloat16*)Cv;
                *(__nv_bfloat162*)&Cb[r0 * DD + col] = __floats2bfloat162_rn(v0, v1);
                *(__nv_bfloat162*)&Cb[(r0 + 8) * DD + col] = __floats2bfloat162_rn(v2, v3);
            } else {
                float* C = (float*)Cv;
                *(float2*)&C[r0 * DD + col] = make_float2(v0, v1);
                *(float2*)&C[(r0 + 8) * DD + col] = make_float2(v2, v3);
            }
        }
    }
}

// All 4 projections, ONE gemm_tile call site. Grid: x = (mat,col), y = rowtile.
__global__ __launch_bounds__(256) void all_gemm_kernel(
    const __nv_bfloat16* __restrict__ Awt, const __nv_bfloat16* __restrict__ Am,
    const __nv_bfloat16* __restrict__ Wq, const __nv_bfloat16* __restrict__ We,
    const __nv_bfloat16* __restrict__ Wa, const __nv_bfloat16* __restrict__ Wk,
    const float* __restrict__ bq, const float* __restrict__ be,
    const float* __restrict__ ba, const float* __restrict__ bk,
    __nv_bfloat16* __restrict__ q_out, float* __restrict__ e_out,
    float* __restrict__ a_out, __nv_bfloat16* __restrict__ k_out)
{
    const int bn = blockIdx.x;
    const int mat = bn >> 2;
    const int colbase = (bn & 3) * GBN;
    const long rowbase = (long)blockIdx.y * GBM;

    const __nv_bfloat16* Asrc;
    const __nv_bfloat16* W;
    const float* bias;
    void* Cv;
    int act;
    if (mat == 0)      { Asrc = Awt; W = Wq; bias = bq; Cv = (void*)q_out; act = 3; }
    else if (mat == 1) { Asrc = Awt; W = We; bias = be; Cv = (void*)e_out; act = 1; }
    else if (mat == 2) { Asrc = Awt; W = Wa; bias = ba; Cv = (void*)a_out; act = 2; }
    else {
        if (blockIdx.y >= BB * MM / GBM) return;   // k has 192 row tiles
        Asrc = Am; W = Wk; bias = bk; Cv = (void*)k_out; act = 3;
    }
    gemm_tile(Asrc, W, bias, Cv, rowbase, colbase, act);
}

// ---------------------------------------------------------------------------
// Fused scores + softmax (mma.sync), 3-stage pipeline, one barrier per K-step.
// ---------------------------------------------------------------------------
#define SC_QSTG (WW * LDSK)
#define SC_KSTG (MM * LDSK)
#define SC_SMEM ((3 * SC_QSTG + 3 * SC_KSTG) * 2 + 2048)

__global__ __launch_bounds__(256) void scores_softmax_kernel(
    const __nv_bfloat16* __restrict__ Q, const __nv_bfloat16* __restrict__ K,
    float* __restrict__ S)
{
    extern __shared__ __align__(128) char dsm[];
    const uint32_t sQ_base = smem_u32(dsm);
    const uint32_t sK_base = sQ_base + 3 * SC_QSTG * 2;
    float* pmax = (float*)(dsm + (3 * SC_QSTG + 3 * SC_KSTG) * 2);
    float* psum = pmax + 2 * WW;

    const int b = blockIdx.x;
    const int tid = threadIdx.x;
    const int wid = tid >> 5;
    const int lane = tid & 31;
    const int wm = wid & 3;
    const int wn = wid >> 2;

    const __nv_bfloat16* Qb = Q + (size_t)b * WW * DD;
    const __nv_bfloat16* Kb = K + (size_t)b * MM * DD;

    float acc[2][6][4];
#pragma unroll
    for (int mi = 0; mi < 2; mi++)
#pragma unroll
        for (int ni = 0; ni < 6; ni++)
#pragma unroll
            for (int v = 0; v < 4; v++) acc[mi][ni][v] = 0.f;

    const int qr0 = tid >> 2, qc0 = (tid & 3) * 8;
    const int qc1i = tid + 256;
    const int qr1 = qc1i >> 2, qc1 = (qc1i & 3) * 8;
    const int kr0 = tid >> 2, kc0 = (tid & 3) * 8;
    const int kr1 = 64 + (tid >> 2), kc1 = (tid & 3) * 8;

#define SSTAGE(buf, kt) do {                                                       \
    const int kk_ = (kt) * GBK;                                                    \
    uint32_t s_;                                                                   \
    s_ = sQ_base + (uint32_t)((((buf) * SC_QSTG) + qr0 * LDSK + qc0) * 2);         \
    asm volatile("cp.async.cg.shared.global [%0], [%1], 16;\n"                     \
                 :: "r"(s_), "l"(Qb + (size_t)qr0 * DD + kk_ + qc0));              \
    s_ = sQ_base + (uint32_t)((((buf) * SC_QSTG) + qr1 * LDSK + qc1) * 2);         \
    asm volatile("cp.async.cg.shared.global [%0], [%1], 16;\n"                     \
                 :: "r"(s_), "l"(Qb + (size_t)qr1 * DD + kk_ + qc1));              \
    s_ = sK_base + (uint32_t)((((buf) * SC_KSTG) + kr0 * LDSK + kc0) * 2);         \
    asm volatile("cp.async.cg.shared.global [%0], [%1], 16;\n"                     \
                 :: "r"(s_), "l"(Kb + (size_t)kr0 * DD + kk_ + kc0));              \
    if (tid < 128) {                                                               \
        s_ = sK_base + (uint32_t)((((buf) * SC_KSTG) + kr1 * LDSK + kc1) * 2);     \
        asm volatile("cp.async.cg.shared.global [%0], [%1], 16;\n"                 \
                     :: "r"(s_), "l"(Kb + (size_t)kr1 * DD + kk_ + kc1));          \
    }                                                                              \
    asm volatile("cp.async.commit_group;\n");                                     \
} while (0)

    SSTAGE(0, 0);
    SSTAGE(1, 1);

    for (int kt = 0; kt < NKT; kt++) {
        if (kt == NKT - 1) asm volatile("cp.async.wait_group 0;\n");
        else               asm volatile("cp.async.wait_group 1;\n");
        __syncthreads();
        if (kt + 2 < NKT) {
            const int nb = (kt + 2) % 3;
            SSTAGE(nb, kt + 2);
        }

        const int buf = kt % 3;
#pragma unroll
        for (int ks = 0; ks < 2; ks++) {
            const int k0 = ks * 16;

            uint32_t af[2][4];
#pragma unroll
            for (int mi = 0; mi < 2; mi++) {
                const int m0 = wm * 32 + mi * 16;
                uint32_t addr = sQ_base + (uint32_t)((buf * SC_QSTG +
                    (m0 + (lane & 15)) * LDSK + k0 + ((lane >> 4) * 8)) * 2);
                asm volatile(
                    "ldmatrix.sync.aligned.m8n8.x4.shared.b16 {%0,%1,%2,%3}, [%4];\n"
                    : "=r"(af[mi][0]), "=r"(af[mi][1]), "=r"(af[mi][2]), "=r"(af[mi][3])
                    : "r"(addr));
            }

            uint32_t bfr[6][2];
#pragma unroll
            for (int nj = 0; nj < 3; nj++) {
                const int n0 = wn * 48 + nj * 16;
                uint32_t addr = sK_base + (uint32_t)((buf * SC_KSTG +
                    (n0 + (lane & 7) + ((lane >> 4) << 3)) * LDSK +
                    k0 + (((lane >> 3) & 1) * 8)) * 2);
                uint32_t r0, r1, r2, r3;
                asm volatile(
                    "ldmatrix.sync.aligned.m8n8.x4.shared.b16 {%0,%1,%2,%3}, [%4];\n"
                    : "=r"(r0), "=r"(r1), "=r"(r2), "=r"(r3) : "r"(addr));
                bfr[nj * 2][0] = r0;     bfr[nj * 2][1] = r1;
                bfr[nj * 2 + 1][0] = r2; bfr[nj * 2 + 1][1] = r3;
            }

#pragma unroll
            for (int mi = 0; mi < 2; mi++)
#pragma unroll
                for (int ni = 0; ni < 6; ni++)
                    asm volatile(
                        "mma.sync.aligned.m16n8k16.row.col.f32.bf16.bf16.f32 "
                        "{%0,%1,%2,%3}, {%4,%5,%6,%7}, {%8,%9}, {%0,%1,%2,%3};\n"
                        : "+f"(acc[mi][ni][0]), "+f"(acc[mi][ni][1]),
                          "+f"(acc[mi][ni][2]), "+f"(acc[mi][ni][3])
                        : "r"(af[mi][0]), "r"(af[mi][1]), "r"(af[mi][2]), "r"(af[mi][3]),
                          "r"(bfr[ni][0]), "r"(bfr[ni][1]));
        }
    }
#undef SSTAGE

    const float scale = 0.04419417382415922f;  // 1/sqrt(512)
#pragma unroll
    for (int mi = 0; mi < 2; mi++)
#pragma unroll
        for (int ni = 0; ni < 6; ni++)
#pragma unroll
            for (int v = 0; v < 4; v++) acc[mi][ni][v] *= scale;

    int rows[2][2];
#pragma unroll
    for (int mi = 0; mi < 2; mi++) {
        rows[mi][0] = wm * 32 + mi * 16 + (lane >> 2);
        rows[mi][1] = rows[mi][0] + 8;
    }

    __syncthreads();   // smem reuse: stages dead, pmax/psum region live

#pragma unroll
    for (int mi = 0; mi < 2; mi++) {
#pragma unroll
        for (int h = 0; h < 2; h++) {
            float mx = -1e30f;
#pragma unroll
            for (int ni = 0; ni < 6; ni++) {
                mx = fmaxf(mx, acc[mi][ni][h * 2 + 0]);
                mx = fmaxf(mx, acc[mi][ni][h * 2 + 1]);
            }
            mx = fmaxf(mx, __shfl_xor_sync(0xffffffffu, mx, 1));
            mx = fmaxf(mx, __shfl_xor_sync(0xffffffffu, mx, 2));
            pmax[wn * WW + rows[mi][h]] = mx;
        }
    }
    __syncthreads();

    float inv[2][2];
#pragma unroll
    for (int mi = 0; mi < 2; mi++) {
#pragma unroll
        for (int h = 0; h < 2; h++) {
            const float gmax = fmaxf(pmax[rows[mi][h]], pmax[WW + rows[mi][h]]);
            float sm = 0.f;
#pragma unroll
            for (int ni = 0; ni < 6; ni++) {
                float e0 = __expf(acc[mi][ni][h * 2 + 0] - gmax);
                float e1 = __expf(acc[mi][ni][h * 2 + 1] - gmax);
                acc[mi][ni][h * 2 + 0] = e0;
                acc[mi][ni][h * 2 + 1] = e1;
                sm += e0 + e1;
            }
            sm += __shfl_xor_sync(0xffffffffu, sm, 1);
            sm += __shfl_xor_sync(0xffffffffu, sm, 2);
            psum[wn * WW + rows[mi][h]] = sm;
        }
    }
    __syncthreads();

#pragma unroll
    for (int mi = 0; mi < 2; mi++)
#pragma unroll
        for (int h = 0; h < 2; h++)
            inv[mi][h] = 1.f / (psum[rows[mi][h]] + psum[WW + rows[mi][h]]);

#pragma unroll
    for (int mi = 0; mi < 2; mi++) {
#pragma unroll
        for (int h = 0; h < 2; h++) {
            float* rowp = S + ((size_t)(b * WW + rows[mi][h])) * MM;
#pragma unroll
            for (int ni = 0; ni < 6; ni++) {
                const int col = wn * 48 + ni * 8 + (lane & 3) * 2;
                *(float2*)(rowp + col) = make_float2(
                    acc[mi][ni][h * 2 + 0] * inv[mi][h],
                    acc[mi][ni][h * 2 + 1] * inv[mi][h]);
            }
        }
    }
}

// ---------------------------------------------------------------------------
// Scan + fused LayerNorm — const-slot build.
// 512 threads: 128 d-lanes x 4 m-groups of 8 rows (m-chunk 32, grid 3 x BB).
// E/A in an 8-deep cp.async ring (2 w per 8KB stage). Outer loop unrolled in
// 8-stage super-iterations with two 4-stage phases; ALL slot indices are
// compile-time constants. One wait+sync per 4 stages (16 barriers total).
// crow via LDS.128. 2 CTAs/SM.
// ---------------------------------------------------------------------------
#define UL_ROWS 8
#define UL_ASZ (4 * WW * UL_ROWS * 8)            // attn: 32768
#define UL_STG_OFF UL_ASZ
#define UL_DEPTH 8
#define UL_STG_BYTES (UL_DEPTH * 8192)           // 65536
#define UL_RED_OFF (UL_STG_OFF + UL_STG_BYTES)   // 98304
#define UL_SMEM (UL_RED_OFF + 4 * 4 * UL_ROWS * 2 * 4)  // +1024 = 99328
#define UL_NST (WW / 2)                          // 64 stages (2 w's each)

__global__ __launch_bounds__(512, 2) void update_ln_kernel(
    const float* __restrict__ mem, const float* __restrict__ attn,
    const float* __restrict__ E, const float* __restrict__ Aneg,
    const float* __restrict__ gamma, const float* __restrict__ beta,
    float* __restrict__ out)
{
    extern __shared__ __align__(16) char dsmu[];
    unsigned long long* a_s2 = (unsigned long long*)dsmu;          // [mg][w][j]
    float (*red)[4][UL_ROWS][2] = (float(*)[4][UL_ROWS][2])(dsmu + UL_RED_OFF);
    const uint32_t stg_base = smem_u32(dsmu) + UL_STG_OFF;

    const int b = blockIdx.y;
    const int m0 = blockIdx.x * (4 * UL_ROWS);   // 32 rows per CTA
    const int tid = threadIdx.x;
    const int dg = tid & 127;    // d-lane: owns floats dg*4 .. dg*4+3
    const int mg = tid >> 7;     // 0..3: rows m0 + mg*UL_ROWS + j

    // staging geometry: one 16B chunk per thread per stage (2 w's per stage)
    const int st_w = tid >> 8;           // 0/1: which w of the pair
    const int st_isA = (tid >> 7) & 1;   // 0=E, 1=Aneg
    const int st_dg = tid & 127;
    const float* st_src_base =
        (st_isA ? Aneg : E) + (size_t)b * WW * DD + st_dg * 4;
    const uint32_t st_dst_off = (uint32_t)((st_w * 2 + st_isA) * 2048 + st_dg * 16);

// slot is a compile-time constant at every call site
#define ULSTAGE(slot, p) do {                                                  \
    const float* src_ = st_src_base + (size_t)(2 * (p) + st_w) * DD;           \
    uint32_t dst_ = stg_base + (slot) * 8192 + st_dst_off;                     \
    asm volatile("cp.async.cg.shared.global [%0], [%1], 16;\n"                 \
                 :: "r"(dst_), "l"(src_));                                     \
    asm volatile("cp.async.commit_group;\n");                                  \
} while (0)

    unsigned long long s[UL_ROWS][2];
    const float4* memp = (const float4*)mem +
        ((size_t)(b * MM + m0 + mg * UL_ROWS)) * 128 + dg;
#pragma unroll
    for (int j = 0; j < UL_ROWS; j++) {
        float4 v = memp[j * 128];
        s[j][0] = pk2(v.x, v.y);
        s[j][1] = pk2(v.z, v.w);
    }

    // prologue: stages 0..3 into slots 0..3
    ULSTAGE(0, 0); ULSTAGE(1, 1); ULSTAGE(2, 2); ULSTAGE(3, 3);

    // attn -> smem, pre-negated & duplicated
    for (int idx = tid; idx < WW * 4 * UL_ROWS; idx += 512) {
        int w = idx / (4 * UL_ROWS), mm = idx % (4 * UL_ROWS);
        float c = attn[((size_t)(b * WW + w)) * MM + m0 + mm];
        a_s2[(mm / UL_ROWS) * (WW * UL_ROWS) + w * UL_ROWS + (mm % UL_ROWS)] =
            pk2(-c, -c);
    }
    __syncthreads();

    const unsigned long long* abase = a_s2 + mg * (WW * UL_ROWS);
    const char* stg_cp = dsmu + UL_STG_OFF;

    // one 4-stage phase: compute stages p..p+3 from slots s0..s0+3 (constant)
#define ULPHASE(s0c, p) do {                                                   \
    _Pragma("unroll")                                                          \
    for (int q = 0; q < 4; q++) {                                              \
        const int sbuf = (s0c) + q;        /* compile-time */                  \
        _Pragma("unroll")                                                      \
        for (int h = 0; h < 2; h++) {                                          \
            const ulonglong2 eu = *(const ulonglong2*)                         \
                (stg_cp + sbuf * 8192 + (h * 2 + 0) * 2048 + dg * 16);         \
            const ulonglong2 au = *(const ulonglong2*)                         \
                (stg_cp + sbuf * 8192 + (h * 2 + 1) * 2048 + dg * 16);         \
            const ulonglong2* crow2 = (const ulonglong2*)                      \
                (abase + (2 * ((p) + q) + h) * UL_ROWS);                       \
            _Pragma("unroll")                                                  \
            for (int t = 0; t < UL_ROWS / 2; t++) {                            \
                ulonglong2 cc = crow2[t];                                      \
                const int j0 = 2 * t, j1 = 2 * t + 1;                          \
                s[j0][0] = fma2(cc.x, fma2(eu.x, s[j0][0], au.x), s[j0][0]);   \
                s[j0][1] = fma2(cc.x, fma2(eu.y, s[j0][1], au.y), s[j0][1]);   \
                s[j1][0] = fma2(cc.y, fma2(eu.x, s[j1][0], au.x), s[j1][0]);   \
                s[j1][1] = fma2(cc.y, fma2(eu.y, s[j1][1], au.y), s[j1][1]);   \
            }                                                                  \
        }                                                                      \
    }                                                                          \
} while (0)

    // main loop: 8 stages per super-iteration, two phases, const slots
    for (int pp = 0; pp < UL_NST; pp += 8) {
        // phase A: compute stages pp..pp+3 (slots 0..3); refill slots 4..7
        asm volatile("cp.async.wait_group 0;\n");
        __syncthreads();
        ULSTAGE(4, pp + 4); ULSTAGE(5, pp + 5);
        ULSTAGE(6, pp + 6); ULSTAGE(7, pp + 7);
        ULPHASE(0, pp);

        // phase B: compute stages pp+4..pp+7 (slots 4..7); refill slots 0..3
        asm volatile("cp.async.wait_group 0;\n");
        __syncthreads();
        if (pp + 8 < UL_NST) {
            ULSTAGE(0, pp + 8);  ULSTAGE(1, pp + 9);
            ULSTAGE(2, pp + 10); ULSTAGE(3, pp + 11);
        }
        ULPHASE(4, pp + 4);
    }
#undef ULSTAGE
#undef ULPHASE

    // per-row LayerNorm: reduce over 128 d-lanes (4 warps per m-group)
    const int wg = (tid >> 5) & 3;
    const int lane = tid & 31;
#pragma unroll
    for (int j = 0; j < UL_ROWS; j++) {
        float x0, x1, x2, x3;
        upk2(x0, x1, s[j][0]);
        upk2(x2, x3, s[j][1]);
        float sm = x0 + x1 + x2 + x3;
        float sq = fmaf(x0, x0, fmaf(x1, x1, fmaf(x2, x2, x3 * x3)));
#pragma unroll
        for (int o = 16; o > 0; o >>= 1) {
            sm += __shfl_xor_sync(0xffffffffu, sm, o);
            sq += __shfl_xor_sync(0xffffffffu, sq, o);
        }
        if (lane == 0) { red[mg][wg][j][0] = sm; red[mg][wg][j][1] = sq; }
    }
    __syncthreads();

    const float4 g4 = ((const float4*)gamma)[dg];
    const float4 bt4 = ((const float4*)beta)[dg];
    float4* outp = (float4*)out + ((size_t)(b * MM + m0 + mg * UL_ROWS)) * 128 + dg;

#pragma unroll
    for (int j = 0; j < UL_ROWS; j++) {
        float Ssum = red[mg][0][j][0] + red[mg][1][j][0] + red[mg][2][j][0] + red[mg][3][j][0];
        float Qsum = red[mg][0][j][1] + red[mg][1][j][1] + red[mg][2][j][1] + red[mg][3][j][1];
        float mu = Ssum * (1.f / 512.f);
        float var = Qsum * (1.f / 512.f) - mu * mu;
        float rs = rsqrtf(var + 1e-5f);
        float x0, x1, x2, x3;
        upk2(x0, x1, s[j][0]);
        upk2(x2, x3, s[j][1]);
        float4 o;
        o.x = fmaf((x0 - mu) * rs, g4.x, bt4.x);
        o.y = fmaf((x1 - mu) * rs, g4.y, bt4.y);
        o.z = fmaf((x2 - mu) * rs, g4.z, bt4.z);
        o.w = fmaf((x3 - mu) * rs, g4.w, bt4.w);
        outp[j * 128] = o;
    }
}

// ---------------------------------------------------------------------------
extern "C" void kernel_launch(void* const* d_in, const int* in_sizes, int n_in,
                              void* d_out, int out_size)
{
    const float* memory = (const float*)d_in[0];
    const float* wtok   = (const float*)d_in[1];
    const float* Wq = (const float*)d_in[2];  const float* bq = (const float*)d_in[3];
    const float* Wk = (const float*)d_in[4];  const float* bk = (const float*)d_in[5];
    const float* We = (const float*)d_in[6];  const float* be = (const float*)d_in[7];
    const float* Wa = (const float*)d_in[8];  const float* ba = (const float*)d_in[9];
    const float* gamma = (const float*)d_in[10];
    const float* beta  = (const float*)d_in[11];
    float* out = (float*)d_out;

    float *e, *a, *s;
    __nv_bfloat16 *qb, *kb, *wt_bf, *m_bf, *wq_bf, *wk_bf, *we_bf, *wa_bf;
    cudaGetSymbolAddress((void**)&e, g_e);
    cudaGetSymbolAddress((void**)&a, g_a);
    cudaGetSymbolAddress((void**)&s, g_s);
    cudaGetSymbolAddress((void**)&qb, g_qb);
    cudaGetSymbolAddress((void**)&kb, g_kb);
    cudaGetSymbolAddress((void**)&wt_bf, g_wtok_bf);
    cudaGetSymbolAddress((void**)&m_bf, g_mem_bf);
    cudaGetSymbolAddress((void**)&wq_bf, g_Wq_bf);
    cudaGetSymbolAddress((void**)&wk_bf, g_Wk_bf);
    cudaGetSymbolAddress((void**)&we_bf, g_We_bf);
    cudaGetSymbolAddress((void**)&wa_bf, g_Wa_bf);

    static int smem_set = 0;
    if (!smem_set) {
        cudaFuncSetAttribute(all_gemm_kernel,
                             cudaFuncAttributeMaxDynamicSharedMemorySize, GEMM_SMEM);
        cudaFuncSetAttribute(scores_softmax_kernel,
                             cudaFuncAttributeMaxDynamicSharedMemorySize, SC_SMEM);
        cudaFuncSetAttribute(update_ln_kernel,
                             cudaFuncAttributeMaxDynamicSharedMemorySize, UL_SMEM);
        smem_set = 1;
    }

    // launch 0: ALL fp32->bf16 conversions
    f2bf_all_kernel<<<2048, 256>>>(
        (const float4*)wtok, (uint2*)wt_bf,
        (const float4*)memory, (uint2*)m_bf,
        (const float4*)Wq, (const float4*)Wk, (const float4*)We, (const float4*)Wa,
        (uint2*)wq_bf, (uint2*)wk_bf, (uint2*)we_bf, (uint2*)wa_bf);

    // launch 1: all four projections
    all_gemm_kernel<<<dim3(16, BB * WW / GBM), 256, GEMM_SMEM>>>(
        wt_bf, m_bf, wq_bf, we_bf, wa_bf, wk_bf,
        bq, be, ba, bk, qb, e, a, kb);

    // launch 2: fused scores + softmax
    scores_softmax_kernel<<<BB, 256, SC_SMEM>>>(qb, kb, s);

    // launch 3: scan + layernorm (const-slot ring, 16 barriers)
    update_ln_kernel<<<dim3(3, BB), 512, UL_SMEM>>>(memory, s, e, a, gamma, beta, out);
}